// round 9
// baseline (speedup 1.0000x reference)
#include <cuda_runtime.h>
#include <cuda_fp16.h>
#include <math.h>

#define NPTS 20000
#define KNN  16
#define C    256
#define G    16
#define EPS  1e-5f
#define P    4          // points per block in K2
#define BM   32         // feat rows per block in K1
#define FS   260        // k1 feat_s stride (words)
#define YS   260        // k1 ybuf stride (words)
#define HP   264        // k2 hid row stride in halves
#define LGS  20         // logit buffer row stride

typedef unsigned long long ull;

// ---------------- scratch (static device memory) ---------------------------
__device__ __half   g_vall16[NPTS * C];         // v_all, fp16
__device__ float    g_qW[NPTS * G];
__device__ float    g_kW[NPTS * G];
__device__ unsigned g_wfrag[3 * 32 * 32 * 64];  // W q/k/v tf32 B-frags (k1)
__device__ unsigned g_w1frag[4096];             // ww1 tf32 B-frags (k1 projection)
__device__ unsigned g_afrag16[2048];            // (Wp2@Ww1) fp16 B-frags (k2)
__device__ float    g_wp2t[C * C];              // Wp2^T: [c][k]
__device__ float    g_sq[C], g_tq[C];
__device__ float    g_sk[C], g_tk[C];
__device__ float    g_sp[C], g_tp[C];
__device__ float    g_sw[G], g_cw[G];

// ---------------- helpers ---------------------------------------------------
__device__ __forceinline__ unsigned f2tf(float x) {
    unsigned r;
    asm("cvt.rna.tf32.f32 %0, %1;" : "=r"(r) : "f"(x));
    return r;
}
__device__ __forceinline__ unsigned smem_u32(const void* p) {
    unsigned r;
    asm("{ .reg .u64 t; cvta.to.shared.u64 t, %1; cvt.u32.u64 %0, t; }"
        : "=r"(r) : "l"(p));
    return r;
}
#define CP_ASYNC16(dst, src) \
    asm volatile("cp.async.ca.shared.global [%0], [%1], 16;" :: "r"(dst), "l"(src))
#define MMA_TF32(acc, a0, a1, a2, a3, b0, b1)                                   \
    asm("mma.sync.aligned.m16n8k8.row.col.f32.tf32.tf32.f32 "                   \
        "{%0,%1,%2,%3},{%4,%5,%6,%7},{%8,%9},{%0,%1,%2,%3};"                    \
        : "+f"(acc.x), "+f"(acc.y), "+f"(acc.z), "+f"(acc.w)                    \
        : "r"(a0), "r"(a1), "r"(a2), "r"(a3), "r"(b0), "r"(b1))
#define MMA_F16(acc, a0, a1, a2, a3, b0, b1)                                    \
    asm("mma.sync.aligned.m16n8k16.row.col.f32.f16.f16.f32 "                    \
        "{%0,%1,%2,%3},{%4,%5,%6,%7},{%8,%9},{%0,%1,%2,%3};"                    \
        : "+f"(acc.x), "+f"(acc.y), "+f"(acc.z), "+f"(acc.w)                    \
        : "r"(a0), "r"(a1), "r"(a2), "r"(a3), "r"(b0), "r"(b1))

// ---------------- prep kernels ---------------------------------------------
__global__ void prep_fold(const float* __restrict__ bq, const float* __restrict__ bnq,
                          const float* __restrict__ bk, const float* __restrict__ bnk,
                          const float* __restrict__ bp1, const float* __restrict__ bnp,
                          const float* __restrict__ bw1, const float* __restrict__ bnw,
                          const float* __restrict__ bp2, const float* __restrict__ ww1) {
    int t = threadIdx.x;
    if (t < C) {
        float s;
        s = bnq[t] * rsqrtf(bnq[3 * C + t] + EPS);
        g_sq[t] = s; g_tq[t] = (bq[t] - bnq[2 * C + t]) * s + bnq[C + t];
        s = bnk[t] * rsqrtf(bnk[3 * C + t] + EPS);
        g_sk[t] = s; g_tk[t] = (bk[t] - bnk[2 * C + t]) * s + bnk[C + t];
        s = bnp[t] * rsqrtf(bnp[3 * C + t] + EPS);
        g_sp[t] = s; g_tp[t] = (bp1[t] - bnp[2 * C + t]) * s + bnp[C + t];
    }
    if (t < G) {
        float s = bnw[t] * rsqrtf(bnw[3 * G + t] + EPS);
        float bp2w = 0.f;
        for (int c = 0; c < C; c++) bp2w += bp2[c] * ww1[c * G + t];
        g_sw[t] = s;
        g_cw[t] = (bw1[t] + bp2w - bnw[2 * G + t]) * s + bnw[G + t];
    }
}

__global__ void prep_wfrag(const float* __restrict__ W, unsigned* __restrict__ dst) {
    int kb = blockIdx.x;
    int i  = threadIdx.x;
    int nb = i >> 5, lane = i & 31;
    int gid = lane >> 2, tig = lane & 3;
    int k0 = kb * 8 + tig, n = nb * 8 + gid;
    dst[((kb * 32 + nb) * 32 + lane) * 2 + 0] = f2tf(W[k0 * C + n]);
    dst[((kb * 32 + nb) * 32 + lane) * 2 + 1] = f2tf(W[(k0 + 4) * C + n]);
}

__global__ void prep_w1frag(const float* __restrict__ ww1) {
    int idx  = blockIdx.x * 256 + threadIdx.x;
    int lane = idx & 31, knb = idx >> 5;
    int kb = knb >> 1, nb = knb & 1;
    int gid = lane >> 2, tig = lane & 3;
    int n  = nb * 8 + gid;
    int k0 = kb * 8 + tig;
    g_w1frag[idx * 2 + 0] = f2tf(ww1[k0 * G + n]);
    g_w1frag[idx * 2 + 1] = f2tf(ww1[(k0 + 4) * G + n]);
}

__global__ void prep_afrag16(const float* __restrict__ wp2, const float* __restrict__ ww1) {
    int idx  = blockIdx.x * 256 + threadIdx.x;
    int lane = idx & 31, knb = idx >> 5;
    int kb = knb >> 1, nb = knb & 1;
    int gid = lane >> 2, tig = lane & 3;
    int g  = nb * 8 + gid;
    int k0 = kb * 16 + tig * 2;
    float d0 = 0.f, d1 = 0.f, d2 = 0.f, d3 = 0.f;
    #pragma unroll 4
    for (int c = 0; c < C; c++) {
        float w = ww1[c * G + g];
        d0 = fmaf(wp2[(k0)     * C + c], w, d0);
        d1 = fmaf(wp2[(k0 + 1) * C + c], w, d1);
        d2 = fmaf(wp2[(k0 + 8) * C + c], w, d2);
        d3 = fmaf(wp2[(k0 + 9) * C + c], w, d3);
    }
    half2 b0 = __floats2half2_rn(d0, d1);
    half2 b1 = __floats2half2_rn(d2, d3);
    g_afrag16[idx * 2 + 0] = *(unsigned*)&b0;
    g_afrag16[idx * 2 + 1] = *(unsigned*)&b1;
}

__global__ void prep_wp2t(const float* __restrict__ wp2) {
    int k = blockIdx.x, c = threadIdx.x;
    g_wp2t[c * C + k] = wp2[k * C + c];
}

// ---------------- K1: q/k/v GEMM + projection, all TF32 mma ----------------
__global__ __launch_bounds__(256, 2) void k1_qkv(
    const float* __restrict__ feat, const float* __restrict__ bv) {
    extern __shared__ float sm[];
    float* feat_s = sm;
    float* ybuf   = sm + BM * FS;
    unsigned* ww1f = (unsigned*)(sm + BM * FS + BM * YS);
    unsigned* featu = (unsigned*)feat_s;

    int t    = threadIdx.x;
    int r0b  = blockIdx.x * BM;
    int warp = t >> 5, lane = t & 31;
    int gid  = lane >> 2, tig = lane & 3;
    int n0   = warp * 32;

    for (int i = t; i < BM * C / 4; i += 256) {
        int r = i >> 6, c4 = (i & 63) * 4;
        float4 f = *(const float4*)&feat[(r0b + r) * C + c4];
        featu[r * FS + c4 + 0] = f2tf(f.x);
        featu[r * FS + c4 + 1] = f2tf(f.y);
        featu[r * FS + c4 + 2] = f2tf(f.z);
        featu[r * FS + c4 + 3] = f2tf(f.w);
    }
    for (int i = t; i < 1024; i += 256)
        *(uint4*)&ww1f[i * 4] = *(const uint4*)&g_w1frag[i * 4];
    __syncthreads();

    #pragma unroll 1
    for (int pass = 0; pass < 3; pass++) {
        const ull* wf = (const ull*)(g_wfrag + pass * (32 * 32 * 64));
        float4 acc[2][4];
        #pragma unroll
        for (int mt = 0; mt < 2; mt++)
            #pragma unroll
            for (int nt = 0; nt < 4; nt++) acc[mt][nt] = make_float4(0.f, 0.f, 0.f, 0.f);

        #pragma unroll 4
        for (int kb = 0; kb < 32; kb++) {
            unsigned a0 = featu[(gid)      * FS + kb * 8 + tig];
            unsigned a1 = featu[(gid + 8)  * FS + kb * 8 + tig];
            unsigned a2 = featu[(gid)      * FS + kb * 8 + tig + 4];
            unsigned a3 = featu[(gid + 8)  * FS + kb * 8 + tig + 4];
            unsigned a4 = featu[(gid + 16) * FS + kb * 8 + tig];
            unsigned a5 = featu[(gid + 24) * FS + kb * 8 + tig];
            unsigned a6 = featu[(gid + 16) * FS + kb * 8 + tig + 4];
            unsigned a7 = featu[(gid + 24) * FS + kb * 8 + tig + 4];
            #pragma unroll
            for (int nt = 0; nt < 4; nt++) {
                ull bb = wf[(kb * 32 + warp * 4 + nt) * 32 + lane];
                unsigned b0 = (unsigned)bb, b1 = (unsigned)(bb >> 32);
                MMA_TF32(acc[0][nt], a0, a1, a2, a3, b0, b1);
                MMA_TF32(acc[1][nt], a4, a5, a6, a7, b0, b1);
            }
        }

        if (pass == 2) {
            #pragma unroll
            for (int nt = 0; nt < 4; nt++) {
                int col = n0 + nt * 8 + tig * 2;
                float2 b2 = *(const float2*)&bv[col];
                #pragma unroll
                for (int mt = 0; mt < 2; mt++) {
                    int rA = r0b + mt * 16 + gid, rB = rA + 8;
                    *(half2*)&g_vall16[rA * C + col] =
                        __floats2half2_rn(acc[mt][nt].x + b2.x, acc[mt][nt].y + b2.y);
                    *(half2*)&g_vall16[rB * C + col] =
                        __floats2half2_rn(acc[mt][nt].z + b2.x, acc[mt][nt].w + b2.y);
                }
            }
        } else {
            const float* sA = (pass == 0) ? g_sq : g_sk;
            const float* tA = (pass == 0) ? g_tq : g_tk;
            #pragma unroll
            for (int nt = 0; nt < 4; nt++) {
                int col = n0 + nt * 8 + tig * 2;
                float2 s2 = *(const float2*)&sA[col];
                float2 t2 = *(const float2*)&tA[col];
                #pragma unroll
                for (int mt = 0; mt < 2; mt++) {
                    int rA = mt * 16 + gid, rB = rA + 8;
                    *(float2*)&ybuf[rA * YS + col] = make_float2(
                        fmaxf(fmaf(acc[mt][nt].x, s2.x, t2.x), 0.f),
                        fmaxf(fmaf(acc[mt][nt].y, s2.y, t2.y), 0.f));
                    *(float2*)&ybuf[rB * YS + col] = make_float2(
                        fmaxf(fmaf(acc[mt][nt].z, s2.x, t2.x), 0.f),
                        fmaxf(fmaf(acc[mt][nt].w, s2.y, t2.y), 0.f));
                }
            }
            __syncthreads();
            if (warp < 4) {
                int m0p = (warp & 1) * 16, nbp = warp >> 1;
                float4 pa = make_float4(0.f, 0.f, 0.f, 0.f);
                #pragma unroll 8
                for (int kb = 0; kb < 32; kb++) {
                    unsigned a0 = f2tf(ybuf[(m0p + gid)     * YS + kb * 8 + tig]);
                    unsigned a1 = f2tf(ybuf[(m0p + gid + 8) * YS + kb * 8 + tig]);
                    unsigned a2 = f2tf(ybuf[(m0p + gid)     * YS + kb * 8 + tig + 4]);
                    unsigned a3 = f2tf(ybuf[(m0p + gid + 8) * YS + kb * 8 + tig + 4]);
                    ull bb = *(const ull*)&ww1f[((kb * 2 + nbp) * 32 + lane) * 2];
                    MMA_TF32(pa, a0, a1, a2, a3, (unsigned)bb, (unsigned)(bb >> 32));
                }
                float* dst = (pass == 0) ? g_qW : g_kW;
                int col = nbp * 8 + tig * 2;
                dst[(r0b + m0p + gid)     * G + col]     = pa.x;
                dst[(r0b + m0p + gid)     * G + col + 1] = pa.y;
                dst[(r0b + m0p + gid + 8) * G + col]     = pa.z;
                dst[(r0b + m0p + gid + 8) * G + col + 1] = pa.w;
            }
            __syncthreads();
        }
    }
}

// ---------------- K2: fused per-point grouped attention -------------------
struct K2S {
    unsigned short hid[P * 16 * HP];  // 33792 B; fp16; becomes hw in place
    unsigned afrag[2048];
    float    lg[64 * LGS];
    float    buf2[64 * G];
    float    vterm[4 * 256];
    float    kwq[64 * 16];
    float    qwb[4 * 16];
    float    pos[64 * 4];
    float    wsum[P * G];
    float    mask[64];
    int      idx[64];
    float    ww2[G * G];
    float    sw[G], cw[G], bw2s[G];
};

__global__ __launch_bounds__(256, 3) void k2_attn(
    const float* __restrict__ coord, const int* __restrict__ knn,
    const float* __restrict__ wp1,   const float* __restrict__ bp2,
    const float* __restrict__ ww2,   const float* __restrict__ bw2,
    float* __restrict__ out) {
    extern __shared__ char smraw[];
    K2S& S = *reinterpret_cast<K2S*>(smraw);
    int t  = threadIdx.x;
    int n0 = blockIdx.x * P;

    for (int i = t; i < 512; i += 256)
        *(uint4*)&S.afrag[i * 4] = *(const uint4*)&g_afrag16[i * 4];
    S.ww2[t] = ww2[t];
    if (t < G) { S.sw[t] = g_sw[t]; S.cw[t] = g_cw[t]; S.bw2s[t] = bw2[t]; }

    // phase 1: gather idx / mask / pos + cp.async prefetch of kW/qW rows
    if (t < 64) {
        int p = t >> 4, n = n0 + p;
        int id  = knn[n * KNN + (t & 15)];
        int ip1 = id + 1;
        float m = (float)((ip1 > 0) - (ip1 < 0));
        int sid = (id > 0) ? id : 0;
        S.idx[t]  = sid;
        S.mask[t] = m;
        #pragma unroll
        for (int d = 0; d < 3; d++)
            S.pos[t * 4 + d] = (coord[sid * 3 + d] - coord[n * 3 + d]) * m;
        unsigned d0 = smem_u32(&S.kwq[t * 16]);
        const float* s0 = &g_kW[sid * G];
        #pragma unroll
        for (int j = 0; j < 4; j++) CP_ASYNC16(d0 + j * 16, s0 + j * 4);
        if (t < 4) {
            unsigned d1 = smem_u32(&S.qwb[t * 16]);
            const float* s1 = &g_qW[(n0 + t) * G];
            #pragma unroll
            for (int j = 0; j < 4; j++) CP_ASYNC16(d1 + j * 16, s1 + j * 4);
        }
        asm volatile("cp.async.commit_group;");
    }
    __syncthreads();

    // phase 2: hidden = relu(bn(pos @ Wp1 + bp1)) -> fp16
    {
        int half_ = t >> 7;
        int cp = (t & 127) * 2;
        float2 w0 = *(const float2*)&wp1[cp];
        float2 w1 = *(const float2*)&wp1[C + cp];
        float2 w2 = *(const float2*)&wp1[2 * C + cp];
        float2 sc = *(const float2*)&g_sp[cp];
        float2 sh = *(const float2*)&g_tp[cp];
        #pragma unroll 4
        for (int ps = half_ * 32; ps < half_ * 32 + 32; ps++) {
            float px = S.pos[ps * 4 + 0];
            float py = S.pos[ps * 4 + 1];
            float pz = S.pos[ps * 4 + 2];
            float h0 = fmaf(px, w0.x, fmaf(py, w1.x, pz * w2.x));
            float h1 = fmaf(px, w0.y, fmaf(py, w1.y, pz * w2.y));
            h0 = fmaxf(fmaf(h0, sc.x, sh.x), 0.f);
            h1 = fmaxf(fmaf(h1, sc.y, sh.y), 0.f);
            *(half2*)&S.hid[ps * HP + cp] = __floats2half2_rn(h0, h1);
        }
    }
    __syncthreads();

    // phase 3a: lg = hidden @ A via fp16 mma m16n8k16
    {
        int w = t >> 5, lane = t & 31, gid = lane >> 2, tig = lane & 3;
        int m0 = (w & 3) * 16, nb = w >> 2;
        float4 acc = make_float4(0.f, 0.f, 0.f, 0.f);
        const ull* bf = (const ull*)S.afrag;
        #pragma unroll
        for (int kb = 0; kb < 16; kb++) {
            unsigned a0 = *(const unsigned*)&S.hid[(m0 + gid)     * HP + kb * 16 + tig * 2];
            unsigned a1 = *(const unsigned*)&S.hid[(m0 + gid + 8) * HP + kb * 16 + tig * 2];
            unsigned a2 = *(const unsigned*)&S.hid[(m0 + gid)     * HP + kb * 16 + tig * 2 + 8];
            unsigned a3 = *(const unsigned*)&S.hid[(m0 + gid + 8) * HP + kb * 16 + tig * 2 + 8];
            ull bb = bf[(kb * 2 + nb) * 32 + lane];
            unsigned b0 = (unsigned)bb, b1 = (unsigned)(bb >> 32);
            MMA_F16(acc, a0, a1, a2, a3, b0, b1);
        }
        S.lg[(m0 + gid)     * LGS + nb * 8 + tig * 2]     = acc.x;
        S.lg[(m0 + gid)     * LGS + nb * 8 + tig * 2 + 1] = acc.y;
        S.lg[(m0 + gid + 8) * LGS + nb * 8 + tig * 2]     = acc.z;
        S.lg[(m0 + gid + 8) * LGS + nb * 8 + tig * 2 + 1] = acc.w;
    }
    __syncthreads();

    // phase 3b (warps 0-1): + lb, relu/sw/cw, @Ww2 -> buf2; then 4a softmax
    if (t < 64) {
        asm volatile("cp.async.wait_group 0;" ::: "memory");
        int r = t, p = r >> 4;
        float m = S.mask[r];
        const float4* kw = (const float4*)&S.kwq[r * 16];
        const float4* qw = (const float4*)&S.qwb[p * 16];
        float u[16];
        #pragma unroll
        for (int q = 0; q < 4; q++) {
            float4 sv = *(const float4*)&S.lg[r * LGS + q * 4];
            float4 kv = kw[q], qv = qw[q];
            float4 lb;
            lb.x = fmaf(m, kv.x, -qv.x); lb.y = fmaf(m, kv.y, -qv.y);
            lb.z = fmaf(m, kv.z, -qv.z); lb.w = fmaf(m, kv.w, -qv.w);
            u[q*4+0] = fmaxf(fmaf(sv.x + lb.x, S.sw[q*4+0], S.cw[q*4+0]), 0.f);
            u[q*4+1] = fmaxf(fmaf(sv.y + lb.y, S.sw[q*4+1], S.cw[q*4+1]), 0.f);
            u[q*4+2] = fmaxf(fmaf(sv.z + lb.z, S.sw[q*4+2], S.cw[q*4+2]), 0.f);
            u[q*4+3] = fmaxf(fmaf(sv.w + lb.w, S.sw[q*4+3], S.cw[q*4+3]), 0.f);
        }
        #pragma unroll
        for (int g2 = 0; g2 < 16; g2++) {
            float acc = S.bw2s[g2];
            #pragma unroll
            for (int g = 0; g < 16; g++) acc = fmaf(u[g], S.ww2[g * 16 + g2], acc);
            S.buf2[r * 16 + g2] = acc;
        }
        __syncwarp();
        int pp = t >> 4, g = t & 15;
        float mx = -1e30f;
        #pragma unroll
        for (int s = 0; s < 16; s++) mx = fmaxf(mx, S.buf2[(pp * 16 + s) * 16 + g]);
        float e[16], sum = 0.f;
        #pragma unroll
        for (int s = 0; s < 16; s++) {
            e[s] = __expf(S.buf2[(pp * 16 + s) * 16 + g] - mx);
            sum += e[s];
        }
        float inv = 1.f / sum, ws = 0.f;
        #pragma unroll
        for (int s = 0; s < 16; s++) {
            float w = e[s] * inv * S.mask[pp * 16 + s];
            S.buf2[(pp * 16 + s) * 16 + g] = w;
            ws += w;
        }
        S.wsum[t] = ws;
    }
    __syncthreads();

    // phase 4: warps 0-3: v-gather with LDG.128; warps 4-7: hw in place.
    // Disjoint memory: A reads g_vall16/buf2, writes vterm; B reads hid/buf2,
    // writes hid. Different pipes (LSU vs FMA) overlap across warps.
    if (t < 128) {
        // ---- A: thread owns (point p, 8-channel chunk), loops neighbors ----
        int p  = t >> 5;           // warp = point
        int ch = t & 31;           // 8-channel chunk
        int c0 = ch * 8;
        int g  = c0 >> 4;
        float a0 = 0.f, a1 = 0.f, a2 = 0.f, a3 = 0.f;
        float a4 = 0.f, a5 = 0.f, a6 = 0.f, a7 = 0.f;
        #pragma unroll
        for (int s = 0; s < 16; s++) {
            float w = S.buf2[(p * 16 + s) * 16 + g];   // warp-broadcast
            uint4 v = *(const uint4*)&g_vall16[S.idx[p * 16 + s] * C + c0];
            float2 v0 = __half22float2(*(half2*)&v.x);
            float2 v1 = __half22float2(*(half2*)&v.y);
            float2 v2 = __half22float2(*(half2*)&v.z);
            float2 v3 = __half22float2(*(half2*)&v.w);
            a0 = fmaf(w, v0.x, a0); a1 = fmaf(w, v0.y, a1);
            a2 = fmaf(w, v1.x, a2); a3 = fmaf(w, v1.y, a3);
            a4 = fmaf(w, v2.x, a4); a5 = fmaf(w, v2.y, a5);
            a6 = fmaf(w, v3.x, a6); a7 = fmaf(w, v3.y, a7);
        }
        *(float4*)&S.vterm[p * 256 + c0]     = make_float4(a0, a1, a2, a3);
        *(float4*)&S.vterm[p * 256 + c0 + 4] = make_float4(a4, a5, a6, a7);
    } else {
        // ---- B: hw[p][g][c] = sum_s w*hid, in place, 4 slots/thread ----
        int tt = t - 128;
        #pragma unroll
        for (int j = 0; j < 4; j++) {
            int si = tt * 4 + j;             // 0..511
            int p = si >> 7, cq = (si & 127) * 2;
            float2 acc[16];
            #pragma unroll
            for (int g = 0; g < 16; g++) acc[g] = make_float2(0.f, 0.f);
            #pragma unroll
            for (int s = 0; s < 16; s++) {
                float2 h = __half22float2(*(const half2*)&S.hid[(p * 16 + s) * HP + cq]);
                const float4* wr = (const float4*)&S.buf2[(p * 16 + s) * 16];
                #pragma unroll
                for (int q = 0; q < 4; q++) {
                    float4 w = wr[q];
                    acc[q*4+0].x = fmaf(w.x, h.x, acc[q*4+0].x); acc[q*4+0].y = fmaf(w.x, h.y, acc[q*4+0].y);
                    acc[q*4+1].x = fmaf(w.y, h.x, acc[q*4+1].x); acc[q*4+1].y = fmaf(w.y, h.y, acc[q*4+1].y);
                    acc[q*4+2].x = fmaf(w.z, h.x, acc[q*4+2].x); acc[q*4+2].y = fmaf(w.z, h.y, acc[q*4+2].y);
                    acc[q*4+3].x = fmaf(w.w, h.x, acc[q*4+3].x); acc[q*4+3].y = fmaf(w.w, h.y, acc[q*4+3].y);
                }
            }
            #pragma unroll
            for (int g = 0; g < 16; g++)
                *(half2*)&S.hid[(p * 16 + g) * HP + cq] = __floats2half2_rn(acc[g].x, acc[g].y);
        }
    }
    __syncthreads();

    // phase 5: out = vterm + hw @ Wp2^T + bp2*wsum
    {
        int c = t, g = c >> 4;
        float b = __ldg(&bp2[c]);
        float acc0 = S.vterm[c]       + b * S.wsum[g];
        float acc1 = S.vterm[256 + c] + b * S.wsum[16 + g];
        float acc2 = S.vterm[512 + c] + b * S.wsum[32 + g];
        float acc3 = S.vterm[768 + c] + b * S.wsum[48 + g];

        const float4* wpt = (const float4*)&g_wp2t[c * C];
        const unsigned short* r0 = &S.hid[(g)      * HP];
        const unsigned short* r1 = &S.hid[(16 + g) * HP];
        const unsigned short* r2 = &S.hid[(32 + g) * HP];
        const unsigned short* r3 = &S.hid[(48 + g) * HP];
        #pragma unroll 8
        for (int kb = 0; kb < 64; kb++) {
            float4 wp = wpt[kb];
            uint2 u0 = *(const uint2*)&r0[kb * 4];
            uint2 u1 = *(const uint2*)&r1[kb * 4];
            uint2 u2 = *(const uint2*)&r2[kb * 4];
            uint2 u3 = *(const uint2*)&r3[kb * 4];
            float2 a0 = __half22float2(*(half2*)&u0.x), b0 = __half22float2(*(half2*)&u0.y);
            float2 a1 = __half22float2(*(half2*)&u1.x), b1 = __half22float2(*(half2*)&u1.y);
            float2 a2 = __half22float2(*(half2*)&u2.x), b2 = __half22float2(*(half2*)&u2.y);
            float2 a3 = __half22float2(*(half2*)&u3.x), b3 = __half22float2(*(half2*)&u3.y);
            acc0 = fmaf(wp.x, a0.x, acc0); acc0 = fmaf(wp.y, a0.y, acc0);
            acc0 = fmaf(wp.z, b0.x, acc0); acc0 = fmaf(wp.w, b0.y, acc0);
            acc1 = fmaf(wp.x, a1.x, acc1); acc1 = fmaf(wp.y, a1.y, acc1);
            acc1 = fmaf(wp.z, b1.x, acc1); acc1 = fmaf(wp.w, b1.y, acc1);
            acc2 = fmaf(wp.x, a2.x, acc2); acc2 = fmaf(wp.y, a2.y, acc2);
            acc2 = fmaf(wp.z, b2.x, acc2); acc2 = fmaf(wp.w, b2.y, acc2);
            acc3 = fmaf(wp.x, a3.x, acc3); acc3 = fmaf(wp.y, a3.y, acc3);
            acc3 = fmaf(wp.z, b3.x, acc3); acc3 = fmaf(wp.w, b3.y, acc3);
        }
        out[(n0 + 0) * C + c] = acc0;
        out[(n0 + 1) * C + c] = acc1;
        out[(n0 + 2) * C + c] = acc2;
        out[(n0 + 3) * C + c] = acc3;
    }
}

// ---------------- launch ----------------------------------------------------
extern "C" void kernel_launch(void* const* d_in, const int* in_sizes, int n_in,
                              void* d_out, int out_size) {
    (void)in_sizes; (void)n_in; (void)out_size;
    const float* feat  = (const float*)d_in[0];
    const float* coord = (const float*)d_in[1];
    const int*   knn   = (const int*)  d_in[2];
    const float* Wq = (const float*)d_in[3];  const float* bq = (const float*)d_in[4];  const float* bnq = (const float*)d_in[5];
    const float* Wk = (const float*)d_in[6];  const float* bk = (const float*)d_in[7];  const float* bnk = (const float*)d_in[8];
    const float* Wv = (const float*)d_in[9];  const float* bv = (const float*)d_in[10];
    const float* Wp1 = (const float*)d_in[11]; const float* bp1 = (const float*)d_in[12]; const float* bnp = (const float*)d_in[13];
    const float* Wp2 = (const float*)d_in[14]; const float* bp2 = (const float*)d_in[15];
    const float* Ww1 = (const float*)d_in[16]; const float* bw1 = (const float*)d_in[17]; const float* bnw = (const float*)d_in[18];
    const float* Ww2 = (const float*)d_in[19]; const float* bw2 = (const float*)d_in[20];
    float* out = (float*)d_out;

    int k1_smem = (BM * FS + BM * YS) * 4 + 4096 * 4;
    cudaFuncSetAttribute(k1_qkv,  cudaFuncAttributeMaxDynamicSharedMemorySize, k1_smem);
    cudaFuncSetAttribute(k2_attn, cudaFuncAttributeMaxDynamicSharedMemorySize, (int)sizeof(K2S));

    unsigned* wfrag;
    cudaGetSymbolAddress((void**)&wfrag, g_wfrag);

    prep_fold<<<1, 256>>>(bq, bnq, bk, bnk, bp1, bnp, bw1, bnw, bp2, Ww1);
    prep_wp2t<<<C, C>>>(Wp2);
    prep_afrag16<<<4, 256>>>(Wp2, Ww1);
    prep_w1frag<<<8, 256>>>(Ww1);
    prep_wfrag<<<32, 1024>>>(Wq, wfrag);
    prep_wfrag<<<32, 1024>>>(Wk, wfrag + 32 * 32 * 64);
    prep_wfrag<<<32, 1024>>>(Wv, wfrag + 2 * 32 * 32 * 64);
    k1_qkv<<<NPTS / BM, 256, k1_smem>>>(feat, bv);
    k2_attn<<<NPTS / P, 256, sizeof(K2S)>>>(coord, knn, Wp1, bp2, Ww2, bw2, out);
}

// round 10
// speedup vs baseline: 1.3266x; 1.3266x over previous
#include <cuda_runtime.h>
#include <cuda_fp16.h>
#include <math.h>

#define NPTS 20000
#define KNN  16
#define C    256
#define G    16
#define EPS  1e-5f
#define P    4          // points per block in K2
#define BM   32         // feat rows per block in K1
#define FS   260        // k1 feat_s stride (words)
#define YS   260        // k1 ybuf stride (words)
#define HP   264        // k2 hid row stride in halves
#define LGS  20         // logit buffer row stride

typedef unsigned long long ull;

// ---------------- scratch (static device memory) ---------------------------
__device__ __half   g_vall16[NPTS * C];         // v_all, fp16
__device__ float    g_qW[NPTS * G];
__device__ float    g_kW[NPTS * G];
__device__ unsigned g_wfrag[3 * 32 * 32 * 64];  // W q/k/v tf32 B-frags (k1)
__device__ unsigned g_w1frag[4096];             // ww1 tf32 B-frags (k1 projection)
__device__ unsigned g_afrag16[2048];            // (Wp2@Ww1) fp16 B-frags (k2)
__device__ __half   g_wp2t16[C * C];            // Wp2^T fp16: [c][k]
__device__ float    g_sq[C], g_tq[C];
__device__ float    g_sk[C], g_tk[C];
__device__ float    g_sp[C], g_tp[C];
__device__ float    g_sw[G], g_cw[G];

// ---------------- helpers ---------------------------------------------------
__device__ __forceinline__ unsigned f2tf(float x) {
    unsigned r;
    asm("cvt.rna.tf32.f32 %0, %1;" : "=r"(r) : "f"(x));
    return r;
}
__device__ __forceinline__ unsigned smem_u32(const void* p) {
    unsigned r;
    asm("{ .reg .u64 t; cvta.to.shared.u64 t, %1; cvt.u32.u64 %0, t; }"
        : "=r"(r) : "l"(p));
    return r;
}
#define CP_ASYNC16(dst, src) \
    asm volatile("cp.async.ca.shared.global [%0], [%1], 16;" :: "r"(dst), "l"(src))
#define MMA_TF32(acc, a0, a1, a2, a3, b0, b1)                                   \
    asm("mma.sync.aligned.m16n8k8.row.col.f32.tf32.tf32.f32 "                   \
        "{%0,%1,%2,%3},{%4,%5,%6,%7},{%8,%9},{%0,%1,%2,%3};"                    \
        : "+f"(acc.x), "+f"(acc.y), "+f"(acc.z), "+f"(acc.w)                    \
        : "r"(a0), "r"(a1), "r"(a2), "r"(a3), "r"(b0), "r"(b1))
#define MMA_F16(acc, a0, a1, a2, a3, b0, b1)                                    \
    asm("mma.sync.aligned.m16n8k16.row.col.f32.f16.f16.f32 "                    \
        "{%0,%1,%2,%3},{%4,%5,%6,%7},{%8,%9},{%0,%1,%2,%3};"                    \
        : "+f"(acc.x), "+f"(acc.y), "+f"(acc.z), "+f"(acc.w)                    \
        : "r"(a0), "r"(a1), "r"(a2), "r"(a3), "r"(b0), "r"(b1))

// ---------------- prep kernels ---------------------------------------------
__global__ void prep_fold(const float* __restrict__ bq, const float* __restrict__ bnq,
                          const float* __restrict__ bk, const float* __restrict__ bnk,
                          const float* __restrict__ bp1, const float* __restrict__ bnp,
                          const float* __restrict__ bw1, const float* __restrict__ bnw,
                          const float* __restrict__ bp2, const float* __restrict__ ww1) {
    int t = threadIdx.x;
    if (t < C) {
        float s;
        s = bnq[t] * rsqrtf(bnq[3 * C + t] + EPS);
        g_sq[t] = s; g_tq[t] = (bq[t] - bnq[2 * C + t]) * s + bnq[C + t];
        s = bnk[t] * rsqrtf(bnk[3 * C + t] + EPS);
        g_sk[t] = s; g_tk[t] = (bk[t] - bnk[2 * C + t]) * s + bnk[C + t];
        s = bnp[t] * rsqrtf(bnp[3 * C + t] + EPS);
        g_sp[t] = s; g_tp[t] = (bp1[t] - bnp[2 * C + t]) * s + bnp[C + t];
    }
    if (t < G) {
        float s = bnw[t] * rsqrtf(bnw[3 * G + t] + EPS);
        float bp2w = 0.f;
        for (int c = 0; c < C; c++) bp2w += bp2[c] * ww1[c * G + t];
        g_sw[t] = s;
        g_cw[t] = (bw1[t] + bp2w - bnw[2 * G + t]) * s + bnw[G + t];
    }
}

__global__ void prep_wfrag(const float* __restrict__ W, unsigned* __restrict__ dst) {
    int kb = blockIdx.x;
    int i  = threadIdx.x;
    int nb = i >> 5, lane = i & 31;
    int gid = lane >> 2, tig = lane & 3;
    int k0 = kb * 8 + tig, n = nb * 8 + gid;
    dst[((kb * 32 + nb) * 32 + lane) * 2 + 0] = f2tf(W[k0 * C + n]);
    dst[((kb * 32 + nb) * 32 + lane) * 2 + 1] = f2tf(W[(k0 + 4) * C + n]);
}

__global__ void prep_w1frag(const float* __restrict__ ww1) {
    int idx  = blockIdx.x * 256 + threadIdx.x;
    int lane = idx & 31, knb = idx >> 5;
    int kb = knb >> 1, nb = knb & 1;
    int gid = lane >> 2, tig = lane & 3;
    int n  = nb * 8 + gid;
    int k0 = kb * 8 + tig;
    g_w1frag[idx * 2 + 0] = f2tf(ww1[k0 * G + n]);
    g_w1frag[idx * 2 + 1] = f2tf(ww1[(k0 + 4) * G + n]);
}

__global__ void prep_afrag16(const float* __restrict__ wp2, const float* __restrict__ ww1) {
    int idx  = blockIdx.x * 256 + threadIdx.x;
    int lane = idx & 31, knb = idx >> 5;
    int kb = knb >> 1, nb = knb & 1;
    int gid = lane >> 2, tig = lane & 3;
    int g  = nb * 8 + gid;
    int k0 = kb * 16 + tig * 2;
    float d0 = 0.f, d1 = 0.f, d2 = 0.f, d3 = 0.f;
    #pragma unroll 4
    for (int c = 0; c < C; c++) {
        float w = ww1[c * G + g];
        d0 = fmaf(wp2[(k0)     * C + c], w, d0);
        d1 = fmaf(wp2[(k0 + 1) * C + c], w, d1);
        d2 = fmaf(wp2[(k0 + 8) * C + c], w, d2);
        d3 = fmaf(wp2[(k0 + 9) * C + c], w, d3);
    }
    half2 b0 = __floats2half2_rn(d0, d1);
    half2 b1 = __floats2half2_rn(d2, d3);
    g_afrag16[idx * 2 + 0] = *(unsigned*)&b0;
    g_afrag16[idx * 2 + 1] = *(unsigned*)&b1;
}

__global__ void prep_wp2t16(const float* __restrict__ wp2) {
    int k = blockIdx.x, c = threadIdx.x;
    g_wp2t16[c * C + k] = __float2half(wp2[k * C + c]);
}

// ---------------- K1: q/k/v GEMM + projection, all TF32 mma ----------------
__global__ __launch_bounds__(256, 2) void k1_qkv(
    const float* __restrict__ feat, const float* __restrict__ bv) {
    extern __shared__ float sm[];
    float* feat_s = sm;
    float* ybuf   = sm + BM * FS;
    unsigned* ww1f = (unsigned*)(sm + BM * FS + BM * YS);
    unsigned* featu = (unsigned*)feat_s;

    int t    = threadIdx.x;
    int r0b  = blockIdx.x * BM;
    int warp = t >> 5, lane = t & 31;
    int gid  = lane >> 2, tig = lane & 3;
    int n0   = warp * 32;

    for (int i = t; i < BM * C / 4; i += 256) {
        int r = i >> 6, c4 = (i & 63) * 4;
        float4 f = *(const float4*)&feat[(r0b + r) * C + c4];
        featu[r * FS + c4 + 0] = f2tf(f.x);
        featu[r * FS + c4 + 1] = f2tf(f.y);
        featu[r * FS + c4 + 2] = f2tf(f.z);
        featu[r * FS + c4 + 3] = f2tf(f.w);
    }
    for (int i = t; i < 1024; i += 256)
        *(uint4*)&ww1f[i * 4] = *(const uint4*)&g_w1frag[i * 4];
    __syncthreads();

    #pragma unroll 1
    for (int pass = 0; pass < 3; pass++) {
        const ull* wf = (const ull*)(g_wfrag + pass * (32 * 32 * 64));
        float4 acc[2][4];
        #pragma unroll
        for (int mt = 0; mt < 2; mt++)
            #pragma unroll
            for (int nt = 0; nt < 4; nt++) acc[mt][nt] = make_float4(0.f, 0.f, 0.f, 0.f);

        #pragma unroll 4
        for (int kb = 0; kb < 32; kb++) {
            unsigned a0 = featu[(gid)      * FS + kb * 8 + tig];
            unsigned a1 = featu[(gid + 8)  * FS + kb * 8 + tig];
            unsigned a2 = featu[(gid)      * FS + kb * 8 + tig + 4];
            unsigned a3 = featu[(gid + 8)  * FS + kb * 8 + tig + 4];
            unsigned a4 = featu[(gid + 16) * FS + kb * 8 + tig];
            unsigned a5 = featu[(gid + 24) * FS + kb * 8 + tig];
            unsigned a6 = featu[(gid + 16) * FS + kb * 8 + tig + 4];
            unsigned a7 = featu[(gid + 24) * FS + kb * 8 + tig + 4];
            #pragma unroll
            for (int nt = 0; nt < 4; nt++) {
                ull bb = wf[(kb * 32 + warp * 4 + nt) * 32 + lane];
                unsigned b0 = (unsigned)bb, b1 = (unsigned)(bb >> 32);
                MMA_TF32(acc[0][nt], a0, a1, a2, a3, b0, b1);
                MMA_TF32(acc[1][nt], a4, a5, a6, a7, b0, b1);
            }
        }

        if (pass == 2) {
            #pragma unroll
            for (int nt = 0; nt < 4; nt++) {
                int col = n0 + nt * 8 + tig * 2;
                float2 b2 = *(const float2*)&bv[col];
                #pragma unroll
                for (int mt = 0; mt < 2; mt++) {
                    int rA = r0b + mt * 16 + gid, rB = rA + 8;
                    *(half2*)&g_vall16[rA * C + col] =
                        __floats2half2_rn(acc[mt][nt].x + b2.x, acc[mt][nt].y + b2.y);
                    *(half2*)&g_vall16[rB * C + col] =
                        __floats2half2_rn(acc[mt][nt].z + b2.x, acc[mt][nt].w + b2.y);
                }
            }
        } else {
            const float* sA = (pass == 0) ? g_sq : g_sk;
            const float* tA = (pass == 0) ? g_tq : g_tk;
            #pragma unroll
            for (int nt = 0; nt < 4; nt++) {
                int col = n0 + nt * 8 + tig * 2;
                float2 s2 = *(const float2*)&sA[col];
                float2 t2 = *(const float2*)&tA[col];
                #pragma unroll
                for (int mt = 0; mt < 2; mt++) {
                    int rA = mt * 16 + gid, rB = rA + 8;
                    *(float2*)&ybuf[rA * YS + col] = make_float2(
                        fmaxf(fmaf(acc[mt][nt].x, s2.x, t2.x), 0.f),
                        fmaxf(fmaf(acc[mt][nt].y, s2.y, t2.y), 0.f));
                    *(float2*)&ybuf[rB * YS + col] = make_float2(
                        fmaxf(fmaf(acc[mt][nt].z, s2.x, t2.x), 0.f),
                        fmaxf(fmaf(acc[mt][nt].w, s2.y, t2.y), 0.f));
                }
            }
            __syncthreads();
            if (warp < 4) {
                int m0p = (warp & 1) * 16, nbp = warp >> 1;
                float4 pa = make_float4(0.f, 0.f, 0.f, 0.f);
                #pragma unroll 8
                for (int kb = 0; kb < 32; kb++) {
                    unsigned a0 = f2tf(ybuf[(m0p + gid)     * YS + kb * 8 + tig]);
                    unsigned a1 = f2tf(ybuf[(m0p + gid + 8) * YS + kb * 8 + tig]);
                    unsigned a2 = f2tf(ybuf[(m0p + gid)     * YS + kb * 8 + tig + 4]);
                    unsigned a3 = f2tf(ybuf[(m0p + gid + 8) * YS + kb * 8 + tig + 4]);
                    ull bb = *(const ull*)&ww1f[((kb * 2 + nbp) * 32 + lane) * 2];
                    MMA_TF32(pa, a0, a1, a2, a3, (unsigned)bb, (unsigned)(bb >> 32));
                }
                float* dst = (pass == 0) ? g_qW : g_kW;
                int col = nbp * 8 + tig * 2;
                dst[(r0b + m0p + gid)     * G + col]     = pa.x;
                dst[(r0b + m0p + gid)     * G + col + 1] = pa.y;
                dst[(r0b + m0p + gid + 8) * G + col]     = pa.z;
                dst[(r0b + m0p + gid + 8) * G + col + 1] = pa.w;
            }
            __syncthreads();
        }
    }
}

// ---------------- K2: fused per-point grouped attention -------------------
struct K2S {
    unsigned short hid[P * 16 * HP];  // 33792 B; fp16; becomes hw in place
    unsigned afrag[2048];
    float    lg[64 * LGS];
    float    buf2[64 * G];
    float    vterm[4 * 256];
    float    kwq[64 * 16];
    float    qwb[4 * 16];
    float    pos[64 * 4];
    float    wsum[P * G];
    float    mask[64];
    int      idx[64];
    float    ww2[G * G];
    float    sw[G], cw[G], bw2s[G];
};

__global__ __launch_bounds__(256, 3) void k2_attn(
    const float* __restrict__ coord, const int* __restrict__ knn,
    const float* __restrict__ wp1,   const float* __restrict__ bp2,
    const float* __restrict__ ww2,   const float* __restrict__ bw2,
    float* __restrict__ out) {
    extern __shared__ char smraw[];
    K2S& S = *reinterpret_cast<K2S*>(smraw);
    int t  = threadIdx.x;
    int n0 = blockIdx.x * P;

    for (int i = t; i < 512; i += 256)
        *(uint4*)&S.afrag[i * 4] = *(const uint4*)&g_afrag16[i * 4];
    S.ww2[t] = ww2[t];
    if (t < G) { S.sw[t] = g_sw[t]; S.cw[t] = g_cw[t]; S.bw2s[t] = bw2[t]; }

    // phase 1: gather idx / mask / pos + cp.async prefetch of kW/qW rows
    if (t < 64) {
        int p = t >> 4, n = n0 + p;
        int id  = knn[n * KNN + (t & 15)];
        int ip1 = id + 1;
        float m = (float)((ip1 > 0) - (ip1 < 0));
        int sid = (id > 0) ? id : 0;
        S.idx[t]  = sid;
        S.mask[t] = m;
        #pragma unroll
        for (int d = 0; d < 3; d++)
            S.pos[t * 4 + d] = (coord[sid * 3 + d] - coord[n * 3 + d]) * m;
        unsigned d0 = smem_u32(&S.kwq[t * 16]);
        const float* s0 = &g_kW[sid * G];
        #pragma unroll
        for (int j = 0; j < 4; j++) CP_ASYNC16(d0 + j * 16, s0 + j * 4);
        if (t < 4) {
            unsigned d1 = smem_u32(&S.qwb[t * 16]);
            const float* s1 = &g_qW[(n0 + t) * G];
            #pragma unroll
            for (int j = 0; j < 4; j++) CP_ASYNC16(d1 + j * 16, s1 + j * 4);
        }
        asm volatile("cp.async.commit_group;");
    }
    __syncthreads();

    // phase 2: hidden = relu(bn(pos @ Wp1 + bp1)) -> fp16
    {
        int half_ = t >> 7;
        int cp = (t & 127) * 2;
        float2 w0 = *(const float2*)&wp1[cp];
        float2 w1 = *(const float2*)&wp1[C + cp];
        float2 w2 = *(const float2*)&wp1[2 * C + cp];
        float2 sc = *(const float2*)&g_sp[cp];
        float2 sh = *(const float2*)&g_tp[cp];
        #pragma unroll 4
        for (int ps = half_ * 32; ps < half_ * 32 + 32; ps++) {
            float px = S.pos[ps * 4 + 0];
            float py = S.pos[ps * 4 + 1];
            float pz = S.pos[ps * 4 + 2];
            float h0 = fmaf(px, w0.x, fmaf(py, w1.x, pz * w2.x));
            float h1 = fmaf(px, w0.y, fmaf(py, w1.y, pz * w2.y));
            h0 = fmaxf(fmaf(h0, sc.x, sh.x), 0.f);
            h1 = fmaxf(fmaf(h1, sc.y, sh.y), 0.f);
            *(half2*)&S.hid[ps * HP + cp] = __floats2half2_rn(h0, h1);
        }
    }
    __syncthreads();

    // phase 3a: lg = hidden @ A via fp16 mma m16n8k16
    {
        int w = t >> 5, lane = t & 31, gid = lane >> 2, tig = lane & 3;
        int m0 = (w & 3) * 16, nb = w >> 2;
        float4 acc = make_float4(0.f, 0.f, 0.f, 0.f);
        const ull* bf = (const ull*)S.afrag;
        #pragma unroll
        for (int kb = 0; kb < 16; kb++) {
            unsigned a0 = *(const unsigned*)&S.hid[(m0 + gid)     * HP + kb * 16 + tig * 2];
            unsigned a1 = *(const unsigned*)&S.hid[(m0 + gid + 8) * HP + kb * 16 + tig * 2];
            unsigned a2 = *(const unsigned*)&S.hid[(m0 + gid)     * HP + kb * 16 + tig * 2 + 8];
            unsigned a3 = *(const unsigned*)&S.hid[(m0 + gid + 8) * HP + kb * 16 + tig * 2 + 8];
            ull bb = bf[(kb * 2 + nb) * 32 + lane];
            unsigned b0 = (unsigned)bb, b1 = (unsigned)(bb >> 32);
            MMA_F16(acc, a0, a1, a2, a3, b0, b1);
        }
        S.lg[(m0 + gid)     * LGS + nb * 8 + tig * 2]     = acc.x;
        S.lg[(m0 + gid)     * LGS + nb * 8 + tig * 2 + 1] = acc.y;
        S.lg[(m0 + gid + 8) * LGS + nb * 8 + tig * 2]     = acc.z;
        S.lg[(m0 + gid + 8) * LGS + nb * 8 + tig * 2 + 1] = acc.w;
    }
    __syncthreads();

    // phase 3b (warps 0-1): + lb, relu/sw/cw, @Ww2 -> buf2; then 4a softmax
    if (t < 64) {
        asm volatile("cp.async.wait_group 0;" ::: "memory");
        int r = t, p = r >> 4;
        float m = S.mask[r];
        const float4* kw = (const float4*)&S.kwq[r * 16];
        const float4* qw = (const float4*)&S.qwb[p * 16];
        float u[16];
        #pragma unroll
        for (int q = 0; q < 4; q++) {
            float4 sv = *(const float4*)&S.lg[r * LGS + q * 4];
            float4 kv = kw[q], qv = qw[q];
            float4 lb;
            lb.x = fmaf(m, kv.x, -qv.x); lb.y = fmaf(m, kv.y, -qv.y);
            lb.z = fmaf(m, kv.z, -qv.z); lb.w = fmaf(m, kv.w, -qv.w);
            u[q*4+0] = fmaxf(fmaf(sv.x + lb.x, S.sw[q*4+0], S.cw[q*4+0]), 0.f);
            u[q*4+1] = fmaxf(fmaf(sv.y + lb.y, S.sw[q*4+1], S.cw[q*4+1]), 0.f);
            u[q*4+2] = fmaxf(fmaf(sv.z + lb.z, S.sw[q*4+2], S.cw[q*4+2]), 0.f);
            u[q*4+3] = fmaxf(fmaf(sv.w + lb.w, S.sw[q*4+3], S.cw[q*4+3]), 0.f);
        }
        #pragma unroll
        for (int g2 = 0; g2 < 16; g2++) {
            float acc = S.bw2s[g2];
            #pragma unroll
            for (int g = 0; g < 16; g++) acc = fmaf(u[g], S.ww2[g * 16 + g2], acc);
            S.buf2[r * 16 + g2] = acc;
        }
        __syncwarp();
        int pp = t >> 4, g = t & 15;
        float mx = -1e30f;
        #pragma unroll
        for (int s = 0; s < 16; s++) mx = fmaxf(mx, S.buf2[(pp * 16 + s) * 16 + g]);
        float e[16], sum = 0.f;
        #pragma unroll
        for (int s = 0; s < 16; s++) {
            e[s] = __expf(S.buf2[(pp * 16 + s) * 16 + g] - mx);
            sum += e[s];
        }
        float inv = 1.f / sum, ws = 0.f;
        #pragma unroll
        for (int s = 0; s < 16; s++) {
            float w = e[s] * inv * S.mask[pp * 16 + s];
            S.buf2[(pp * 16 + s) * 16 + g] = w;
            ws += w;
        }
        S.wsum[t] = ws;
    }
    __syncthreads();

    // phase 4A: v-gather, all 256 threads: thread = (point, 4-channel chunk)
    {
        int p  = t >> 6;
        int c0 = (t & 63) * 4;
        int g  = c0 >> 4;
        float a0 = 0.f, a1 = 0.f, a2 = 0.f, a3 = 0.f;
        #pragma unroll
        for (int s = 0; s < 16; s++) {
            float w = S.buf2[(p * 16 + s) * 16 + g];
            uint2 v = *(const uint2*)&g_vall16[S.idx[p * 16 + s] * C + c0];
            float2 v0 = __half22float2(*(half2*)&v.x);
            float2 v1 = __half22float2(*(half2*)&v.y);
            a0 = fmaf(w, v0.x, a0); a1 = fmaf(w, v0.y, a1);
            a2 = fmaf(w, v1.x, a2); a3 = fmaf(w, v1.y, a3);
        }
        *(float4*)&S.vterm[p * 256 + c0] = make_float4(a0, a1, a2, a3);
    }
    // phase 4B: hw[p][g][c] = sum_s w*hid, in place, 2 slots/thread (R8 form)
    {
        #pragma unroll
        for (int j = 0; j < 2; j++) {
            int si = t + j * 256;
            int p = si >> 7, cq = (si & 127) * 2;
            float2 acc[16];
            #pragma unroll
            for (int g = 0; g < 16; g++) acc[g] = make_float2(0.f, 0.f);
            #pragma unroll
            for (int s = 0; s < 16; s++) {
                float2 h = __half22float2(*(const half2*)&S.hid[(p * 16 + s) * HP + cq]);
                const float4* wr = (const float4*)&S.buf2[(p * 16 + s) * 16];
                #pragma unroll
                for (int q = 0; q < 4; q++) {
                    float4 w = wr[q];
                    acc[q*4+0].x = fmaf(w.x, h.x, acc[q*4+0].x); acc[q*4+0].y = fmaf(w.x, h.y, acc[q*4+0].y);
                    acc[q*4+1].x = fmaf(w.y, h.x, acc[q*4+1].x); acc[q*4+1].y = fmaf(w.y, h.y, acc[q*4+1].y);
                    acc[q*4+2].x = fmaf(w.z, h.x, acc[q*4+2].x); acc[q*4+2].y = fmaf(w.z, h.y, acc[q*4+2].y);
                    acc[q*4+3].x = fmaf(w.w, h.x, acc[q*4+3].x); acc[q*4+3].y = fmaf(w.w, h.y, acc[q*4+3].y);
                }
            }
            #pragma unroll
            for (int g = 0; g < 16; g++)
                *(half2*)&S.hid[(p * 16 + g) * HP + cq] = __floats2half2_rn(acc[g].x, acc[g].y);
        }
    }
    __syncthreads();

    // phase 5: out = vterm + hw @ Wp2^T (fp16) + bp2*wsum
    {
        int c = t, g = c >> 4;
        float b = __ldg(&bp2[c]);
        float acc0 = S.vterm[c]       + b * S.wsum[g];
        float acc1 = S.vterm[256 + c] + b * S.wsum[16 + g];
        float acc2 = S.vterm[512 + c] + b * S.wsum[32 + g];
        float acc3 = S.vterm[768 + c] + b * S.wsum[48 + g];

        const uint4* wpt = (const uint4*)&g_wp2t16[c * C];
        const unsigned short* r0 = &S.hid[(g)      * HP];
        const unsigned short* r1 = &S.hid[(16 + g) * HP];
        const unsigned short* r2 = &S.hid[(32 + g) * HP];
        const unsigned short* r3 = &S.hid[(48 + g) * HP];
        #pragma unroll 4
        for (int kb = 0; kb < 32; kb++) {
            uint4 wpu = wpt[kb];   // 8 halves of Wp2^T row c
            float2 w0 = __half22float2(*(half2*)&wpu.x);
            float2 w1 = __half22float2(*(half2*)&wpu.y);
            float2 w2 = __half22float2(*(half2*)&wpu.z);
            float2 w3 = __half22float2(*(half2*)&wpu.w);
            uint4 u0 = *(const uint4*)&r0[kb * 8];
            uint4 u1 = *(const uint4*)&r1[kb * 8];
            uint4 u2 = *(const uint4*)&r2[kb * 8];
            uint4 u3 = *(const uint4*)&r3[kb * 8];
            float2 h00 = __half22float2(*(half2*)&u0.x), h01 = __half22float2(*(half2*)&u0.y);
            float2 h02 = __half22float2(*(half2*)&u0.z), h03 = __half22float2(*(half2*)&u0.w);
            float2 h10 = __half22float2(*(half2*)&u1.x), h11 = __half22float2(*(half2*)&u1.y);
            float2 h12 = __half22float2(*(half2*)&u1.z), h13 = __half22float2(*(half2*)&u1.w);
            float2 h20 = __half22float2(*(half2*)&u2.x), h21 = __half22float2(*(half2*)&u2.y);
            float2 h22 = __half22float2(*(half2*)&u2.z), h23 = __half22float2(*(half2*)&u2.w);
            float2 h30 = __half22float2(*(half2*)&u3.x), h31 = __half22float2(*(half2*)&u3.y);
            float2 h32 = __half22float2(*(half2*)&u3.z), h33 = __half22float2(*(half2*)&u3.w);
            acc0 = fmaf(w0.x, h00.x, acc0); acc0 = fmaf(w0.y, h00.y, acc0);
            acc0 = fmaf(w1.x, h01.x, acc0); acc0 = fmaf(w1.y, h01.y, acc0);
            acc0 = fmaf(w2.x, h02.x, acc0); acc0 = fmaf(w2.y, h02.y, acc0);
            acc0 = fmaf(w3.x, h03.x, acc0); acc0 = fmaf(w3.y, h03.y, acc0);
            acc1 = fmaf(w0.x, h10.x, acc1); acc1 = fmaf(w0.y, h10.y, acc1);
            acc1 = fmaf(w1.x, h11.x, acc1); acc1 = fmaf(w1.y, h11.y, acc1);
            acc1 = fmaf(w2.x, h12.x, acc1); acc1 = fmaf(w2.y, h12.y, acc1);
            acc1 = fmaf(w3.x, h13.x, acc1); acc1 = fmaf(w3.y, h13.y, acc1);
            acc2 = fmaf(w0.x, h20.x, acc2); acc2 = fmaf(w0.y, h20.y, acc2);
            acc2 = fmaf(w1.x, h21.x, acc2); acc2 = fmaf(w1.y, h21.y, acc2);
            acc2 = fmaf(w2.x, h22.x, acc2); acc2 = fmaf(w2.y, h22.y, acc2);
            acc2 = fmaf(w3.x, h23.x, acc2); acc2 = fmaf(w3.y, h23.y, acc2);
            acc3 = fmaf(w0.x, h30.x, acc3); acc3 = fmaf(w0.y, h30.y, acc3);
            acc3 = fmaf(w1.x, h31.x, acc3); acc3 = fmaf(w1.y, h31.y, acc3);
            acc3 = fmaf(w2.x, h32.x, acc3); acc3 = fmaf(w2.y, h32.y, acc3);
            acc3 = fmaf(w3.x, h33.x, acc3); acc3 = fmaf(w3.y, h33.y, acc3);
        }
        out[(n0 + 0) * C + c] = acc0;
        out[(n0 + 1) * C + c] = acc1;
        out[(n0 + 2) * C + c] = acc2;
        out[(n0 + 3) * C + c] = acc3;
    }
}

// ---------------- launch ----------------------------------------------------
extern "C" void kernel_launch(void* const* d_in, const int* in_sizes, int n_in,
                              void* d_out, int out_size) {
    (void)in_sizes; (void)n_in; (void)out_size;
    const float* feat  = (const float*)d_in[0];
    const float* coord = (const float*)d_in[1];
    const int*   knn   = (const int*)  d_in[2];
    const float* Wq = (const float*)d_in[3];  const float* bq = (const float*)d_in[4];  const float* bnq = (const float*)d_in[5];
    const float* Wk = (const float*)d_in[6];  const float* bk = (const float*)d_in[7];  const float* bnk = (const float*)d_in[8];
    const float* Wv = (const float*)d_in[9];  const float* bv = (const float*)d_in[10];
    const float* Wp1 = (const float*)d_in[11]; const float* bp1 = (const float*)d_in[12]; const float* bnp = (const float*)d_in[13];
    const float* Wp2 = (const float*)d_in[14]; const float* bp2 = (const float*)d_in[15];
    const float* Ww1 = (const float*)d_in[16]; const float* bw1 = (const float*)d_in[17]; const float* bnw = (const float*)d_in[18];
    const float* Ww2 = (const float*)d_in[19]; const float* bw2 = (const float*)d_in[20];
    float* out = (float*)d_out;

    int k1_smem = (BM * FS + BM * YS) * 4 + 4096 * 4;
    cudaFuncSetAttribute(k1_qkv,  cudaFuncAttributeMaxDynamicSharedMemorySize, k1_smem);
    cudaFuncSetAttribute(k2_attn, cudaFuncAttributeMaxDynamicSharedMemorySize, (int)sizeof(K2S));

    unsigned* wfrag;
    cudaGetSymbolAddress((void**)&wfrag, g_wfrag);

    prep_fold<<<1, 256>>>(bq, bnq, bk, bnk, bp1, bnp, bw1, bnw, bp2, Ww1);
    prep_wp2t16<<<C, C>>>(Wp2);
    prep_afrag16<<<4, 256>>>(Wp2, Ww1);
    prep_w1frag<<<8, 256>>>(Ww1);
    prep_wfrag<<<32, 1024>>>(Wq, wfrag);
    prep_wfrag<<<32, 1024>>>(Wk, wfrag + 32 * 32 * 64);
    prep_wfrag<<<32, 1024>>>(Wv, wfrag + 2 * 32 * 32 * 64);
    k1_qkv<<<NPTS / BM, 256, k1_smem>>>(feat, bv);
    k2_attn<<<NPTS / P, 256, sizeof(K2S)>>>(coord, knn, Wp1, bp2, Ww2, bw2, out);
}

// round 11
// speedup vs baseline: 1.6989x; 1.2807x over previous
#include <cuda_runtime.h>
#include <cuda_fp16.h>
#include <math.h>

#define NPTS 20000
#define KNN  16
#define C    256
#define G    16
#define EPS  1e-5f
#define P    8          // points per block in K2
#define BM   32         // feat rows per block in K1
#define FSH  264        // k1 feat_s stride (halves)
#define YS   260        // k1 ybuf stride (words)
#define HP   264        // k2 hid row stride in halves
#define LGS  20         // k2 logit/weight buffer row stride (floats)

typedef unsigned long long ull;

// ---------------- scratch (static device memory) ---------------------------
__device__ __half   g_vall16[NPTS * C];          // v_all, fp16
__device__ float    g_qW[NPTS * G];
__device__ float    g_kW[NPTS * G];
__device__ unsigned g_wfrag16[3 * 16 * 32 * 64]; // W q/k/v fp16 B-frags (k1)
__device__ unsigned g_w1frag[4096];              // ww1 tf32 B-frags (k1 projection)
__device__ unsigned g_afrag16[2048];             // (Wp2@Ww1) fp16 B-frags (k2)
__device__ __half   g_wp2t16[C * C];             // Wp2^T fp16: [c][k]
__device__ float    g_sq[C], g_tq[C];
__device__ float    g_sk[C], g_tk[C];
__device__ float    g_sp[C], g_tp[C];
__device__ float    g_sw[G], g_cw[G];

// ---------------- helpers ---------------------------------------------------
__device__ __forceinline__ unsigned f2tf(float x) {
    unsigned r;
    asm("cvt.rna.tf32.f32 %0, %1;" : "=r"(r) : "f"(x));
    return r;
}
__device__ __forceinline__ unsigned smem_u32(const void* p) {
    unsigned r;
    asm("{ .reg .u64 t; cvta.to.shared.u64 t, %1; cvt.u32.u64 %0, t; }"
        : "=r"(r) : "l"(p));
    return r;
}
#define CP_ASYNC16(dst, src) \
    asm volatile("cp.async.ca.shared.global [%0], [%1], 16;" :: "r"(dst), "l"(src))
#define MMA_TF32(acc, a0, a1, a2, a3, b0, b1)                                   \
    asm("mma.sync.aligned.m16n8k8.row.col.f32.tf32.tf32.f32 "                   \
        "{%0,%1,%2,%3},{%4,%5,%6,%7},{%8,%9},{%0,%1,%2,%3};"                    \
        : "+f"(acc.x), "+f"(acc.y), "+f"(acc.z), "+f"(acc.w)                    \
        : "r"(a0), "r"(a1), "r"(a2), "r"(a3), "r"(b0), "r"(b1))
#define MMA_F16(acc, a0, a1, a2, a3, b0, b1)                                    \
    asm("mma.sync.aligned.m16n8k16.row.col.f32.f16.f16.f32 "                    \
        "{%0,%1,%2,%3},{%4,%5,%6,%7},{%8,%9},{%0,%1,%2,%3};"                    \
        : "+f"(acc.x), "+f"(acc.y), "+f"(acc.z), "+f"(acc.w)                    \
        : "r"(a0), "r"(a1), "r"(a2), "r"(a3), "r"(b0), "r"(b1))

// ---------------- prep kernels ---------------------------------------------
__global__ void prep_fold(const float* __restrict__ bq, const float* __restrict__ bnq,
                          const float* __restrict__ bk, const float* __restrict__ bnk,
                          const float* __restrict__ bp1, const float* __restrict__ bnp,
                          const float* __restrict__ bw1, const float* __restrict__ bnw,
                          const float* __restrict__ bp2, const float* __restrict__ ww1) {
    int t = threadIdx.x;
    if (t < C) {
        float s;
        s = bnq[t] * rsqrtf(bnq[3 * C + t] + EPS);
        g_sq[t] = s; g_tq[t] = (bq[t] - bnq[2 * C + t]) * s + bnq[C + t];
        s = bnk[t] * rsqrtf(bnk[3 * C + t] + EPS);
        g_sk[t] = s; g_tk[t] = (bk[t] - bnk[2 * C + t]) * s + bnk[C + t];
        s = bnp[t] * rsqrtf(bnp[3 * C + t] + EPS);
        g_sp[t] = s; g_tp[t] = (bp1[t] - bnp[2 * C + t]) * s + bnp[C + t];
    }
    if (t < G) {
        float s = bnw[t] * rsqrtf(bnw[3 * G + t] + EPS);
        float bp2w = 0.f;
        for (int c = 0; c < C; c++) bp2w += bp2[c] * ww1[c * G + t];
        g_sw[t] = s;
        g_cw[t] = (bw1[t] + bp2w - bnw[2 * G + t]) * s + bnw[G + t];
    }
}

// pack W q/k/v into fp16 m16n8k16 B-frags. blockIdx.x = pass*16 + kb.
__global__ void prep_wfrag16(const float* __restrict__ Wq,
                             const float* __restrict__ Wk,
                             const float* __restrict__ Wv) {
    int pass = blockIdx.x >> 4, kb = blockIdx.x & 15;
    const float* W = (pass == 0) ? Wq : ((pass == 1) ? Wk : Wv);
    int i  = threadIdx.x;
    int nb = i >> 5, lane = i & 31;
    int gid = lane >> 2, tig = lane & 3;
    int n  = nb * 8 + gid;
    int k0 = kb * 16 + tig * 2;
    half2 b0 = __floats2half2_rn(W[k0 * C + n],       W[(k0 + 1) * C + n]);
    half2 b1 = __floats2half2_rn(W[(k0 + 8) * C + n], W[(k0 + 9) * C + n]);
    unsigned* dst = g_wfrag16 + pass * (16 * 32 * 64);
    dst[((kb * 32 + nb) * 32 + lane) * 2 + 0] = *(unsigned*)&b0;
    dst[((kb * 32 + nb) * 32 + lane) * 2 + 1] = *(unsigned*)&b1;
}

// merged: blocks 0-7 pack ww1 tf32 B-frags; blocks 8-11 pack A fp16 B-frags
__global__ void prep_small(const float* __restrict__ ww1, const float* __restrict__ wp2) {
    if (blockIdx.x < 8) {
        int idx  = blockIdx.x * 256 + threadIdx.x;   // 0..2047
        int lane = idx & 31, knb = idx >> 5;
        int kb = knb >> 1, nb = knb & 1;
        int gid = lane >> 2, tig = lane & 3;
        int n  = nb * 8 + gid;
        int k0 = kb * 8 + tig;
        g_w1frag[idx * 2 + 0] = f2tf(ww1[k0 * G + n]);
        g_w1frag[idx * 2 + 1] = f2tf(ww1[(k0 + 4) * G + n]);
    } else {
        int idx  = (blockIdx.x - 8) * 256 + threadIdx.x;   // 0..1023
        int lane = idx & 31, knb = idx >> 5;
        int kb = knb >> 1, nb = knb & 1;
        int gid = lane >> 2, tig = lane & 3;
        int g  = nb * 8 + gid;
        int k0 = kb * 16 + tig * 2;
        float d0 = 0.f, d1 = 0.f, d2 = 0.f, d3 = 0.f;
        #pragma unroll 4
        for (int c = 0; c < C; c++) {
            float w = ww1[c * G + g];
            d0 = fmaf(wp2[(k0)     * C + c], w, d0);
            d1 = fmaf(wp2[(k0 + 1) * C + c], w, d1);
            d2 = fmaf(wp2[(k0 + 8) * C + c], w, d2);
            d3 = fmaf(wp2[(k0 + 9) * C + c], w, d3);
        }
        half2 b0 = __floats2half2_rn(d0, d1);
        half2 b1 = __floats2half2_rn(d2, d3);
        g_afrag16[idx * 2 + 0] = *(unsigned*)&b0;
        g_afrag16[idx * 2 + 1] = *(unsigned*)&b1;
    }
}

__global__ void prep_wp2t16(const float* __restrict__ wp2) {
    int k = blockIdx.x, c = threadIdx.x;
    g_wp2t16[c * C + k] = __float2half(wp2[k * C + c]);
}

// ---------------- K1: q/k/v GEMM fp16 mma + tf32 projection ----------------
__global__ __launch_bounds__(256, 2) void k1_qkv(
    const float* __restrict__ feat, const float* __restrict__ bv) {
    extern __shared__ float sm[];
    unsigned short* feat16 = (unsigned short*)sm;                 // 32*FSH halves
    float* ybuf   = sm + (BM * FSH) / 2;                          // 32*YS floats
    unsigned* ww1f = (unsigned*)(sm + (BM * FSH) / 2 + BM * YS);  // 4096 unsigned

    int t    = threadIdx.x;
    int r0b  = blockIdx.x * BM;
    int warp = t >> 5, lane = t & 31;
    int gid  = lane >> 2, tig = lane & 3;
    int n0   = warp * 32;

    for (int i = t; i < BM * C / 4; i += 256) {
        int r = i >> 6, c4 = (i & 63) * 4;
        float4 f = *(const float4*)&feat[(r0b + r) * C + c4];
        half2 h0 = __floats2half2_rn(f.x, f.y);
        half2 h1 = __floats2half2_rn(f.z, f.w);
        uint2 pk; pk.x = *(unsigned*)&h0; pk.y = *(unsigned*)&h1;
        *(uint2*)&feat16[r * FSH + c4] = pk;
    }
    for (int i = t; i < 1024; i += 256)
        *(uint4*)&ww1f[i * 4] = *(const uint4*)&g_w1frag[i * 4];
    __syncthreads();

    #pragma unroll 1
    for (int pass = 0; pass < 3; pass++) {
        const ull* wf = (const ull*)(g_wfrag16 + pass * (16 * 32 * 64));
        float4 acc[2][4];
        #pragma unroll
        for (int mt = 0; mt < 2; mt++)
            #pragma unroll
            for (int nt = 0; nt < 4; nt++) acc[mt][nt] = make_float4(0.f, 0.f, 0.f, 0.f);

        #pragma unroll 4
        for (int kb = 0; kb < 16; kb++) {
            int kof = kb * 16 + tig * 2;
            unsigned a0 = *(const unsigned*)&feat16[(gid)      * FSH + kof];
            unsigned a1 = *(const unsigned*)&feat16[(gid + 8)  * FSH + kof];
            unsigned a2 = *(const unsigned*)&feat16[(gid)      * FSH + kof + 8];
            unsigned a3 = *(const unsigned*)&feat16[(gid + 8)  * FSH + kof + 8];
            unsigned a4 = *(const unsigned*)&feat16[(gid + 16) * FSH + kof];
            unsigned a5 = *(const unsigned*)&feat16[(gid + 24) * FSH + kof];
            unsigned a6 = *(const unsigned*)&feat16[(gid + 16) * FSH + kof + 8];
            unsigned a7 = *(const unsigned*)&feat16[(gid + 24) * FSH + kof + 8];
            #pragma unroll
            for (int nt = 0; nt < 4; nt++) {
                ull bb = wf[((kb * 32) + warp * 4 + nt) * 32 + lane];
                unsigned b0 = (unsigned)bb, b1 = (unsigned)(bb >> 32);
                MMA_F16(acc[0][nt], a0, a1, a2, a3, b0, b1);
                MMA_F16(acc[1][nt], a4, a5, a6, a7, b0, b1);
            }
        }

        if (pass == 2) {
            #pragma unroll
            for (int nt = 0; nt < 4; nt++) {
                int col = n0 + nt * 8 + tig * 2;
                float2 b2 = *(const float2*)&bv[col];
                #pragma unroll
                for (int mt = 0; mt < 2; mt++) {
                    int rA = r0b + mt * 16 + gid, rB = rA + 8;
                    *(half2*)&g_vall16[rA * C + col] =
                        __floats2half2_rn(acc[mt][nt].x + b2.x, acc[mt][nt].y + b2.y);
                    *(half2*)&g_vall16[rB * C + col] =
                        __floats2half2_rn(acc[mt][nt].z + b2.x, acc[mt][nt].w + b2.y);
                }
            }
        } else {
            const float* sA = (pass == 0) ? g_sq : g_sk;
            const float* tA = (pass == 0) ? g_tq : g_tk;
            #pragma unroll
            for (int nt = 0; nt < 4; nt++) {
                int col = n0 + nt * 8 + tig * 2;
                float2 s2 = *(const float2*)&sA[col];
                float2 t2 = *(const float2*)&tA[col];
                #pragma unroll
                for (int mt = 0; mt < 2; mt++) {
                    int rA = mt * 16 + gid, rB = rA + 8;
                    *(float2*)&ybuf[rA * YS + col] = make_float2(
                        fmaxf(fmaf(acc[mt][nt].x, s2.x, t2.x), 0.f),
                        fmaxf(fmaf(acc[mt][nt].y, s2.y, t2.y), 0.f));
                    *(float2*)&ybuf[rB * YS + col] = make_float2(
                        fmaxf(fmaf(acc[mt][nt].z, s2.x, t2.x), 0.f),
                        fmaxf(fmaf(acc[mt][nt].w, s2.y, t2.y), 0.f));
                }
            }
            __syncthreads();
            if (warp < 4) {
                int m0p = (warp & 1) * 16, nbp = warp >> 1;
                float4 pa = make_float4(0.f, 0.f, 0.f, 0.f);
                #pragma unroll 8
                for (int kb = 0; kb < 32; kb++) {
                    unsigned a0 = f2tf(ybuf[(m0p + gid)     * YS + kb * 8 + tig]);
                    unsigned a1 = f2tf(ybuf[(m0p + gid + 8) * YS + kb * 8 + tig]);
                    unsigned a2 = f2tf(ybuf[(m0p + gid)     * YS + kb * 8 + tig + 4]);
                    unsigned a3 = f2tf(ybuf[(m0p + gid + 8) * YS + kb * 8 + tig + 4]);
                    ull bb = *(const ull*)&ww1f[((kb * 2 + nbp) * 32 + lane) * 2];
                    MMA_TF32(pa, a0, a1, a2, a3, (unsigned)bb, (unsigned)(bb >> 32));
                }
                float* dst = (pass == 0) ? g_qW : g_kW;
                int col = nbp * 8 + tig * 2;
                dst[(r0b + m0p + gid)     * G + col]     = pa.x;
                dst[(r0b + m0p + gid)     * G + col + 1] = pa.y;
                dst[(r0b + m0p + gid + 8) * G + col]     = pa.z;
                dst[(r0b + m0p + gid + 8) * G + col + 1] = pa.w;
            }
            __syncthreads();
        }
    }
}

// ---------------- K2: fused per-point grouped attention, P=8 ---------------
struct K2S {
    unsigned short hid[P * 16 * HP];  // 67584 B; fp16; becomes hw in place
    float    lgb[P * 16 * LGS];       // 10240: raw logits -> logits2 -> weights
    float    vterm[P * 256];          // 8192
    float    kwq[P * 16 * 16];        // 8192: prefetched kW rows
    float    qwb[P * 16];             // 512
    float    pos[P * 16 * 4];         // 2048
    float    wsum[P * 16];            // 512
    float    mask[P * 16];            // 512
    int      idx[P * 16];             // 512
    float    ww2[G * G];              // 1024
    float    sw[G], cw[G], bw2s[G];
};

__global__ __launch_bounds__(256, 2) void k2_attn(
    const float* __restrict__ coord, const int* __restrict__ knn,
    const float* __restrict__ wp1,   const float* __restrict__ bp2,
    const float* __restrict__ ww2,   const float* __restrict__ bw2,
    float* __restrict__ out) {
    extern __shared__ char smraw[];
    K2S& S = *reinterpret_cast<K2S*>(smraw);
    int t  = threadIdx.x;
    int n0 = blockIdx.x * P;

    S.ww2[t] = ww2[t];
    if (t < G) { S.sw[t] = g_sw[t]; S.cw[t] = g_cw[t]; S.bw2s[t] = bw2[t]; }

    // phase 1 (t<128): gather idx / mask / pos + cp.async prefetch kW/qW
    if (t < 128) {
        int p = t >> 4, n = n0 + p;
        int id  = knn[n * KNN + (t & 15)];
        int ip1 = id + 1;
        float m = (float)((ip1 > 0) - (ip1 < 0));
        int sid = (id > 0) ? id : 0;
        S.idx[t]  = sid;
        S.mask[t] = m;
        #pragma unroll
        for (int d = 0; d < 3; d++)
            S.pos[t * 4 + d] = (coord[sid * 3 + d] - coord[n * 3 + d]) * m;
        unsigned d0 = smem_u32(&S.kwq[t * 16]);
        const float* s0 = &g_kW[sid * G];
        #pragma unroll
        for (int j = 0; j < 4; j++) CP_ASYNC16(d0 + j * 16, s0 + j * 4);
        if (t < P) {
            unsigned d1 = smem_u32(&S.qwb[t * 16]);
            const float* s1 = &g_qW[(n0 + t) * G];
            #pragma unroll
            for (int j = 0; j < 4; j++) CP_ASYNC16(d1 + j * 16, s1 + j * 4);
        }
        asm volatile("cp.async.commit_group;");
    }
    __syncthreads();

    // phase 2: hidden = relu(bn(pos @ Wp1 + bp1)) -> fp16; 128 rows
    {
        int half_ = t >> 7;
        int cp = (t & 127) * 2;
        float2 w0 = *(const float2*)&wp1[cp];
        float2 w1 = *(const float2*)&wp1[C + cp];
        float2 w2 = *(const float2*)&wp1[2 * C + cp];
        float2 sc = *(const float2*)&g_sp[cp];
        float2 sh = *(const float2*)&g_tp[cp];
        #pragma unroll 4
        for (int ps = half_ * 64; ps < half_ * 64 + 64; ps++) {
            float px = S.pos[ps * 4 + 0];
            float py = S.pos[ps * 4 + 1];
            float pz = S.pos[ps * 4 + 2];
            float h0 = fmaf(px, w0.x, fmaf(py, w1.x, pz * w2.x));
            float h1 = fmaf(px, w0.y, fmaf(py, w1.y, pz * w2.y));
            h0 = fmaxf(fmaf(h0, sc.x, sh.x), 0.f);
            h1 = fmaxf(fmaf(h1, sc.y, sh.y), 0.f);
            *(half2*)&S.hid[ps * HP + cp] = __floats2half2_rn(h0, h1);
        }
    }
    __syncthreads();

    // phase 3a: lg = hidden @ A via fp16 mma; warp w owns 16 rows, both n-halves
    {
        int w = t >> 5, lane = t & 31, gid = lane >> 2, tig = lane & 3;
        int m0 = w * 16;
        float4 acc0 = make_float4(0.f, 0.f, 0.f, 0.f);
        float4 acc1 = make_float4(0.f, 0.f, 0.f, 0.f);
        const ull* bf = (const ull*)g_afrag16;
        #pragma unroll
        for (int kb = 0; kb < 16; kb++) {
            int kof = kb * 16 + tig * 2;
            unsigned a0 = *(const unsigned*)&S.hid[(m0 + gid)     * HP + kof];
            unsigned a1 = *(const unsigned*)&S.hid[(m0 + gid + 8) * HP + kof];
            unsigned a2 = *(const unsigned*)&S.hid[(m0 + gid)     * HP + kof + 8];
            unsigned a3 = *(const unsigned*)&S.hid[(m0 + gid + 8) * HP + kof + 8];
            ull bb0 = bf[(kb * 2 + 0) * 32 + lane];
            ull bb1 = bf[(kb * 2 + 1) * 32 + lane];
            MMA_F16(acc0, a0, a1, a2, a3, (unsigned)bb0, (unsigned)(bb0 >> 32));
            MMA_F16(acc1, a0, a1, a2, a3, (unsigned)bb1, (unsigned)(bb1 >> 32));
        }
        S.lgb[(m0 + gid)     * LGS + tig * 2]      = acc0.x;
        S.lgb[(m0 + gid)     * LGS + tig * 2 + 1]  = acc0.y;
        S.lgb[(m0 + gid + 8) * LGS + tig * 2]      = acc0.z;
        S.lgb[(m0 + gid + 8) * LGS + tig * 2 + 1]  = acc0.w;
        S.lgb[(m0 + gid)     * LGS + 8 + tig * 2]     = acc1.x;
        S.lgb[(m0 + gid)     * LGS + 8 + tig * 2 + 1] = acc1.y;
        S.lgb[(m0 + gid + 8) * LGS + 8 + tig * 2]     = acc1.z;
        S.lgb[(m0 + gid + 8) * LGS + 8 + tig * 2 + 1] = acc1.w;
    }
    __syncthreads();

    // phase 3b (t<128): + lb, relu/sw/cw, @Ww2 (in place) ; then 4a softmax
    if (t < 128) {
        asm volatile("cp.async.wait_group 0;" ::: "memory");
        int r = t, p = r >> 4;
        float m = S.mask[r];
        const float4* kw = (const float4*)&S.kwq[r * 16];
        const float4* qw = (const float4*)&S.qwb[p * 16];
        float u[16];
        #pragma unroll
        for (int q = 0; q < 4; q++) {
            float4 sv = *(const float4*)&S.lgb[r * LGS + q * 4];
            float4 kv = kw[q], qv = qw[q];
            float4 lb;
            lb.x = fmaf(m, kv.x, -qv.x); lb.y = fmaf(m, kv.y, -qv.y);
            lb.z = fmaf(m, kv.z, -qv.z); lb.w = fmaf(m, kv.w, -qv.w);
            u[q*4+0] = fmaxf(fmaf(sv.x + lb.x, S.sw[q*4+0], S.cw[q*4+0]), 0.f);
            u[q*4+1] = fmaxf(fmaf(sv.y + lb.y, S.sw[q*4+1], S.cw[q*4+1]), 0.f);
            u[q*4+2] = fmaxf(fmaf(sv.z + lb.z, S.sw[q*4+2], S.cw[q*4+2]), 0.f);
            u[q*4+3] = fmaxf(fmaf(sv.w + lb.w, S.sw[q*4+3], S.cw[q*4+3]), 0.f);
        }
        #pragma unroll
        for (int g2 = 0; g2 < 16; g2++) {
            float acc = S.bw2s[g2];
            #pragma unroll
            for (int g = 0; g < 16; g++) acc = fmaf(u[g], S.ww2[g * 16 + g2], acc);
            S.lgb[r * LGS + g2] = acc;
        }
        __syncwarp();
        // 4a softmax: thread (pp,g); warp w covers rows 32w..32w+31 = points 2w,2w+1
        int pp = t >> 4, g = t & 15;
        float mx = -1e30f;
        #pragma unroll
        for (int s = 0; s < 16; s++) mx = fmaxf(mx, S.lgb[(pp * 16 + s) * LGS + g]);
        float e[16], sum = 0.f;
        #pragma unroll
        for (int s = 0; s < 16; s++) {
            e[s] = __expf(S.lgb[(pp * 16 + s) * LGS + g] - mx);
            sum += e[s];
        }
        float inv = 1.f / sum, ws = 0.f;
        #pragma unroll
        for (int s = 0; s < 16; s++) {
            float w = e[s] * inv * S.mask[pp * 16 + s];
            S.lgb[(pp * 16 + s) * LGS + g] = w;
            ws += w;
        }
        S.wsum[t] = ws;
    }
    __syncthreads();

    // phase 4A: v-gather: 512 (point, 4ch) slots, 2 per thread
    {
        #pragma unroll
        for (int j = 0; j < 2; j++) {
            int si = t + j * 256;
            int p  = si >> 6;
            int c0 = (si & 63) * 4;
            int g  = c0 >> 4;
            float a0 = 0.f, a1 = 0.f, a2 = 0.f, a3 = 0.f;
            #pragma unroll
            for (int s = 0; s < 16; s++) {
                float w = S.lgb[(p * 16 + s) * LGS + g];
                uint2 v = *(const uint2*)&g_vall16[S.idx[p * 16 + s] * C + c0];
                float2 v0 = __half22float2(*(half2*)&v.x);
                float2 v1 = __half22float2(*(half2*)&v.y);
                a0 = fmaf(w, v0.x, a0); a1 = fmaf(w, v0.y, a1);
                a2 = fmaf(w, v1.x, a2); a3 = fmaf(w, v1.y, a3);
            }
            *(float4*)&S.vterm[p * 256 + c0] = make_float4(a0, a1, a2, a3);
        }
    }
    // phase 4B: hw in place: 1024 (point, 2ch) slots, 4 per thread
    {
        #pragma unroll
        for (int j = 0; j < 4; j++) {
            int si = t + j * 256;
            int p = si >> 7, cq = (si & 127) * 2;
            float2 acc[16];
            #pragma unroll
            for (int g = 0; g < 16; g++) acc[g] = make_float2(0.f, 0.f);
            #pragma unroll
            for (int s = 0; s < 16; s++) {
                float2 h = __half22float2(*(const half2*)&S.hid[(p * 16 + s) * HP + cq]);
                const float4* wr = (const float4*)&S.lgb[(p * 16 + s) * LGS];
                #pragma unroll
                for (int q = 0; q < 4; q++) {
                    float4 w = wr[q];
                    acc[q*4+0].x = fmaf(w.x, h.x, acc[q*4+0].x); acc[q*4+0].y = fmaf(w.x, h.y, acc[q*4+0].y);
                    acc[q*4+1].x = fmaf(w.y, h.x, acc[q*4+1].x); acc[q*4+1].y = fmaf(w.y, h.y, acc[q*4+1].y);
                    acc[q*4+2].x = fmaf(w.z, h.x, acc[q*4+2].x); acc[q*4+2].y = fmaf(w.z, h.y, acc[q*4+2].y);
                    acc[q*4+3].x = fmaf(w.w, h.x, acc[q*4+3].x); acc[q*4+3].y = fmaf(w.w, h.y, acc[q*4+3].y);
                }
            }
            #pragma unroll
            for (int g = 0; g < 16; g++)
                *(half2*)&S.hid[(p * 16 + g) * HP + cq] = __floats2half2_rn(acc[g].x, acc[g].y);
        }
    }
    __syncthreads();

    // phase 5: out[p][c] = vterm + hw[p][g] . Wp2^T[c] + bp2[c]*wsum[p][g]
    {
        int c = t, g = c >> 4;
        float b = __ldg(&bp2[c]);
        float acc[P];
        #pragma unroll
        for (int p = 0; p < P; p++)
            acc[p] = S.vterm[p * 256 + c] + b * S.wsum[p * 16 + g];

        const uint4* wpt = (const uint4*)&g_wp2t16[c * C];
        #pragma unroll 2
        for (int kb = 0; kb < 32; kb++) {
            uint4 wpu = wpt[kb];
            float2 w0 = __half22float2(*(half2*)&wpu.x);
            float2 w1 = __half22float2(*(half2*)&wpu.y);
            float2 w2 = __half22float2(*(half2*)&wpu.z);
            float2 w3 = __half22float2(*(half2*)&wpu.w);
            #pragma unroll
            for (int p = 0; p < P; p++) {
                uint4 u = *(const uint4*)&S.hid[(p * 16 + g) * HP + kb * 8];
                float2 h0 = __half22float2(*(half2*)&u.x);
                float2 h1 = __half22float2(*(half2*)&u.y);
                float2 h2 = __half22float2(*(half2*)&u.z);
                float2 h3 = __half22float2(*(half2*)&u.w);
                acc[p] = fmaf(w0.x, h0.x, acc[p]); acc[p] = fmaf(w0.y, h0.y, acc[p]);
                acc[p] = fmaf(w1.x, h1.x, acc[p]); acc[p] = fmaf(w1.y, h1.y, acc[p]);
                acc[p] = fmaf(w2.x, h2.x, acc[p]); acc[p] = fmaf(w2.y, h2.y, acc[p]);
                acc[p] = fmaf(w3.x, h3.x, acc[p]); acc[p] = fmaf(w3.y, h3.y, acc[p]);
            }
        }
        #pragma unroll
        for (int p = 0; p < P; p++)
            out[(n0 + p) * C + c] = acc[p];
    }
}

// ---------------- launch ----------------------------------------------------
extern "C" void kernel_launch(void* const* d_in, const int* in_sizes, int n_in,
                              void* d_out, int out_size) {
    (void)in_sizes; (void)n_in; (void)out_size;
    const float* feat  = (const float*)d_in[0];
    const float* coord = (const float*)d_in[1];
    const int*   knn   = (const int*)  d_in[2];
    const float* Wq = (const float*)d_in[3];  const float* bq = (const float*)d_in[4];  const float* bnq = (const float*)d_in[5];
    const float* Wk = (const float*)d_in[6];  const float* bk = (const float*)d_in[7];  const float* bnk = (const float*)d_in[8];
    const float* Wv = (const float*)d_in[9];  const float* bv = (const float*)d_in[10];
    const float* Wp1 = (const float*)d_in[11]; const float* bp1 = (const float*)d_in[12]; const float* bnp = (const float*)d_in[13];
    const float* Wp2 = (const float*)d_in[14]; const float* bp2 = (const float*)d_in[15];
    const float* Ww1 = (const float*)d_in[16]; const float* bw1 = (const float*)d_in[17]; const float* bnw = (const float*)d_in[18];
    const float* Ww2 = (const float*)d_in[19]; const float* bw2 = (const float*)d_in[20];
    float* out = (float*)d_out;

    int k1_smem = (BM * FSH) * 2 + (BM * YS) * 4 + 4096 * 4;
    cudaFuncSetAttribute(k1_qkv,  cudaFuncAttributeMaxDynamicSharedMemorySize, k1_smem);
    cudaFuncSetAttribute(k2_attn, cudaFuncAttributeMaxDynamicSharedMemorySize, (int)sizeof(K2S));

    prep_fold<<<1, 256>>>(bq, bnq, bk, bnk, bp1, bnp, bw1, bnw, bp2, Ww1);
    prep_wp2t16<<<C, C>>>(Wp2);
    prep_small<<<12, 256>>>(Ww1, Wp2);
    prep_wfrag16<<<48, 1024>>>(Wq, Wk, Wv);
    k1_qkv<<<NPTS / BM, 256, k1_smem>>>(feat, bv);
    k2_attn<<<NPTS / P, 256, sizeof(K2S)>>>(coord, knn, Wp1, bp2, Ww2, bw2, out);
}

// round 12
// speedup vs baseline: 2.0402x; 1.2009x over previous
#include <cuda_runtime.h>
#include <cuda_fp16.h>
#include <math.h>

#define NPTS 20000
#define KNN  16
#define C    256
#define G    16
#define EPS  1e-5f
#define P    8          // points per block in K2
#define BM   32         // feat rows per block in K1
#define FSH  264        // k1 feat_s stride (halves)
#define YS   260        // k1 ybuf stride (words)
#define HP   264        // k2 hid row stride in halves
#define LGS  20         // k2 logit/weight buffer row stride (floats)

typedef unsigned long long ull;

// ---------------- scratch (static device memory) ---------------------------
__device__ __half   g_vall16[NPTS * C];          // v_all, fp16
__device__ float    g_qW[NPTS * G];
__device__ float    g_kW[NPTS * G];
__device__ unsigned g_wfrag16[3 * 16 * 32 * 64]; // W q/k/v fp16 B-frags (k1)
__device__ unsigned g_w1frag[4096];              // ww1 tf32 B-frags (k1 projection)
__device__ unsigned g_afrag16[2048];             // (Wp2@Ww1) fp16 B-frags (k2 ph3a)
__device__ unsigned g_p5a[16 * 16 * 32 * 4];     // Wp2^T fp16 A-frags (k2 ph5), 128KB
__device__ float    g_sq[C], g_tq[C];
__device__ float    g_sk[C], g_tk[C];
__device__ float    g_sp[C], g_tp[C];
__device__ float    g_sw[G], g_cw[G];

// ---------------- helpers ---------------------------------------------------
__device__ __forceinline__ unsigned f2tf(float x) {
    unsigned r;
    asm("cvt.rna.tf32.f32 %0, %1;" : "=r"(r) : "f"(x));
    return r;
}
__device__ __forceinline__ unsigned smem_u32(const void* p) {
    unsigned r;
    asm("{ .reg .u64 t; cvta.to.shared.u64 t, %1; cvt.u32.u64 %0, t; }"
        : "=r"(r) : "l"(p));
    return r;
}
#define CP_ASYNC16(dst, src) \
    asm volatile("cp.async.ca.shared.global [%0], [%1], 16;" :: "r"(dst), "l"(src))
#define MMA_TF32(acc, a0, a1, a2, a3, b0, b1)                                   \
    asm("mma.sync.aligned.m16n8k8.row.col.f32.tf32.tf32.f32 "                   \
        "{%0,%1,%2,%3},{%4,%5,%6,%7},{%8,%9},{%0,%1,%2,%3};"                    \
        : "+f"(acc.x), "+f"(acc.y), "+f"(acc.z), "+f"(acc.w)                    \
        : "r"(a0), "r"(a1), "r"(a2), "r"(a3), "r"(b0), "r"(b1))
#define MMA_F16(acc, a0, a1, a2, a3, b0, b1)                                    \
    asm("mma.sync.aligned.m16n8k16.row.col.f32.f16.f16.f32 "                    \
        "{%0,%1,%2,%3},{%4,%5,%6,%7},{%8,%9},{%0,%1,%2,%3};"                    \
        : "+f"(acc.x), "+f"(acc.y), "+f"(acc.z), "+f"(acc.w)                    \
        : "r"(a0), "r"(a1), "r"(a2), "r"(a3), "r"(b0), "r"(b1))

// ---------------- prep kernels ---------------------------------------------
__global__ void prep_fold(const float* __restrict__ bq, const float* __restrict__ bnq,
                          const float* __restrict__ bk, const float* __restrict__ bnk,
                          const float* __restrict__ bp1, const float* __restrict__ bnp,
                          const float* __restrict__ bw1, const float* __restrict__ bnw,
                          const float* __restrict__ bp2, const float* __restrict__ ww1) {
    int t = threadIdx.x;
    if (t < C) {
        float s;
        s = bnq[t] * rsqrtf(bnq[3 * C + t] + EPS);
        g_sq[t] = s; g_tq[t] = (bq[t] - bnq[2 * C + t]) * s + bnq[C + t];
        s = bnk[t] * rsqrtf(bnk[3 * C + t] + EPS);
        g_sk[t] = s; g_tk[t] = (bk[t] - bnk[2 * C + t]) * s + bnk[C + t];
        s = bnp[t] * rsqrtf(bnp[3 * C + t] + EPS);
        g_sp[t] = s; g_tp[t] = (bp1[t] - bnp[2 * C + t]) * s + bnp[C + t];
    }
    if (t < G) {
        float s = bnw[t] * rsqrtf(bnw[3 * G + t] + EPS);
        float bp2w = 0.f;
        for (int c = 0; c < C; c++) bp2w += bp2[c] * ww1[c * G + t];
        g_sw[t] = s;
        g_cw[t] = (bw1[t] + bp2w - bnw[2 * G + t]) * s + bnw[G + t];
    }
}

// pack W q/k/v into fp16 m16n8k16 B-frags. blockIdx.x = pass*16 + kb.
__global__ void prep_wfrag16(const float* __restrict__ Wq,
                             const float* __restrict__ Wk,
                             const float* __restrict__ Wv) {
    int pass = blockIdx.x >> 4, kb = blockIdx.x & 15;
    const float* W = (pass == 0) ? Wq : ((pass == 1) ? Wk : Wv);
    int i  = threadIdx.x;
    int nb = i >> 5, lane = i & 31;
    int gid = lane >> 2, tig = lane & 3;
    int n  = nb * 8 + gid;
    int k0 = kb * 16 + tig * 2;
    half2 b0 = __floats2half2_rn(W[k0 * C + n],       W[(k0 + 1) * C + n]);
    half2 b1 = __floats2half2_rn(W[(k0 + 8) * C + n], W[(k0 + 9) * C + n]);
    unsigned* dst = g_wfrag16 + pass * (16 * 32 * 64);
    dst[((kb * 32 + nb) * 32 + lane) * 2 + 0] = *(unsigned*)&b0;
    dst[((kb * 32 + nb) * 32 + lane) * 2 + 1] = *(unsigned*)&b1;
}

// merged: blocks 0-7 pack ww1 tf32 B-frags; blocks 8-11 pack A fp16 B-frags
__global__ void prep_small(const float* __restrict__ ww1, const float* __restrict__ wp2) {
    if (blockIdx.x < 8) {
        int idx  = blockIdx.x * 256 + threadIdx.x;   // 0..2047
        int lane = idx & 31, knb = idx >> 5;
        int kb = knb >> 1, nb = knb & 1;
        int gid = lane >> 2, tig = lane & 3;
        int n  = nb * 8 + gid;
        int k0 = kb * 8 + tig;
        g_w1frag[idx * 2 + 0] = f2tf(ww1[k0 * G + n]);
        g_w1frag[idx * 2 + 1] = f2tf(ww1[(k0 + 4) * G + n]);
    } else {
        int idx  = (blockIdx.x - 8) * 256 + threadIdx.x;   // 0..1023
        int lane = idx & 31, knb = idx >> 5;
        int kb = knb >> 1, nb = knb & 1;
        int gid = lane >> 2, tig = lane & 3;
        int g  = nb * 8 + gid;
        int k0 = kb * 16 + tig * 2;
        float d0 = 0.f, d1 = 0.f, d2 = 0.f, d3 = 0.f;
        #pragma unroll 4
        for (int c = 0; c < C; c++) {
            float w = ww1[c * G + g];
            d0 = fmaf(wp2[(k0)     * C + c], w, d0);
            d1 = fmaf(wp2[(k0 + 1) * C + c], w, d1);
            d2 = fmaf(wp2[(k0 + 8) * C + c], w, d2);
            d3 = fmaf(wp2[(k0 + 9) * C + c], w, d3);
        }
        half2 b0 = __floats2half2_rn(d0, d1);
        half2 b1 = __floats2half2_rn(d2, d3);
        g_afrag16[idx * 2 + 0] = *(unsigned*)&b0;
        g_afrag16[idx * 2 + 1] = *(unsigned*)&b1;
    }
}

// pack Wp2^T into fp16 m16n8k16 A-frags for k2 phase 5.
// A[m][k] = Wp2[k_glob][c = g*16 + m]; frag (g, kb) per lane = uint4.
__global__ void prep_p5a(const float* __restrict__ wp2) {
    int g = blockIdx.x;            // 16
    int t = threadIdx.x;           // 512
    int kb = t >> 5, lane = t & 31;
    int gid = lane >> 2, tig = lane & 3;
    int c0 = g * 16 + gid;
    int k0 = kb * 16 + tig * 2;
    half2 ax = __floats2half2_rn(wp2[(k0)     * C + c0],     wp2[(k0 + 1) * C + c0]);
    half2 ay = __floats2half2_rn(wp2[(k0)     * C + c0 + 8], wp2[(k0 + 1) * C + c0 + 8]);
    half2 az = __floats2half2_rn(wp2[(k0 + 8) * C + c0],     wp2[(k0 + 9) * C + c0]);
    half2 aw = __floats2half2_rn(wp2[(k0 + 8) * C + c0 + 8], wp2[(k0 + 9) * C + c0 + 8]);
    uint4 v;
    v.x = *(unsigned*)&ax; v.y = *(unsigned*)&ay;
    v.z = *(unsigned*)&az; v.w = *(unsigned*)&aw;
    ((uint4*)g_p5a)[(g * 16 + kb) * 32 + lane] = v;
}

// ---------------- K1: q/k/v GEMM fp16 mma + tf32 projection ----------------
__global__ __launch_bounds__(256, 2) void k1_qkv(
    const float* __restrict__ feat, const float* __restrict__ bv) {
    extern __shared__ float sm[];
    unsigned short* feat16 = (unsigned short*)sm;                 // 32*FSH halves
    float* ybuf   = sm + (BM * FSH) / 2;                          // 32*YS floats
    unsigned* ww1f = (unsigned*)(sm + (BM * FSH) / 2 + BM * YS);  // 4096 unsigned

    int t    = threadIdx.x;
    int r0b  = blockIdx.x * BM;
    int warp = t >> 5, lane = t & 31;
    int gid  = lane >> 2, tig = lane & 3;
    int n0   = warp * 32;

    for (int i = t; i < BM * C / 4; i += 256) {
        int r = i >> 6, c4 = (i & 63) * 4;
        float4 f = *(const float4*)&feat[(r0b + r) * C + c4];
        half2 h0 = __floats2half2_rn(f.x, f.y);
        half2 h1 = __floats2half2_rn(f.z, f.w);
        uint2 pk; pk.x = *(unsigned*)&h0; pk.y = *(unsigned*)&h1;
        *(uint2*)&feat16[r * FSH + c4] = pk;
    }
    for (int i = t; i < 1024; i += 256)
        *(uint4*)&ww1f[i * 4] = *(const uint4*)&g_w1frag[i * 4];
    __syncthreads();

    #pragma unroll 1
    for (int pass = 0; pass < 3; pass++) {
        const ull* wf = (const ull*)(g_wfrag16 + pass * (16 * 32 * 64));
        float4 acc[2][4];
        #pragma unroll
        for (int mt = 0; mt < 2; mt++)
            #pragma unroll
            for (int nt = 0; nt < 4; nt++) acc[mt][nt] = make_float4(0.f, 0.f, 0.f, 0.f);

        #pragma unroll 4
        for (int kb = 0; kb < 16; kb++) {
            int kof = kb * 16 + tig * 2;
            unsigned a0 = *(const unsigned*)&feat16[(gid)      * FSH + kof];
            unsigned a1 = *(const unsigned*)&feat16[(gid + 8)  * FSH + kof];
            unsigned a2 = *(const unsigned*)&feat16[(gid)      * FSH + kof + 8];
            unsigned a3 = *(const unsigned*)&feat16[(gid + 8)  * FSH + kof + 8];
            unsigned a4 = *(const unsigned*)&feat16[(gid + 16) * FSH + kof];
            unsigned a5 = *(const unsigned*)&feat16[(gid + 24) * FSH + kof];
            unsigned a6 = *(const unsigned*)&feat16[(gid + 16) * FSH + kof + 8];
            unsigned a7 = *(const unsigned*)&feat16[(gid + 24) * FSH + kof + 8];
            #pragma unroll
            for (int nt = 0; nt < 4; nt++) {
                ull bb = wf[((kb * 32) + warp * 4 + nt) * 32 + lane];
                unsigned b0 = (unsigned)bb, b1 = (unsigned)(bb >> 32);
                MMA_F16(acc[0][nt], a0, a1, a2, a3, b0, b1);
                MMA_F16(acc[1][nt], a4, a5, a6, a7, b0, b1);
            }
        }

        if (pass == 2) {
            #pragma unroll
            for (int nt = 0; nt < 4; nt++) {
                int col = n0 + nt * 8 + tig * 2;
                float2 b2 = *(const float2*)&bv[col];
                #pragma unroll
                for (int mt = 0; mt < 2; mt++) {
                    int rA = r0b + mt * 16 + gid, rB = rA + 8;
                    *(half2*)&g_vall16[rA * C + col] =
                        __floats2half2_rn(acc[mt][nt].x + b2.x, acc[mt][nt].y + b2.y);
                    *(half2*)&g_vall16[rB * C + col] =
                        __floats2half2_rn(acc[mt][nt].z + b2.x, acc[mt][nt].w + b2.y);
                }
            }
        } else {
            const float* sA = (pass == 0) ? g_sq : g_sk;
            const float* tA = (pass == 0) ? g_tq : g_tk;
            #pragma unroll
            for (int nt = 0; nt < 4; nt++) {
                int col = n0 + nt * 8 + tig * 2;
                float2 s2 = *(const float2*)&sA[col];
                float2 t2 = *(const float2*)&tA[col];
                #pragma unroll
                for (int mt = 0; mt < 2; mt++) {
                    int rA = mt * 16 + gid, rB = rA + 8;
                    *(float2*)&ybuf[rA * YS + col] = make_float2(
                        fmaxf(fmaf(acc[mt][nt].x, s2.x, t2.x), 0.f),
                        fmaxf(fmaf(acc[mt][nt].y, s2.y, t2.y), 0.f));
                    *(float2*)&ybuf[rB * YS + col] = make_float2(
                        fmaxf(fmaf(acc[mt][nt].z, s2.x, t2.x), 0.f),
                        fmaxf(fmaf(acc[mt][nt].w, s2.y, t2.y), 0.f));
                }
            }
            __syncthreads();
            if (warp < 4) {
                int m0p = (warp & 1) * 16, nbp = warp >> 1;
                float4 pa = make_float4(0.f, 0.f, 0.f, 0.f);
                #pragma unroll 8
                for (int kb = 0; kb < 32; kb++) {
                    unsigned a0 = f2tf(ybuf[(m0p + gid)     * YS + kb * 8 + tig]);
                    unsigned a1 = f2tf(ybuf[(m0p + gid + 8) * YS + kb * 8 + tig]);
                    unsigned a2 = f2tf(ybuf[(m0p + gid)     * YS + kb * 8 + tig + 4]);
                    unsigned a3 = f2tf(ybuf[(m0p + gid + 8) * YS + kb * 8 + tig + 4]);
                    ull bb = *(const ull*)&ww1f[((kb * 2 + nbp) * 32 + lane) * 2];
                    MMA_TF32(pa, a0, a1, a2, a3, (unsigned)bb, (unsigned)(bb >> 32));
                }
                float* dst = (pass == 0) ? g_qW : g_kW;
                int col = nbp * 8 + tig * 2;
                dst[(r0b + m0p + gid)     * G + col]     = pa.x;
                dst[(r0b + m0p + gid)     * G + col + 1] = pa.y;
                dst[(r0b + m0p + gid + 8) * G + col]     = pa.z;
                dst[(r0b + m0p + gid + 8) * G + col + 1] = pa.w;
            }
            __syncthreads();
        }
    }
}

// ---------------- K2: fused per-point grouped attention, P=8 ---------------
struct K2S {
    unsigned short hid[P * 16 * HP];  // 67584 B; fp16; becomes hw in place
    float    lgb[P * 16 * LGS];       // 10240: raw logits -> logits2 -> weights
    float    vterm[P * 256];          // 8192
    float    kwq[P * 16 * 16];        // 8192: prefetched kW rows
    float    qwb[P * 16];             // 512
    float    pos[P * 16 * 4];         // 2048
    float    wsum[P * 16];            // 512
    float    mask[P * 16];            // 512
    int      idx[P * 16];             // 512
    float    ww2[G * G];              // 1024
    float    bp2s[C];                 // 1024
    float    sw[G], cw[G], bw2s[G];
};

__global__ __launch_bounds__(256, 2) void k2_attn(
    const float* __restrict__ coord, const int* __restrict__ knn,
    const float* __restrict__ wp1,   const float* __restrict__ bp2,
    const float* __restrict__ ww2,   const float* __restrict__ bw2,
    float* __restrict__ out) {
    extern __shared__ char smraw[];
    K2S& S = *reinterpret_cast<K2S*>(smraw);
    int t  = threadIdx.x;
    int n0 = blockIdx.x * P;

    S.ww2[t]  = ww2[t];
    S.bp2s[t] = __ldg(&bp2[t]);
    if (t < G) { S.sw[t] = g_sw[t]; S.cw[t] = g_cw[t]; S.bw2s[t] = bw2[t]; }

    // phase 1 (t<128): gather idx / mask / pos + cp.async prefetch kW/qW
    if (t < 128) {
        int p = t >> 4, n = n0 + p;
        int id  = knn[n * KNN + (t & 15)];
        int ip1 = id + 1;
        float m = (float)((ip1 > 0) - (ip1 < 0));
        int sid = (id > 0) ? id : 0;
        S.idx[t]  = sid;
        S.mask[t] = m;
        #pragma unroll
        for (int d = 0; d < 3; d++)
            S.pos[t * 4 + d] = (coord[sid * 3 + d] - coord[n * 3 + d]) * m;
        unsigned d0 = smem_u32(&S.kwq[t * 16]);
        const float* s0 = &g_kW[sid * G];
        #pragma unroll
        for (int j = 0; j < 4; j++) CP_ASYNC16(d0 + j * 16, s0 + j * 4);
        if (t < P) {
            unsigned d1 = smem_u32(&S.qwb[t * 16]);
            const float* s1 = &g_qW[(n0 + t) * G];
            #pragma unroll
            for (int j = 0; j < 4; j++) CP_ASYNC16(d1 + j * 16, s1 + j * 4);
        }
        asm volatile("cp.async.commit_group;");
    }
    __syncthreads();

    // phase 2: hidden = relu(bn(pos @ Wp1 + bp1)) -> fp16; 128 rows
    {
        int half_ = t >> 7;
        int cp = (t & 127) * 2;
        float2 w0 = *(const float2*)&wp1[cp];
        float2 w1 = *(const float2*)&wp1[C + cp];
        float2 w2 = *(const float2*)&wp1[2 * C + cp];
        float2 sc = *(const float2*)&g_sp[cp];
        float2 sh = *(const float2*)&g_tp[cp];
        #pragma unroll 4
        for (int ps = half_ * 64; ps < half_ * 64 + 64; ps++) {
            float px = S.pos[ps * 4 + 0];
            float py = S.pos[ps * 4 + 1];
            float pz = S.pos[ps * 4 + 2];
            float h0 = fmaf(px, w0.x, fmaf(py, w1.x, pz * w2.x));
            float h1 = fmaf(px, w0.y, fmaf(py, w1.y, pz * w2.y));
            h0 = fmaxf(fmaf(h0, sc.x, sh.x), 0.f);
            h1 = fmaxf(fmaf(h1, sc.y, sh.y), 0.f);
            *(half2*)&S.hid[ps * HP + cp] = __floats2half2_rn(h0, h1);
        }
    }
    __syncthreads();

    // phase 3a: lg = hidden @ A via fp16 mma; warp w owns 16 rows, both n-halves
    {
        int w = t >> 5, lane = t & 31, gid = lane >> 2, tig = lane & 3;
        int m0 = w * 16;
        float4 acc0 = make_float4(0.f, 0.f, 0.f, 0.f);
        float4 acc1 = make_float4(0.f, 0.f, 0.f, 0.f);
        const ull* bf = (const ull*)g_afrag16;
        #pragma unroll
        for (int kb = 0; kb < 16; kb++) {
            int kof = kb * 16 + tig * 2;
            unsigned a0 = *(const unsigned*)&S.hid[(m0 + gid)     * HP + kof];
            unsigned a1 = *(const unsigned*)&S.hid[(m0 + gid + 8) * HP + kof];
            unsigned a2 = *(const unsigned*)&S.hid[(m0 + gid)     * HP + kof + 8];
            unsigned a3 = *(const unsigned*)&S.hid[(m0 + gid + 8) * HP + kof + 8];
            ull bb0 = bf[(kb * 2 + 0) * 32 + lane];
            ull bb1 = bf[(kb * 2 + 1) * 32 + lane];
            MMA_F16(acc0, a0, a1, a2, a3, (unsigned)bb0, (unsigned)(bb0 >> 32));
            MMA_F16(acc1, a0, a1, a2, a3, (unsigned)bb1, (unsigned)(bb1 >> 32));
        }
        S.lgb[(m0 + gid)     * LGS + tig * 2]      = acc0.x;
        S.lgb[(m0 + gid)     * LGS + tig * 2 + 1]  = acc0.y;
        S.lgb[(m0 + gid + 8) * LGS + tig * 2]      = acc0.z;
        S.lgb[(m0 + gid + 8) * LGS + tig * 2 + 1]  = acc0.w;
        S.lgb[(m0 + gid)     * LGS + 8 + tig * 2]     = acc1.x;
        S.lgb[(m0 + gid)     * LGS + 8 + tig * 2 + 1] = acc1.y;
        S.lgb[(m0 + gid + 8) * LGS + 8 + tig * 2]     = acc1.z;
        S.lgb[(m0 + gid + 8) * LGS + 8 + tig * 2 + 1] = acc1.w;
    }
    __syncthreads();

    // phase 3b (t<128): + lb, relu/sw/cw, @Ww2 (in place) ; then 4a softmax
    if (t < 128) {
        asm volatile("cp.async.wait_group 0;" ::: "memory");
        int r = t, p = r >> 4;
        float m = S.mask[r];
        const float4* kw = (const float4*)&S.kwq[r * 16];
        const float4* qw = (const float4*)&S.qwb[p * 16];
        float u[16];
        #pragma unroll
        for (int q = 0; q < 4; q++) {
            float4 sv = *(const float4*)&S.lgb[r * LGS + q * 4];
            float4 kv = kw[q], qv = qw[q];
            float4 lb;
            lb.x = fmaf(m, kv.x, -qv.x); lb.y = fmaf(m, kv.y, -qv.y);
            lb.z = fmaf(m, kv.z, -qv.z); lb.w = fmaf(m, kv.w, -qv.w);
            u[q*4+0] = fmaxf(fmaf(sv.x + lb.x, S.sw[q*4+0], S.cw[q*4+0]), 0.f);
            u[q*4+1] = fmaxf(fmaf(sv.y + lb.y, S.sw[q*4+1], S.cw[q*4+1]), 0.f);
            u[q*4+2] = fmaxf(fmaf(sv.z + lb.z, S.sw[q*4+2], S.cw[q*4+2]), 0.f);
            u[q*4+3] = fmaxf(fmaf(sv.w + lb.w, S.sw[q*4+3], S.cw[q*4+3]), 0.f);
        }
        #pragma unroll
        for (int g2 = 0; g2 < 16; g2++) {
            float acc = S.bw2s[g2];
            #pragma unroll
            for (int g = 0; g < 16; g++) acc = fmaf(u[g], S.ww2[g * 16 + g2], acc);
            S.lgb[r * LGS + g2] = acc;
        }
        __syncwarp();
        // 4a softmax: thread (pp,g); warp w covers rows 32w..32w+31 = points 2w,2w+1
        int pp = t >> 4, g = t & 15;
        float mx = -1e30f;
        #pragma unroll
        for (int s = 0; s < 16; s++) mx = fmaxf(mx, S.lgb[(pp * 16 + s) * LGS + g]);
        float e[16], sum = 0.f;
        #pragma unroll
        for (int s = 0; s < 16; s++) {
            e[s] = __expf(S.lgb[(pp * 16 + s) * LGS + g] - mx);
            sum += e[s];
        }
        float inv = 1.f / sum, ws = 0.f;
        #pragma unroll
        for (int s = 0; s < 16; s++) {
            float w = e[s] * inv * S.mask[pp * 16 + s];
            S.lgb[(pp * 16 + s) * LGS + g] = w;
            ws += w;
        }
        S.wsum[t] = ws;
    }
    __syncthreads();

    // phase 4A: v-gather: 512 (point, 4ch) slots, 2 per thread
    {
        #pragma unroll
        for (int j = 0; j < 2; j++) {
            int si = t + j * 256;
            int p  = si >> 6;
            int c0 = (si & 63) * 4;
            int g  = c0 >> 4;
            float a0 = 0.f, a1 = 0.f, a2 = 0.f, a3 = 0.f;
            #pragma unroll
            for (int s = 0; s < 16; s++) {
                float w = S.lgb[(p * 16 + s) * LGS + g];
                uint2 v = *(const uint2*)&g_vall16[S.idx[p * 16 + s] * C + c0];
                float2 v0 = __half22float2(*(half2*)&v.x);
                float2 v1 = __half22float2(*(half2*)&v.y);
                a0 = fmaf(w, v0.x, a0); a1 = fmaf(w, v0.y, a1);
                a2 = fmaf(w, v1.x, a2); a3 = fmaf(w, v1.y, a3);
            }
            *(float4*)&S.vterm[p * 256 + c0] = make_float4(a0, a1, a2, a3);
        }
    }
    // phase 4B: hw in place: 1024 (point, 2ch) slots, 4 per thread
    {
        #pragma unroll
        for (int j = 0; j < 4; j++) {
            int si = t + j * 256;
            int p = si >> 7, cq = (si & 127) * 2;
            float2 acc[16];
            #pragma unroll
            for (int g = 0; g < 16; g++) acc[g] = make_float2(0.f, 0.f);
            #pragma unroll
            for (int s = 0; s < 16; s++) {
                float2 h = __half22float2(*(const half2*)&S.hid[(p * 16 + s) * HP + cq]);
                const float4* wr = (const float4*)&S.lgb[(p * 16 + s) * LGS];
                #pragma unroll
                for (int q = 0; q < 4; q++) {
                    float4 w = wr[q];
                    acc[q*4+0].x = fmaf(w.x, h.x, acc[q*4+0].x); acc[q*4+0].y = fmaf(w.x, h.y, acc[q*4+0].y);
                    acc[q*4+1].x = fmaf(w.y, h.x, acc[q*4+1].x); acc[q*4+1].y = fmaf(w.y, h.y, acc[q*4+1].y);
                    acc[q*4+2].x = fmaf(w.z, h.x, acc[q*4+2].x); acc[q*4+2].y = fmaf(w.z, h.y, acc[q*4+2].y);
                    acc[q*4+3].x = fmaf(w.w, h.x, acc[q*4+3].x); acc[q*4+3].y = fmaf(w.w, h.y, acc[q*4+3].y);
                }
            }
            #pragma unroll
            for (int g = 0; g < 16; g++)
                *(half2*)&S.hid[(p * 16 + g) * HP + cq] = __floats2half2_rn(acc[g].x, acc[g].y);
        }
    }
    __syncthreads();

    // phase 5: per-group GEMM out[16c x 8p] = Wp2^T-block @ hw, fp16 mma.
    // warp w handles groups g = w and g = w+8; 16 k-chunks of 16.
    {
        int w = t >> 5, lane = t & 31, gid = lane >> 2, tig = lane & 3;
        const uint4* af = (const uint4*)g_p5a;
        #pragma unroll
        for (int gi = 0; gi < 2; gi++) {
            int g = w + gi * 8;
            float4 acc = make_float4(0.f, 0.f, 0.f, 0.f);
            #pragma unroll
            for (int kb = 0; kb < 16; kb++) {
                uint4 a = af[(g * 16 + kb) * 32 + lane];
                unsigned b0 = *(const unsigned*)&S.hid[(gid * 16 + g) * HP + kb * 16 + tig * 2];
                unsigned b1 = *(const unsigned*)&S.hid[(gid * 16 + g) * HP + kb * 16 + tig * 2 + 8];
                MMA_F16(acc, a.x, a.y, a.z, a.w, b0, b1);
            }
            int cg0 = g * 16 + gid, cg1 = cg0 + 8;
            int p0 = tig * 2, p1 = p0 + 1;
            float b0c = S.bp2s[cg0], b1c = S.bp2s[cg1];
            out[(n0 + p0) * C + cg0] = acc.x + S.vterm[p0 * 256 + cg0] + b0c * S.wsum[p0 * 16 + g];
            out[(n0 + p1) * C + cg0] = acc.y + S.vterm[p1 * 256 + cg0] + b0c * S.wsum[p1 * 16 + g];
            out[(n0 + p0) * C + cg1] = acc.z + S.vterm[p0 * 256 + cg1] + b1c * S.wsum[p0 * 16 + g];
            out[(n0 + p1) * C + cg1] = acc.w + S.vterm[p1 * 256 + cg1] + b1c * S.wsum[p1 * 16 + g];
        }
    }
}

// ---------------- launch ----------------------------------------------------
extern "C" void kernel_launch(void* const* d_in, const int* in_sizes, int n_in,
                              void* d_out, int out_size) {
    (void)in_sizes; (void)n_in; (void)out_size;
    const float* feat  = (const float*)d_in[0];
    const float* coord = (const float*)d_in[1];
    const int*   knn   = (const int*)  d_in[2];
    const float* Wq = (const float*)d_in[3];  const float* bq = (const float*)d_in[4];  const float* bnq = (const float*)d_in[5];
    const float* Wk = (const float*)d_in[6];  const float* bk = (const float*)d_in[7];  const float* bnk = (const float*)d_in[8];
    const float* Wv = (const float*)d_in[9];  const float* bv = (const float*)d_in[10];
    const float* Wp1 = (const float*)d_in[11]; const float* bp1 = (const float*)d_in[12]; const float* bnp = (const float*)d_in[13];
    const float* Wp2 = (const float*)d_in[14]; const float* bp2 = (const float*)d_in[15];
    const float* Ww1 = (const float*)d_in[16]; const float* bw1 = (const float*)d_in[17]; const float* bnw = (const float*)d_in[18];
    const float* Ww2 = (const float*)d_in[19]; const float* bw2 = (const float*)d_in[20];
    float* out = (float*)d_out;

    int k1_smem = (BM * FSH) * 2 + (BM * YS) * 4 + 4096 * 4;
    cudaFuncSetAttribute(k1_qkv,  cudaFuncAttributeMaxDynamicSharedMemorySize, k1_smem);
    cudaFuncSetAttribute(k2_attn, cudaFuncAttributeMaxDynamicSharedMemorySize, (int)sizeof(K2S));

    prep_fold<<<1, 256>>>(bq, bnq, bk, bnk, bp1, bnp, bw1, bnw, bp2, Ww1);
    prep_p5a<<<16, 512>>>(Wp2);
    prep_small<<<12, 256>>>(Ww1, Wp2);
    prep_wfrag16<<<48, 1024>>>(Wq, Wk, Wv);
    k1_qkv<<<NPTS / BM, 256, k1_smem>>>(feat, bv);
    k2_attn<<<NPTS / P, 256, sizeof(K2S)>>>(coord, knn, Wp1, bp2, Ww2, bw2, out);
}

// round 13
// speedup vs baseline: 2.4652x; 1.2083x over previous
#include <cuda_runtime.h>
#include <cuda_fp16.h>
#include <math.h>

#define NPTS 20000
#define KNN  16
#define C    256
#define G    16
#define EPS  1e-5f
#define P    8          // points per block in K2
#define BM   32         // feat rows per block in K1
#define FSH  264        // k1 feat_s stride (halves)
#define YS   260        // k1 ybuf stride (words)
#define HP   264        // k2 hid row stride in halves
#define LGS  20         // k2 logit/weight buffer row stride (floats)

typedef unsigned long long ull;

// ---------------- scratch (static device memory) ---------------------------
__device__ __half   g_vall16[NPTS * C];          // v_all, fp16
__device__ float    g_qW[NPTS * G];
__device__ float    g_kW[NPTS * G];
__device__ unsigned g_wfrag16[3 * 16 * 32 * 64]; // W q/k/v fp16 B-frags (k1)
__device__ unsigned g_w1frag[4096];              // ww1 tf32 B-frags (k1 projection)
__device__ unsigned g_afrag16[2048];             // (Wp2@Ww1) fp16 B-frags (k2 ph3a)
__device__ unsigned g_p5a[16 * 16 * 32 * 4];     // Wp2^T fp16 A-frags (k2 ph5), 128KB
__device__ float    g_sq[C], g_tq[C];
__device__ float    g_sk[C], g_tk[C];
__device__ float    g_sp[C], g_tp[C];
__device__ float    g_sw[G], g_cw[G];

// ---------------- helpers ---------------------------------------------------
__device__ __forceinline__ unsigned f2tf(float x) {
    unsigned r;
    asm("cvt.rna.tf32.f32 %0, %1;" : "=r"(r) : "f"(x));
    return r;
}
__device__ __forceinline__ unsigned smem_u32(const void* p) {
    unsigned r;
    asm("{ .reg .u64 t; cvta.to.shared.u64 t, %1; cvt.u32.u64 %0, t; }"
        : "=r"(r) : "l"(p));
    return r;
}
#define CP_ASYNC16(dst, src) \
    asm volatile("cp.async.ca.shared.global [%0], [%1], 16;" :: "r"(dst), "l"(src))
#define MMA_TF32(acc, a0, a1, a2, a3, b0, b1)                                   \
    asm("mma.sync.aligned.m16n8k8.row.col.f32.tf32.tf32.f32 "                   \
        "{%0,%1,%2,%3},{%4,%5,%6,%7},{%8,%9},{%0,%1,%2,%3};"                    \
        : "+f"(acc.x), "+f"(acc.y), "+f"(acc.z), "+f"(acc.w)                    \
        : "r"(a0), "r"(a1), "r"(a2), "r"(a3), "r"(b0), "r"(b1))
#define MMA_F16(acc, a0, a1, a2, a3, b0, b1)                                    \
    asm("mma.sync.aligned.m16n8k16.row.col.f32.f16.f16.f32 "                    \
        "{%0,%1,%2,%3},{%4,%5,%6,%7},{%8,%9},{%0,%1,%2,%3};"                    \
        : "+f"(acc.x), "+f"(acc.y), "+f"(acc.z), "+f"(acc.w)                    \
        : "r"(a0), "r"(a1), "r"(a2), "r"(a3), "r"(b0), "r"(b1))

// ---------------- prep kernels ---------------------------------------------
__global__ void prep_fold(const float* __restrict__ bq, const float* __restrict__ bnq,
                          const float* __restrict__ bk, const float* __restrict__ bnk,
                          const float* __restrict__ bp1, const float* __restrict__ bnp,
                          const float* __restrict__ bw1, const float* __restrict__ bnw,
                          const float* __restrict__ bp2, const float* __restrict__ ww1) {
    int t = threadIdx.x;
    if (t < C) {
        float s;
        s = bnq[t] * rsqrtf(bnq[3 * C + t] + EPS);
        g_sq[t] = s; g_tq[t] = (bq[t] - bnq[2 * C + t]) * s + bnq[C + t];
        s = bnk[t] * rsqrtf(bnk[3 * C + t] + EPS);
        g_sk[t] = s; g_tk[t] = (bk[t] - bnk[2 * C + t]) * s + bnk[C + t];
        s = bnp[t] * rsqrtf(bnp[3 * C + t] + EPS);
        g_sp[t] = s; g_tp[t] = (bp1[t] - bnp[2 * C + t]) * s + bnp[C + t];
    }
    if (t < G) {
        float s = bnw[t] * rsqrtf(bnw[3 * G + t] + EPS);
        float bp2w = 0.f;
        for (int c = 0; c < C; c++) bp2w += bp2[c] * ww1[c * G + t];
        g_sw[t] = s;
        g_cw[t] = (bw1[t] + bp2w - bnw[2 * G + t]) * s + bnw[G + t];
    }
}

__global__ void prep_wfrag16(const float* __restrict__ Wq,
                             const float* __restrict__ Wk,
                             const float* __restrict__ Wv) {
    int pass = blockIdx.x >> 4, kb = blockIdx.x & 15;
    const float* W = (pass == 0) ? Wq : ((pass == 1) ? Wk : Wv);
    int i  = threadIdx.x;
    int nb = i >> 5, lane = i & 31;
    int gid = lane >> 2, tig = lane & 3;
    int n  = nb * 8 + gid;
    int k0 = kb * 16 + tig * 2;
    half2 b0 = __floats2half2_rn(W[k0 * C + n],       W[(k0 + 1) * C + n]);
    half2 b1 = __floats2half2_rn(W[(k0 + 8) * C + n], W[(k0 + 9) * C + n]);
    unsigned* dst = g_wfrag16 + pass * (16 * 32 * 64);
    dst[((kb * 32 + nb) * 32 + lane) * 2 + 0] = *(unsigned*)&b0;
    dst[((kb * 32 + nb) * 32 + lane) * 2 + 1] = *(unsigned*)&b1;
}

__global__ void prep_small(const float* __restrict__ ww1, const float* __restrict__ wp2) {
    if (blockIdx.x < 8) {
        int idx  = blockIdx.x * 256 + threadIdx.x;
        int lane = idx & 31, knb = idx >> 5;
        int kb = knb >> 1, nb = knb & 1;
        int gid = lane >> 2, tig = lane & 3;
        int n  = nb * 8 + gid;
        int k0 = kb * 8 + tig;
        g_w1frag[idx * 2 + 0] = f2tf(ww1[k0 * G + n]);
        g_w1frag[idx * 2 + 1] = f2tf(ww1[(k0 + 4) * G + n]);
    } else {
        int idx  = (blockIdx.x - 8) * 256 + threadIdx.x;
        int lane = idx & 31, knb = idx >> 5;
        int kb = knb >> 1, nb = knb & 1;
        int gid = lane >> 2, tig = lane & 3;
        int g  = nb * 8 + gid;
        int k0 = kb * 16 + tig * 2;
        float d0 = 0.f, d1 = 0.f, d2 = 0.f, d3 = 0.f;
        #pragma unroll 4
        for (int c = 0; c < C; c++) {
            float w = ww1[c * G + g];
            d0 = fmaf(wp2[(k0)     * C + c], w, d0);
            d1 = fmaf(wp2[(k0 + 1) * C + c], w, d1);
            d2 = fmaf(wp2[(k0 + 8) * C + c], w, d2);
            d3 = fmaf(wp2[(k0 + 9) * C + c], w, d3);
        }
        half2 b0 = __floats2half2_rn(d0, d1);
        half2 b1 = __floats2half2_rn(d2, d3);
        g_afrag16[idx * 2 + 0] = *(unsigned*)&b0;
        g_afrag16[idx * 2 + 1] = *(unsigned*)&b1;
    }
}

__global__ void prep_p5a(const float* __restrict__ wp2) {
    int g = blockIdx.x;
    int t = threadIdx.x;
    int kb = t >> 5, lane = t & 31;
    int gid = lane >> 2, tig = lane & 3;
    int c0 = g * 16 + gid;
    int k0 = kb * 16 + tig * 2;
    half2 ax = __floats2half2_rn(wp2[(k0)     * C + c0],     wp2[(k0 + 1) * C + c0]);
    half2 ay = __floats2half2_rn(wp2[(k0)     * C + c0 + 8], wp2[(k0 + 1) * C + c0 + 8]);
    half2 az = __floats2half2_rn(wp2[(k0 + 8) * C + c0],     wp2[(k0 + 9) * C + c0]);
    half2 aw = __floats2half2_rn(wp2[(k0 + 8) * C + c0 + 8], wp2[(k0 + 9) * C + c0 + 8]);
    uint4 v;
    v.x = *(unsigned*)&ax; v.y = *(unsigned*)&ay;
    v.z = *(unsigned*)&az; v.w = *(unsigned*)&aw;
    ((uint4*)g_p5a)[(g * 16 + kb) * 32 + lane] = v;
}

// ---------------- K1: q/k/v GEMM fp16 mma + tf32 projection ----------------
__global__ __launch_bounds__(256, 2) void k1_qkv(
    const float* __restrict__ feat, const float* __restrict__ bv) {
    extern __shared__ float sm[];
    unsigned short* feat16 = (unsigned short*)sm;
    float* ybuf   = sm + (BM * FSH) / 2;
    unsigned* ww1f = (unsigned*)(sm + (BM * FSH) / 2 + BM * YS);

    int t    = threadIdx.x;
    int r0b  = blockIdx.x * BM;
    int warp = t >> 5, lane = t & 31;
    int gid  = lane >> 2, tig = lane & 3;
    int n0   = warp * 32;

    for (int i = t; i < BM * C / 4; i += 256) {
        int r = i >> 6, c4 = (i & 63) * 4;
        float4 f = *(const float4*)&feat[(r0b + r) * C + c4];
        half2 h0 = __floats2half2_rn(f.x, f.y);
        half2 h1 = __floats2half2_rn(f.z, f.w);
        uint2 pk; pk.x = *(unsigned*)&h0; pk.y = *(unsigned*)&h1;
        *(uint2*)&feat16[r * FSH + c4] = pk;
    }
    for (int i = t; i < 1024; i += 256)
        *(uint4*)&ww1f[i * 4] = *(const uint4*)&g_w1frag[i * 4];
    __syncthreads();

    #pragma unroll 1
    for (int pass = 0; pass < 3; pass++) {
        const ull* wf = (const ull*)(g_wfrag16 + pass * (16 * 32 * 64));
        float4 acc[2][4];
        #pragma unroll
        for (int mt = 0; mt < 2; mt++)
            #pragma unroll
            for (int nt = 0; nt < 4; nt++) acc[mt][nt] = make_float4(0.f, 0.f, 0.f, 0.f);

        #pragma unroll 4
        for (int kb = 0; kb < 16; kb++) {
            int kof = kb * 16 + tig * 2;
            unsigned a0 = *(const unsigned*)&feat16[(gid)      * FSH + kof];
            unsigned a1 = *(const unsigned*)&feat16[(gid + 8)  * FSH + kof];
            unsigned a2 = *(const unsigned*)&feat16[(gid)      * FSH + kof + 8];
            unsigned a3 = *(const unsigned*)&feat16[(gid + 8)  * FSH + kof + 8];
            unsigned a4 = *(const unsigned*)&feat16[(gid + 16) * FSH + kof];
            unsigned a5 = *(const unsigned*)&feat16[(gid + 24) * FSH + kof];
            unsigned a6 = *(const unsigned*)&feat16[(gid + 16) * FSH + kof + 8];
            unsigned a7 = *(const unsigned*)&feat16[(gid + 24) * FSH + kof + 8];
            #pragma unroll
            for (int nt = 0; nt < 4; nt++) {
                ull bb = wf[((kb * 32) + warp * 4 + nt) * 32 + lane];
                unsigned b0 = (unsigned)bb, b1 = (unsigned)(bb >> 32);
                MMA_F16(acc[0][nt], a0, a1, a2, a3, b0, b1);
                MMA_F16(acc[1][nt], a4, a5, a6, a7, b0, b1);
            }
        }

        if (pass == 2) {
            #pragma unroll
            for (int nt = 0; nt < 4; nt++) {
                int col = n0 + nt * 8 + tig * 2;
                float2 b2 = *(const float2*)&bv[col];
                #pragma unroll
                for (int mt = 0; mt < 2; mt++) {
                    int rA = r0b + mt * 16 + gid, rB = rA + 8;
                    *(half2*)&g_vall16[rA * C + col] =
                        __floats2half2_rn(acc[mt][nt].x + b2.x, acc[mt][nt].y + b2.y);
                    *(half2*)&g_vall16[rB * C + col] =
                        __floats2half2_rn(acc[mt][nt].z + b2.x, acc[mt][nt].w + b2.y);
                }
            }
        } else {
            const float* sA = (pass == 0) ? g_sq : g_sk;
            const float* tA = (pass == 0) ? g_tq : g_tk;
            #pragma unroll
            for (int nt = 0; nt < 4; nt++) {
                int col = n0 + nt * 8 + tig * 2;
                float2 s2 = *(const float2*)&sA[col];
                float2 t2 = *(const float2*)&tA[col];
                #pragma unroll
                for (int mt = 0; mt < 2; mt++) {
                    int rA = mt * 16 + gid, rB = rA + 8;
                    *(float2*)&ybuf[rA * YS + col] = make_float2(
                        fmaxf(fmaf(acc[mt][nt].x, s2.x, t2.x), 0.f),
                        fmaxf(fmaf(acc[mt][nt].y, s2.y, t2.y), 0.f));
                    *(float2*)&ybuf[rB * YS + col] = make_float2(
                        fmaxf(fmaf(acc[mt][nt].z, s2.x, t2.x), 0.f),
                        fmaxf(fmaf(acc[mt][nt].w, s2.y, t2.y), 0.f));
                }
            }
            __syncthreads();
            if (warp < 4) {
                int m0p = (warp & 1) * 16, nbp = warp >> 1;
                float4 pa = make_float4(0.f, 0.f, 0.f, 0.f);
                #pragma unroll 8
                for (int kb = 0; kb < 32; kb++) {
                    unsigned a0 = f2tf(ybuf[(m0p + gid)     * YS + kb * 8 + tig]);
                    unsigned a1 = f2tf(ybuf[(m0p + gid + 8) * YS + kb * 8 + tig]);
                    unsigned a2 = f2tf(ybuf[(m0p + gid)     * YS + kb * 8 + tig + 4]);
                    unsigned a3 = f2tf(ybuf[(m0p + gid + 8) * YS + kb * 8 + tig + 4]);
                    ull bb = *(const ull*)&ww1f[((kb * 2 + nbp) * 32 + lane) * 2];
                    MMA_TF32(pa, a0, a1, a2, a3, (unsigned)bb, (unsigned)(bb >> 32));
                }
                float* dst = (pass == 0) ? g_qW : g_kW;
                int col = nbp * 8 + tig * 2;
                dst[(r0b + m0p + gid)     * G + col]     = pa.x;
                dst[(r0b + m0p + gid)     * G + col + 1] = pa.y;
                dst[(r0b + m0p + gid + 8) * G + col]     = pa.z;
                dst[(r0b + m0p + gid + 8) * G + col + 1] = pa.w;
            }
            __syncthreads();
        }
    }
}

// ---------------- K2: fused per-point grouped attention, P=8 ---------------
struct K2S {
    unsigned short hid[P * 16 * HP];  // 67584 B; fp16; becomes hw in place
    float    lgb[P * 16 * LGS];       // 10240: raw logits -> logits2 -> weights
    float    vterm[P * 256];          // 8192
    float    kwq[P * 16 * 16];        // 8192
    unsigned short wT16[P * 16 * 16]; // 4096: transposed fp16 softmax weights
    float    qwb[P * 16];             // 512
    float    pos[P * 16 * 4];         // 2048
    float    wsum[P * 16];            // 512
    float    mask[P * 16];            // 512
    int      idx[P * 16];             // 512
    float    ww2[G * G];              // 1024
    float    bp2s[C];                 // 1024
    float    sw[G], cw[G], bw2s[G];
};

__global__ __launch_bounds__(256, 2) void k2_attn(
    const float* __restrict__ coord, const int* __restrict__ knn,
    const float* __restrict__ wp1,   const float* __restrict__ bp2,
    const float* __restrict__ ww2,   const float* __restrict__ bw2,
    float* __restrict__ out) {
    extern __shared__ char smraw[];
    K2S& S = *reinterpret_cast<K2S*>(smraw);
    int t  = threadIdx.x;
    int n0 = blockIdx.x * P;

    S.ww2[t]  = ww2[t];
    S.bp2s[t] = __ldg(&bp2[t]);
    if (t < G) { S.sw[t] = g_sw[t]; S.cw[t] = g_cw[t]; S.bw2s[t] = bw2[t]; }

    // phase 1 (t<128): gather idx / mask / pos + cp.async prefetch kW/qW
    if (t < 128) {
        int p = t >> 4, n = n0 + p;
        int id  = knn[n * KNN + (t & 15)];
        int ip1 = id + 1;
        float m = (float)((ip1 > 0) - (ip1 < 0));
        int sid = (id > 0) ? id : 0;
        S.idx[t]  = sid;
        S.mask[t] = m;
        #pragma unroll
        for (int d = 0; d < 3; d++)
            S.pos[t * 4 + d] = (coord[sid * 3 + d] - coord[n * 3 + d]) * m;
        unsigned d0 = smem_u32(&S.kwq[t * 16]);
        const float* s0 = &g_kW[sid * G];
        #pragma unroll
        for (int j = 0; j < 4; j++) CP_ASYNC16(d0 + j * 16, s0 + j * 4);
        if (t < P) {
            unsigned d1 = smem_u32(&S.qwb[t * 16]);
            const float* s1 = &g_qW[(n0 + t) * G];
            #pragma unroll
            for (int j = 0; j < 4; j++) CP_ASYNC16(d1 + j * 16, s1 + j * 4);
        }
        asm volatile("cp.async.commit_group;");
    }
    __syncthreads();

    // phase 2: hidden = relu(bn(pos @ Wp1 + bp1)) -> fp16; 128 rows
    {
        int half_ = t >> 7;
        int cp = (t & 127) * 2;
        float2 w0 = *(const float2*)&wp1[cp];
        float2 w1 = *(const float2*)&wp1[C + cp];
        float2 w2 = *(const float2*)&wp1[2 * C + cp];
        float2 sc = *(const float2*)&g_sp[cp];
        float2 sh = *(const float2*)&g_tp[cp];
        #pragma unroll 4
        for (int ps = half_ * 64; ps < half_ * 64 + 64; ps++) {
            float px = S.pos[ps * 4 + 0];
            float py = S.pos[ps * 4 + 1];
            float pz = S.pos[ps * 4 + 2];
            float h0 = fmaf(px, w0.x, fmaf(py, w1.x, pz * w2.x));
            float h1 = fmaf(px, w0.y, fmaf(py, w1.y, pz * w2.y));
            h0 = fmaxf(fmaf(h0, sc.x, sh.x), 0.f);
            h1 = fmaxf(fmaf(h1, sc.y, sh.y), 0.f);
            *(half2*)&S.hid[ps * HP + cp] = __floats2half2_rn(h0, h1);
        }
    }
    __syncthreads();

    // phase 3a: lg = hidden @ A via fp16 mma
    {
        int w = t >> 5, lane = t & 31, gid = lane >> 2, tig = lane & 3;
        int m0 = w * 16;
        float4 acc0 = make_float4(0.f, 0.f, 0.f, 0.f);
        float4 acc1 = make_float4(0.f, 0.f, 0.f, 0.f);
        const ull* bf = (const ull*)g_afrag16;
        #pragma unroll
        for (int kb = 0; kb < 16; kb++) {
            int kof = kb * 16 + tig * 2;
            unsigned a0 = *(const unsigned*)&S.hid[(m0 + gid)     * HP + kof];
            unsigned a1 = *(const unsigned*)&S.hid[(m0 + gid + 8) * HP + kof];
            unsigned a2 = *(const unsigned*)&S.hid[(m0 + gid)     * HP + kof + 8];
            unsigned a3 = *(const unsigned*)&S.hid[(m0 + gid + 8) * HP + kof + 8];
            ull bb0 = bf[(kb * 2 + 0) * 32 + lane];
            ull bb1 = bf[(kb * 2 + 1) * 32 + lane];
            MMA_F16(acc0, a0, a1, a2, a3, (unsigned)bb0, (unsigned)(bb0 >> 32));
            MMA_F16(acc1, a0, a1, a2, a3, (unsigned)bb1, (unsigned)(bb1 >> 32));
        }
        S.lgb[(m0 + gid)     * LGS + tig * 2]      = acc0.x;
        S.lgb[(m0 + gid)     * LGS + tig * 2 + 1]  = acc0.y;
        S.lgb[(m0 + gid + 8) * LGS + tig * 2]      = acc0.z;
        S.lgb[(m0 + gid + 8) * LGS + tig * 2 + 1]  = acc0.w;
        S.lgb[(m0 + gid)     * LGS + 8 + tig * 2]     = acc1.x;
        S.lgb[(m0 + gid)     * LGS + 8 + tig * 2 + 1] = acc1.y;
        S.lgb[(m0 + gid + 8) * LGS + 8 + tig * 2]     = acc1.z;
        S.lgb[(m0 + gid + 8) * LGS + 8 + tig * 2 + 1] = acc1.w;
    }
    __syncthreads();

    // phase 3b (t<128): + lb, relu/sw/cw, @Ww2 (in place); then 4a softmax
    if (t < 128) {
        asm volatile("cp.async.wait_group 0;" ::: "memory");
        int r = t, p = r >> 4;
        float m = S.mask[r];
        const float4* kw = (const float4*)&S.kwq[r * 16];
        const float4* qw = (const float4*)&S.qwb[p * 16];
        float u[16];
        #pragma unroll
        for (int q = 0; q < 4; q++) {
            float4 sv = *(const float4*)&S.lgb[r * LGS + q * 4];
            float4 kv = kw[q], qv = qw[q];
            float4 lb;
            lb.x = fmaf(m, kv.x, -qv.x); lb.y = fmaf(m, kv.y, -qv.y);
            lb.z = fmaf(m, kv.z, -qv.z); lb.w = fmaf(m, kv.w, -qv.w);
            u[q*4+0] = fmaxf(fmaf(sv.x + lb.x, S.sw[q*4+0], S.cw[q*4+0]), 0.f);
            u[q*4+1] = fmaxf(fmaf(sv.y + lb.y, S.sw[q*4+1], S.cw[q*4+1]), 0.f);
            u[q*4+2] = fmaxf(fmaf(sv.z + lb.z, S.sw[q*4+2], S.cw[q*4+2]), 0.f);
            u[q*4+3] = fmaxf(fmaf(sv.w + lb.w, S.sw[q*4+3], S.cw[q*4+3]), 0.f);
        }
        #pragma unroll
        for (int g2 = 0; g2 < 16; g2++) {
            float acc = S.bw2s[g2];
            #pragma unroll
            for (int g = 0; g < 16; g++) acc = fmaf(u[g], S.ww2[g * 16 + g2], acc);
            S.lgb[r * LGS + g2] = acc;
        }
        __syncwarp();
        // 4a softmax: thread (pp,g) owns all 16 s -> also emit transposed fp16 row
        int pp = t >> 4, g = t & 15;
        float mx = -1e30f;
        #pragma unroll
        for (int s = 0; s < 16; s++) mx = fmaxf(mx, S.lgb[(pp * 16 + s) * LGS + g]);
        float e[16], sum = 0.f;
        #pragma unroll
        for (int s = 0; s < 16; s++) {
            e[s] = __expf(S.lgb[(pp * 16 + s) * LGS + g] - mx);
            sum += e[s];
        }
        float inv = 1.f / sum, ws = 0.f;
        #pragma unroll
        for (int s = 0; s < 16; s++) {
            float w = e[s] * inv * S.mask[pp * 16 + s];
            e[s] = w;
            S.lgb[(pp * 16 + s) * LGS + g] = w;
            ws += w;
        }
        S.wsum[t] = ws;
        // transposed fp16 weights for phase 4B mma A-operand
        unsigned wu[8];
        #pragma unroll
        for (int sb = 0; sb < 8; sb++) {
            half2 h = __floats2half2_rn(e[sb * 2], e[sb * 2 + 1]);
            wu[sb] = *(unsigned*)&h;
        }
        uint4* wtrow = (uint4*)&S.wT16[(pp * 16 + g) * 16];
        wtrow[0] = make_uint4(wu[0], wu[1], wu[2], wu[3]);
        wtrow[1] = make_uint4(wu[4], wu[5], wu[6], wu[7]);
    }
    __syncthreads();

    // phase 4A: v-gather: 512 (point, 4ch) slots, 2 per thread
    {
        #pragma unroll
        for (int j = 0; j < 2; j++) {
            int si = t + j * 256;
            int p  = si >> 6;
            int c0 = (si & 63) * 4;
            int g  = c0 >> 4;
            float a0 = 0.f, a1 = 0.f, a2 = 0.f, a3 = 0.f;
            #pragma unroll
            for (int s = 0; s < 16; s++) {
                float w = S.lgb[(p * 16 + s) * LGS + g];
                uint2 v = *(const uint2*)&g_vall16[S.idx[p * 16 + s] * C + c0];
                float2 v0 = __half22float2(*(half2*)&v.x);
                float2 v1 = __half22float2(*(half2*)&v.y);
                a0 = fmaf(w, v0.x, a0); a1 = fmaf(w, v0.y, a1);
                a2 = fmaf(w, v1.x, a2); a3 = fmaf(w, v1.y, a3);
            }
            *(float4*)&S.vterm[p * 256 + c0] = make_float4(a0, a1, a2, a3);
        }
    }
    // phase 4B: hw = wT @ hid via fp16 mma, in place. warp = point.
    // Chunk nb reads+writes the same disjoint 8-column slab -> no hazard.
    {
        int w = t >> 5, lane = t & 31, gid = lane >> 2, tig = lane & 3;
        int p = w;
        const unsigned short* wa = &S.wT16[p * 256];
        unsigned a0 = *(const unsigned*)&wa[gid * 16 + tig * 2];
        unsigned a1 = *(const unsigned*)&wa[(gid + 8) * 16 + tig * 2];
        unsigned a2 = *(const unsigned*)&wa[gid * 16 + tig * 2 + 8];
        unsigned a3 = *(const unsigned*)&wa[(gid + 8) * 16 + tig * 2 + 8];
        const unsigned short* hb = &S.hid[p * 16 * HP];
        #pragma unroll 4
        for (int nb = 0; nb < 32; nb++) {
            int c = nb * 8 + gid;
            unsigned s0 = hb[(2 * tig)     * HP + c];
            unsigned s1 = hb[(2 * tig + 1) * HP + c];
            unsigned s2 = hb[(2 * tig + 8) * HP + c];
            unsigned s3 = hb[(2 * tig + 9) * HP + c];
            unsigned b0 = s0 | (s1 << 16);
            unsigned b1 = s2 | (s3 << 16);
            float4 acc = make_float4(0.f, 0.f, 0.f, 0.f);
            MMA_F16(acc, a0, a1, a2, a3, b0, b1);
            int co = nb * 8 + tig * 2;
            *(half2*)&S.hid[(p * 16 + gid)     * HP + co] = __floats2half2_rn(acc.x, acc.y);
            *(half2*)&S.hid[(p * 16 + gid + 8) * HP + co] = __floats2half2_rn(acc.z, acc.w);
        }
    }
    __syncthreads();

    // phase 5: per-group GEMM out[16c x 8p] = Wp2^T-block @ hw, fp16 mma.
    {
        int w = t >> 5, lane = t & 31, gid = lane >> 2, tig = lane & 3;
        const uint4* af = (const uint4*)g_p5a;
        #pragma unroll
        for (int gi = 0; gi < 2; gi++) {
            int g = w + gi * 8;
            float4 acc = make_float4(0.f, 0.f, 0.f, 0.f);
            #pragma unroll
            for (int kb = 0; kb < 16; kb++) {
                uint4 a = af[(g * 16 + kb) * 32 + lane];
                unsigned b0 = *(const unsigned*)&S.hid[(gid * 16 + g) * HP + kb * 16 + tig * 2];
                unsigned b1 = *(const unsigned*)&S.hid[(gid * 16 + g) * HP + kb * 16 + tig * 2 + 8];
                MMA_F16(acc, a.x, a.y, a.z, a.w, b0, b1);
            }
            int cg0 = g * 16 + gid, cg1 = cg0 + 8;
            int p0 = tig * 2, p1 = p0 + 1;
            float b0c = S.bp2s[cg0], b1c = S.bp2s[cg1];
            out[(n0 + p0) * C + cg0] = acc.x + S.vterm[p0 * 256 + cg0] + b0c * S.wsum[p0 * 16 + g];
            out[(n0 + p1) * C + cg0] = acc.y + S.vterm[p1 * 256 + cg0] + b0c * S.wsum[p1 * 16 + g];
            out[(n0 + p0) * C + cg1] = acc.z + S.vterm[p0 * 256 + cg1] + b1c * S.wsum[p0 * 16 + g];
            out[(n0 + p1) * C + cg1] = acc.w + S.vterm[p1 * 256 + cg1] + b1c * S.wsum[p1 * 16 + g];
        }
    }
}

// ---------------- launch ----------------------------------------------------
extern "C" void kernel_launch(void* const* d_in, const int* in_sizes, int n_in,
                              void* d_out, int out_size) {
    (void)in_sizes; (void)n_in; (void)out_size;
    const float* feat  = (const float*)d_in[0];
    const float* coord = (const float*)d_in[1];
    const int*   knn   = (const int*)  d_in[2];
    const float* Wq = (const float*)d_in[3];  const float* bq = (const float*)d_in[4];  const float* bnq = (const float*)d_in[5];
    const float* Wk = (const float*)d_in[6];  const float* bk = (const float*)d_in[7];  const float* bnk = (const float*)d_in[8];
    const float* Wv = (const float*)d_in[9];  const float* bv = (const float*)d_in[10];
    const float* Wp1 = (const float*)d_in[11]; const float* bp1 = (const float*)d_in[12]; const float* bnp = (const float*)d_in[13];
    const float* Wp2 = (const float*)d_in[14]; const float* bp2 = (const float*)d_in[15];
    const float* Ww1 = (const float*)d_in[16]; const float* bw1 = (const float*)d_in[17]; const float* bnw = (const float*)d_in[18];
    const float* Ww2 = (const float*)d_in[19]; const float* bw2 = (const float*)d_in[20];
    float* out = (float*)d_out;

    int k1_smem = (BM * FSH) * 2 + (BM * YS) * 4 + 4096 * 4;
    cudaFuncSetAttribute(k1_qkv,  cudaFuncAttributeMaxDynamicSharedMemorySize, k1_smem);
    cudaFuncSetAttribute(k2_attn, cudaFuncAttributeMaxDynamicSharedMemorySize, (int)sizeof(K2S));

    prep_fold<<<1, 256>>>(bq, bnq, bk, bnk, bp1, bnp, bw1, bnw, bp2, Ww1);
    prep_p5a<<<16, 512>>>(Wp2);
    prep_small<<<12, 256>>>(Ww1, Wp2);
    prep_wfrag16<<<48, 1024>>>(Wq, Wk, Wv);
    k1_qkv<<<NPTS / BM, 256, k1_smem>>>(feat, bv);
    k2_attn<<<NPTS / P, 256, sizeof(K2S)>>>(coord, knn, Wp1, bp2, Ww2, bw2, out);
}

// round 15
// speedup vs baseline: 2.5651x; 1.0405x over previous
#include <cuda_runtime.h>
#include <cuda_fp16.h>
#include <math.h>

#define NPTS 20000
#define KNN  16
#define C    256
#define G    16
#define EPS  1e-5f
#define P    8          // points per block in K2
#define BM   32         // feat rows per block in K1
#define FSH  264        // k1 feat_s stride (halves)
#define YSH  264        // k1 ybuf stride (halves)
#define HP   264        // k2 hid row stride in halves
#define LGS  20         // k2 logit/weight buffer row stride (floats)

typedef unsigned long long ull;

// ---------------- scratch (static device memory) ---------------------------
__device__ __half   g_vall16[NPTS * C];          // v_all, fp16
__device__ float    g_qW[NPTS * G];
__device__ float    g_kW[NPTS * G];
__device__ unsigned g_wfrag16[3 * 16 * 32 * 64]; // W q/k/v fp16 B-frags (k1)
__device__ unsigned g_w1frag16[2048];            // ww1 fp16 B-frags (k1 projection)
__device__ unsigned g_afrag16[2048];             // (Wp2@Ww1) fp16 B-frags (k2 ph3a)
__device__ unsigned g_p5a[16 * 16 * 32 * 4];     // Wp2^T fp16 A-frags (k2 ph5)
__device__ unsigned g_wp1h[5 * 128];             // half2-packed wp1 w0/w1/w2/sc/sh
__device__ float    g_sq[C], g_tq[C];
__device__ float    g_sk[C], g_tk[C];
__device__ float    g_sw[G], g_cw[G];

// ---------------- helpers ---------------------------------------------------
__device__ __forceinline__ unsigned smem_u32(const void* p) {
    unsigned r;
    asm("{ .reg .u64 t; cvta.to.shared.u64 t, %1; cvt.u32.u64 %0, t; }"
        : "=r"(r) : "l"(p));
    return r;
}
#define CP_ASYNC16(dst, src) \
    asm volatile("cp.async.ca.shared.global [%0], [%1], 16;" :: "r"(dst), "l"(src))
#define MMA_F16(acc, a0, a1, a2, a3, b0, b1)                                    \
    asm("mma.sync.aligned.m16n8k16.row.col.f32.f16.f16.f32 "                    \
        "{%0,%1,%2,%3},{%4,%5,%6,%7},{%8,%9},{%0,%1,%2,%3};"                    \
        : "+f"(acc.x), "+f"(acc.y), "+f"(acc.z), "+f"(acc.w)                    \
        : "r"(a0), "r"(a1), "r"(a2), "r"(a3), "r"(b0), "r"(b1))

// ---------------- prep kernels ---------------------------------------------
// pack W q/k/v into fp16 m16n8k16 B-frags. blockIdx.x = pass*16 + kb.
__global__ void prep_wfrag16(const float* __restrict__ Wq,
                             const float* __restrict__ Wk,
                             const float* __restrict__ Wv) {
    int pass = blockIdx.x >> 4, kb = blockIdx.x & 15;
    const float* W = (pass == 0) ? Wq : ((pass == 1) ? Wk : Wv);
    int i  = threadIdx.x;
    int nb = i >> 5, lane = i & 31;
    int gid = lane >> 2, tig = lane & 3;
    int n  = nb * 8 + gid;
    int k0 = kb * 16 + tig * 2;
    half2 b0 = __floats2half2_rn(W[k0 * C + n],       W[(k0 + 1) * C + n]);
    half2 b1 = __floats2half2_rn(W[(k0 + 8) * C + n], W[(k0 + 9) * C + n]);
    unsigned* dst = g_wfrag16 + pass * (16 * 32 * 64);
    dst[((kb * 32 + nb) * 32 + lane) * 2 + 0] = *(unsigned*)&b0;
    dst[((kb * 32 + nb) * 32 + lane) * 2 + 1] = *(unsigned*)&b1;
}

// merged small preps. 21 blocks x 512 threads.
__global__ void mega_prep(const float* __restrict__ bq, const float* __restrict__ bnq,
                          const float* __restrict__ bk, const float* __restrict__ bnk,
                          const float* __restrict__ bp1, const float* __restrict__ bnp,
                          const float* __restrict__ bw1, const float* __restrict__ bnw,
                          const float* __restrict__ bp2, const float* __restrict__ ww1,
                          const float* __restrict__ wp1, const float* __restrict__ wp2) {
    int b = blockIdx.x, t = threadIdx.x;
    if (b == 0) {
        if (t < C) {
            float s;
            s = bnq[t] * rsqrtf(bnq[3 * C + t] + EPS);
            g_sq[t] = s; g_tq[t] = (bq[t] - bnq[2 * C + t]) * s + bnq[C + t];
            s = bnk[t] * rsqrtf(bnk[3 * C + t] + EPS);
            g_sk[t] = s; g_tk[t] = (bk[t] - bnk[2 * C + t]) * s + bnk[C + t];
        }
        if (t < G) {
            float s = bnw[t] * rsqrtf(bnw[3 * G + t] + EPS);
            float bp2w = 0.f;
            for (int c = 0; c < C; c++) bp2w += bp2[c] * ww1[c * G + t];
            g_sw[t] = s;
            g_cw[t] = (bw1[t] + bp2w - bnw[2 * G + t]) * s + bnw[G + t];
        }
        if (t >= 256 && t < 384) {
            int cpi = t - 256;
            int c0 = 2 * cpi, c1 = c0 + 1;
            float sa = bnp[c0] * rsqrtf(bnp[3 * C + c0] + EPS);
            float ta = (bp1[c0] - bnp[2 * C + c0]) * sa + bnp[C + c0];
            float sb = bnp[c1] * rsqrtf(bnp[3 * C + c1] + EPS);
            float tb = (bp1[c1] - bnp[2 * C + c1]) * sb + bnp[C + c1];
            half2 h;
            h = __floats2half2_rn(wp1[c0],         wp1[c1]);         g_wp1h[cpi]       = *(unsigned*)&h;
            h = __floats2half2_rn(wp1[C + c0],     wp1[C + c1]);     g_wp1h[128 + cpi] = *(unsigned*)&h;
            h = __floats2half2_rn(wp1[2 * C + c0], wp1[2 * C + c1]); g_wp1h[256 + cpi] = *(unsigned*)&h;
            h = __floats2half2_rn(sa, sb);                           g_wp1h[384 + cpi] = *(unsigned*)&h;
            h = __floats2half2_rn(ta, tb);                           g_wp1h[512 + cpi] = *(unsigned*)&h;
        }
    } else if (b <= 2) {
        // ww1 fp16 B-frags: 1024 entries, each uint2
        int idx  = (b - 1) * 512 + t;
        int lane = idx & 31, knb = idx >> 5;
        int kb = knb >> 1, nb = knb & 1;
        int gid = lane >> 2, tig = lane & 3;
        int n  = nb * 8 + gid;
        int k0 = kb * 16 + tig * 2;
        half2 b0 = __floats2half2_rn(ww1[k0 * G + n],       ww1[(k0 + 1) * G + n]);
        half2 b1 = __floats2half2_rn(ww1[(k0 + 8) * G + n], ww1[(k0 + 9) * G + n]);
        g_w1frag16[idx * 2 + 0] = *(unsigned*)&b0;
        g_w1frag16[idx * 2 + 1] = *(unsigned*)&b1;
    } else if (b <= 4) {
        // (Wp2@Ww1) fp16 B-frags
        int idx  = (b - 3) * 512 + t;
        int lane = idx & 31, knb = idx >> 5;
        int kb = knb >> 1, nb = knb & 1;
        int gid = lane >> 2, tig = lane & 3;
        int g  = nb * 8 + gid;
        int k0 = kb * 16 + tig * 2;
        float d0 = 0.f, d1 = 0.f, d2 = 0.f, d3 = 0.f;
        #pragma unroll 4
        for (int c = 0; c < C; c++) {
            float w = ww1[c * G + g];
            d0 = fmaf(wp2[(k0)     * C + c], w, d0);
            d1 = fmaf(wp2[(k0 + 1) * C + c], w, d1);
            d2 = fmaf(wp2[(k0 + 8) * C + c], w, d2);
            d3 = fmaf(wp2[(k0 + 9) * C + c], w, d3);
        }
        half2 b0 = __floats2half2_rn(d0, d1);
        half2 b1 = __floats2half2_rn(d2, d3);
        g_afrag16[idx * 2 + 0] = *(unsigned*)&b0;
        g_afrag16[idx * 2 + 1] = *(unsigned*)&b1;
    } else {
        // Wp2^T fp16 A-frags for k2 phase 5; g = b-5
        int g = b - 5;
        int kb = t >> 5, lane = t & 31;
        int gid = lane >> 2, tig = lane & 3;
        int c0 = g * 16 + gid;
        int k0 = kb * 16 + tig * 2;
        half2 ax = __floats2half2_rn(wp2[(k0)     * C + c0],     wp2[(k0 + 1) * C + c0]);
        half2 ay = __floats2half2_rn(wp2[(k0)     * C + c0 + 8], wp2[(k0 + 1) * C + c0 + 8]);
        half2 az = __floats2half2_rn(wp2[(k0 + 8) * C + c0],     wp2[(k0 + 9) * C + c0]);
        half2 aw = __floats2half2_rn(wp2[(k0 + 8) * C + c0 + 8], wp2[(k0 + 9) * C + c0 + 8]);
        uint4 v;
        v.x = *(unsigned*)&ax; v.y = *(unsigned*)&ay;
        v.z = *(unsigned*)&az; v.w = *(unsigned*)&aw;
        ((uint4*)g_p5a)[(g * 16 + kb) * 32 + lane] = v;
    }
}

// ---------------- K1: q/k/v GEMM + projection, all fp16 mma ----------------
__global__ __launch_bounds__(256, 2) void k1_qkv(
    const float* __restrict__ feat, const float* __restrict__ bv) {
    extern __shared__ float sm[];
    unsigned short* feat16 = (unsigned short*)sm;                   // 32*FSH halves
    unsigned short* ybuf16 = (unsigned short*)sm + BM * FSH;        // 32*YSH halves

    int t    = threadIdx.x;
    int r0b  = blockIdx.x * BM;
    int warp = t >> 5, lane = t & 31;
    int gid  = lane >> 2, tig = lane & 3;
    int n0   = warp * 32;

    for (int i = t; i < BM * C / 4; i += 256) {
        int r = i >> 6, c4 = (i & 63) * 4;
        float4 f = *(const float4*)&feat[(r0b + r) * C + c4];
        half2 h0 = __floats2half2_rn(f.x, f.y);
        half2 h1 = __floats2half2_rn(f.z, f.w);
        uint2 pk; pk.x = *(unsigned*)&h0; pk.y = *(unsigned*)&h1;
        *(uint2*)&feat16[r * FSH + c4] = pk;
    }
    __syncthreads();

    #pragma unroll 1
    for (int pass = 0; pass < 3; pass++) {
        const ull* wf = (const ull*)(g_wfrag16 + pass * (16 * 32 * 64));
        float4 acc[2][4];
        #pragma unroll
        for (int mt = 0; mt < 2; mt++)
            #pragma unroll
            for (int nt = 0; nt < 4; nt++) acc[mt][nt] = make_float4(0.f, 0.f, 0.f, 0.f);

        #pragma unroll 4
        for (int kb = 0; kb < 16; kb++) {
            int kof = kb * 16 + tig * 2;
            unsigned a0 = *(const unsigned*)&feat16[(gid)      * FSH + kof];
            unsigned a1 = *(const unsigned*)&feat16[(gid + 8)  * FSH + kof];
            unsigned a2 = *(const unsigned*)&feat16[(gid)      * FSH + kof + 8];
            unsigned a3 = *(const unsigned*)&feat16[(gid + 8)  * FSH + kof + 8];
            unsigned a4 = *(const unsigned*)&feat16[(gid + 16) * FSH + kof];
            unsigned a5 = *(const unsigned*)&feat16[(gid + 24) * FSH + kof];
            unsigned a6 = *(const unsigned*)&feat16[(gid + 16) * FSH + kof + 8];
            unsigned a7 = *(const unsigned*)&feat16[(gid + 24) * FSH + kof + 8];
            #pragma unroll
            for (int nt = 0; nt < 4; nt++) {
                ull bb = wf[((kb * 32) + warp * 4 + nt) * 32 + lane];
                unsigned b0 = (unsigned)bb, b1 = (unsigned)(bb >> 32);
                MMA_F16(acc[0][nt], a0, a1, a2, a3, b0, b1);
                MMA_F16(acc[1][nt], a4, a5, a6, a7, b0, b1);
            }
        }

        if (pass == 2) {
            #pragma unroll
            for (int nt = 0; nt < 4; nt++) {
                int col = n0 + nt * 8 + tig * 2;
                float2 b2 = *(const float2*)&bv[col];
                #pragma unroll
                for (int mt = 0; mt < 2; mt++) {
                    int rA = r0b + mt * 16 + gid, rB = rA + 8;
                    *(half2*)&g_vall16[rA * C + col] =
                        __floats2half2_rn(acc[mt][nt].x + b2.x, acc[mt][nt].y + b2.y);
                    *(half2*)&g_vall16[rB * C + col] =
                        __floats2half2_rn(acc[mt][nt].z + b2.x, acc[mt][nt].w + b2.y);
                }
            }
        } else {
            const float* sA = (pass == 0) ? g_sq : g_sk;
            const float* tA = (pass == 0) ? g_tq : g_tk;
            #pragma unroll
            for (int nt = 0; nt < 4; nt++) {
                int col = n0 + nt * 8 + tig * 2;
                float2 s2 = *(const float2*)&sA[col];
                float2 t2 = *(const float2*)&tA[col];
                #pragma unroll
                for (int mt = 0; mt < 2; mt++) {
                    int rA = mt * 16 + gid, rB = rA + 8;
                    *(half2*)&ybuf16[rA * YSH + col] = __floats2half2_rn(
                        fmaxf(fmaf(acc[mt][nt].x, s2.x, t2.x), 0.f),
                        fmaxf(fmaf(acc[mt][nt].y, s2.y, t2.y), 0.f));
                    *(half2*)&ybuf16[rB * YSH + col] = __floats2half2_rn(
                        fmaxf(fmaf(acc[mt][nt].z, s2.x, t2.x), 0.f),
                        fmaxf(fmaf(acc[mt][nt].w, s2.y, t2.y), 0.f));
                }
            }
            __syncthreads();
            // projection y @ ww1 via fp16 mma: 4 warps (2 m-tiles x 2 n-halves)
            if (warp < 4) {
                int m0p = (warp & 1) * 16, nbp = warp >> 1;
                float4 pa = make_float4(0.f, 0.f, 0.f, 0.f);
                const ull* w1f = (const ull*)g_w1frag16;
                #pragma unroll 4
                for (int kb = 0; kb < 16; kb++) {
                    int kof = kb * 16 + tig * 2;
                    unsigned a0 = *(const unsigned*)&ybuf16[(m0p + gid)     * YSH + kof];
                    unsigned a1 = *(const unsigned*)&ybuf16[(m0p + gid + 8) * YSH + kof];
                    unsigned a2 = *(const unsigned*)&ybuf16[(m0p + gid)     * YSH + kof + 8];
                    unsigned a3 = *(const unsigned*)&ybuf16[(m0p + gid + 8) * YSH + kof + 8];
                    ull bb = w1f[(kb * 2 + nbp) * 32 + lane];
                    MMA_F16(pa, a0, a1, a2, a3, (unsigned)bb, (unsigned)(bb >> 32));
                }
                float* dst = (pass == 0) ? g_qW : g_kW;
                int col = nbp * 8 + tig * 2;
                dst[(r0b + m0p + gid)     * G + col]     = pa.x;
                dst[(r0b + m0p + gid)     * G + col + 1] = pa.y;
                dst[(r0b + m0p + gid + 8) * G + col]     = pa.z;
                dst[(r0b + m0p + gid + 8) * G + col + 1] = pa.w;
            }
            __syncthreads();
        }
    }
}

// ---------------- K2: fused per-point grouped attention, P=8 ---------------
struct K2S {
    unsigned short hid[P * 16 * HP];  // 67584 B; fp16; becomes hw in place
    float    lgb[P * 16 * LGS];       // raw logits -> logits2 -> weights
    float    vterm[P * 256];
    float    kwq[P * 16 * 16];
    unsigned short wT16[P * 16 * 16]; // transposed fp16 softmax weights
    float    qwb[P * 16];
    unsigned posh[P * 16 * 3];        // broadcast half2 pos
    float    wsum[P * 16];
    float    mask[P * 16];
    int      idx[P * 16];
    float    ww2[G * G];
    float    bp2s[C];
    float    sw[G], cw[G], bw2s[G];
};

__global__ __launch_bounds__(256, 2) void k2_attn(
    const float* __restrict__ coord, const int* __restrict__ knn,
    const float* __restrict__ bp2,   const float* __restrict__ ww2,
    const float* __restrict__ bw2,   float* __restrict__ out) {
    extern __shared__ char smraw[];
    K2S& S = *reinterpret_cast<K2S*>(smraw);
    int t  = threadIdx.x;
    int n0 = blockIdx.x * P;

    S.ww2[t]  = ww2[t];
    S.bp2s[t] = __ldg(&bp2[t]);
    if (t < G) { S.sw[t] = g_sw[t]; S.cw[t] = g_cw[t]; S.bw2s[t] = bw2[t]; }

    // phase 1 (t<128): gather idx / mask / pos(half2) + cp.async kW/qW
    if (t < 128) {
        int p = t >> 4, n = n0 + p;
        int id  = knn[n * KNN + (t & 15)];
        int ip1 = id + 1;
        float m = (float)((ip1 > 0) - (ip1 < 0));
        int sid = (id > 0) ? id : 0;
        S.idx[t]  = sid;
        S.mask[t] = m;
        #pragma unroll
        for (int d = 0; d < 3; d++) {
            float pd = (coord[sid * 3 + d] - coord[n * 3 + d]) * m;
            half2 h = __float2half2_rn(pd);
            S.posh[t * 3 + d] = *(unsigned*)&h;
        }
        unsigned d0 = smem_u32(&S.kwq[t * 16]);
        const float* s0 = &g_kW[sid * G];
        #pragma unroll
        for (int j = 0; j < 4; j++) CP_ASYNC16(d0 + j * 16, s0 + j * 4);
        if (t < P) {
            unsigned d1 = smem_u32(&S.qwb[t * 16]);
            const float* s1 = &g_qW[(n0 + t) * G];
            #pragma unroll
            for (int j = 0; j < 4; j++) CP_ASYNC16(d1 + j * 16, s1 + j * 4);
        }
        asm volatile("cp.async.commit_group;");
    }
    __syncthreads();

    // phase 2: hidden = relu(bn(pos @ Wp1 + bp1)) in half2; 128 rows
    {
        int half_ = t >> 7;
        int cpi = t & 127;
        half2 w0 = *(half2*)&g_wp1h[cpi];
        half2 w1 = *(half2*)&g_wp1h[128 + cpi];
        half2 w2 = *(half2*)&g_wp1h[256 + cpi];
        half2 sc = *(half2*)&g_wp1h[384 + cpi];
        half2 sh = *(half2*)&g_wp1h[512 + cpi];
        half2 z  = __float2half2_rn(0.f);
        #pragma unroll 4
        for (int ps = half_ * 64; ps < half_ * 64 + 64; ps++) {
            half2 px = *(half2*)&S.posh[ps * 3 + 0];
            half2 py = *(half2*)&S.posh[ps * 3 + 1];
            half2 pz = *(half2*)&S.posh[ps * 3 + 2];
            half2 h = __hfma2(px, w0, __hfma2(py, w1, __hmul2(pz, w2)));
            h = __hmax2(__hfma2(h, sc, sh), z);
            *(half2*)&S.hid[ps * HP + cpi * 2] = h;
        }
    }
    __syncthreads();

    // phase 3a: lg = hidden @ A via fp16 mma
    {
        int w = t >> 5, lane = t & 31, gid = lane >> 2, tig = lane & 3;
        int m0 = w * 16;
        float4 acc0 = make_float4(0.f, 0.f, 0.f, 0.f);
        float4 acc1 = make_float4(0.f, 0.f, 0.f, 0.f);
        const ull* bf = (const ull*)g_afrag16;
        #pragma unroll
        for (int kb = 0; kb < 16; kb++) {
            int kof = kb * 16 + tig * 2;
            unsigned a0 = *(const unsigned*)&S.hid[(m0 + gid)     * HP + kof];
            unsigned a1 = *(const unsigned*)&S.hid[(m0 + gid + 8) * HP + kof];
            unsigned a2 = *(const unsigned*)&S.hid[(m0 + gid)     * HP + kof + 8];
            unsigned a3 = *(const unsigned*)&S.hid[(m0 + gid + 8) * HP + kof + 8];
            ull bb0 = bf[(kb * 2 + 0) * 32 + lane];
            ull bb1 = bf[(kb * 2 + 1) * 32 + lane];
            MMA_F16(acc0, a0, a1, a2, a3, (unsigned)bb0, (unsigned)(bb0 >> 32));
            MMA_F16(acc1, a0, a1, a2, a3, (unsigned)bb1, (unsigned)(bb1 >> 32));
        }
        S.lgb[(m0 + gid)     * LGS + tig * 2]      = acc0.x;
        S.lgb[(m0 + gid)     * LGS + tig * 2 + 1]  = acc0.y;
        S.lgb[(m0 + gid + 8) * LGS + tig * 2]      = acc0.z;
        S.lgb[(m0 + gid + 8) * LGS + tig * 2 + 1]  = acc0.w;
        S.lgb[(m0 + gid)     * LGS + 8 + tig * 2]     = acc1.x;
        S.lgb[(m0 + gid)     * LGS + 8 + tig * 2 + 1] = acc1.y;
        S.lgb[(m0 + gid + 8) * LGS + 8 + tig * 2]     = acc1.z;
        S.lgb[(m0 + gid + 8) * LGS + 8 + tig * 2 + 1] = acc1.w;
    }
    __syncthreads();

    // phase 3b (t<128): + lb, relu/sw/cw, @Ww2 (in place); then 4a softmax
    if (t < 128) {
        asm volatile("cp.async.wait_group 0;" ::: "memory");
        int r = t, p = r >> 4;
        float m = S.mask[r];
        const float4* kw = (const float4*)&S.kwq[r * 16];
        const float4* qw = (const float4*)&S.qwb[p * 16];
        float u[16];
        #pragma unroll
        for (int q = 0; q < 4; q++) {
            float4 sv = *(const float4*)&S.lgb[r * LGS + q * 4];
            float4 kv = kw[q], qv = qw[q];
            float4 lb;
            lb.x = fmaf(m, kv.x, -qv.x); lb.y = fmaf(m, kv.y, -qv.y);
            lb.z = fmaf(m, kv.z, -qv.z); lb.w = fmaf(m, kv.w, -qv.w);
            u[q*4+0] = fmaxf(fmaf(sv.x + lb.x, S.sw[q*4+0], S.cw[q*4+0]), 0.f);
            u[q*4+1] = fmaxf(fmaf(sv.y + lb.y, S.sw[q*4+1], S.cw[q*4+1]), 0.f);
            u[q*4+2] = fmaxf(fmaf(sv.z + lb.z, S.sw[q*4+2], S.cw[q*4+2]), 0.f);
            u[q*4+3] = fmaxf(fmaf(sv.w + lb.w, S.sw[q*4+3], S.cw[q*4+3]), 0.f);
        }
        #pragma unroll
        for (int g2 = 0; g2 < 16; g2++) {
            float acc = S.bw2s[g2];
            #pragma unroll
            for (int g = 0; g < 16; g++) acc = fmaf(u[g], S.ww2[g * 16 + g2], acc);
            S.lgb[r * LGS + g2] = acc;
        }
        __syncwarp();
        // 4a softmax; warp w covers rows 32w..32w+31 = points 2w,2w+1
        int pp = t >> 4, g = t & 15;
        float mx = -1e30f;
        #pragma unroll
        for (int s = 0; s < 16; s++) mx = fmaxf(mx, S.lgb[(pp * 16 + s) * LGS + g]);
        float e[16], sum = 0.f;
        #pragma unroll
        for (int s = 0; s < 16; s++) {
            e[s] = __expf(S.lgb[(pp * 16 + s) * LGS + g] - mx);
            sum += e[s];
        }
        float inv = 1.f / sum, ws = 0.f;
        #pragma unroll
        for (int s = 0; s < 16; s++) {
            float w = e[s] * inv * S.mask[pp * 16 + s];
            e[s] = w;
            S.lgb[(pp * 16 + s) * LGS + g] = w;
            ws += w;
        }
        S.wsum[t] = ws;
        unsigned wu[8];
        #pragma unroll
        for (int sb = 0; sb < 8; sb++) {
            half2 h = __floats2half2_rn(e[sb * 2], e[sb * 2 + 1]);
            wu[sb] = *(unsigned*)&h;
        }
        uint4* wtrow = (uint4*)&S.wT16[(pp * 16 + g) * 16];
        wtrow[0] = make_uint4(wu[0], wu[1], wu[2], wu[3]);
        wtrow[1] = make_uint4(wu[4], wu[5], wu[6], wu[7]);
    }
    __syncthreads();

    // phase 4A: v-gather: 512 (point, 4ch) slots, 2 per thread
    {
        #pragma unroll
        for (int j = 0; j < 2; j++) {
            int si = t + j * 256;
            int p  = si >> 6;
            int c0 = (si & 63) * 4;
            int g  = c0 >> 4;
            float a0 = 0.f, a1 = 0.f, a2 = 0.f, a3 = 0.f;
            #pragma unroll
            for (int s = 0; s < 16; s++) {
                float w = S.lgb[(p * 16 + s) * LGS + g];
                uint2 v = *(const uint2*)&g_vall16[S.idx[p * 16 + s] * C + c0];
                float2 v0 = __half22float2(*(half2*)&v.x);
                float2 v1 = __half22float2(*(half2*)&v.y);
                a0 = fmaf(w, v0.x, a0); a1 = fmaf(w, v0.y, a1);
                a2 = fmaf(w, v1.x, a2); a3 = fmaf(w, v1.y, a3);
            }
            *(float4*)&S.vterm[p * 256 + c0] = make_float4(a0, a1, a2, a3);
        }
    }
    // phase 4B: hw = wT @ hid via fp16 mma, in place. warp = point.
    {
        int w = t >> 5, lane = t & 31, gid = lane >> 2, tig = lane & 3;
        int p = w;
        const unsigned short* wa = &S.wT16[p * 256];
        unsigned a0 = *(const unsigned*)&wa[gid * 16 + tig * 2];
        unsigned a1 = *(const unsigned*)&wa[(gid + 8) * 16 + tig * 2];
        unsigned a2 = *(const unsigned*)&wa[gid * 16 + tig * 2 + 8];
        unsigned a3 = *(const unsigned*)&wa[(gid + 8) * 16 + tig * 2 + 8];
        const unsigned short* hb = &S.hid[p * 16 * HP];
        #pragma unroll 4
        for (int nb = 0; nb < 32; nb++) {
            int c = nb * 8 + gid;
            unsigned s0 = hb[(2 * tig)     * HP + c];
            unsigned s1 = hb[(2 * tig + 1) * HP + c];
            unsigned s2 = hb[(2 * tig + 8) * HP + c];
            unsigned s3 = hb[(2 * tig + 9) * HP + c];
            unsigned b0 = s0 | (s1 << 16);
            unsigned b1 = s2 | (s3 << 16);
            float4 acc = make_float4(0.f, 0.f, 0.f, 0.f);
            MMA_F16(acc, a0, a1, a2, a3, b0, b1);
            int co = nb * 8 + tig * 2;
            *(half2*)&S.hid[(p * 16 + gid)     * HP + co] = __floats2half2_rn(acc.x, acc.y);
            *(half2*)&S.hid[(p * 16 + gid + 8) * HP + co] = __floats2half2_rn(acc.z, acc.w);
        }
    }
    __syncthreads();

    // phase 5: per-group GEMM out[16c x 8p] = Wp2^T-block @ hw, fp16 mma.
    {
        int w = t >> 5, lane = t & 31, gid = lane >> 2, tig = lane & 3;
        const uint4* af = (const uint4*)g_p5a;
        #pragma unroll
        for (int gi = 0; gi < 2; gi++) {
            int g = w + gi * 8;
            float4 acc = make_float4(0.f, 0.f, 0.f, 0.f);
            #pragma unroll
            for (int kb = 0; kb < 16; kb++) {
                uint4 a = af[(g * 16 + kb) * 32 + lane];
                unsigned b0 = *(const unsigned*)&S.hid[(gid * 16 + g) * HP + kb * 16 + tig * 2];
                unsigned b1 = *(const unsigned*)&S.hid[(gid * 16 + g) * HP + kb * 16 + tig * 2 + 8];
                MMA_F16(acc, a.x, a.y, a.z, a.w, b0, b1);
            }
            int cg0 = g * 16 + gid, cg1 = cg0 + 8;
            int p0 = tig * 2, p1 = p0 + 1;
            float b0c = S.bp2s[cg0], b1c = S.bp2s[cg1];
            out[(n0 + p0) * C + cg0] = acc.x + S.vterm[p0 * 256 + cg0] + b0c * S.wsum[p0 * 16 + g];
            out[(n0 + p1) * C + cg0] = acc.y + S.vterm[p1 * 256 + cg0] + b0c * S.wsum[p1 * 16 + g];
            out[(n0 + p0) * C + cg1] = acc.z + S.vterm[p0 * 256 + cg1] + b1c * S.wsum[p0 * 16 + g];
            out[(n0 + p1) * C + cg1] = acc.w + S.vterm[p1 * 256 + cg1] + b1c * S.wsum[p1 * 16 + g];
        }
    }
}

// ---------------- launch ----------------------------------------------------
extern "C" void kernel_launch(void* const* d_in, const int* in_sizes, int n_in,
                              void* d_out, int out_size) {
    (void)in_sizes; (void)n_in; (void)out_size;
    const float* feat  = (const float*)d_in[0];
    const float* coord = (const float*)d_in[1];
    const int*   knn   = (const int*)  d_in[2];
    const float* Wq = (const float*)d_in[3];  const float* bq = (const float*)d_in[4];  const float* bnq = (const float*)d_in[5];
    const float* Wk = (const float*)d_in[6];  const float* bk = (const float*)d_in[7];  const float* bnk = (const float*)d_in[8];
    const float* Wv = (const float*)d_in[9];  const float* bv = (const float*)d_in[10];
    const float* Wp1 = (const float*)d_in[11]; const float* bp1 = (const float*)d_in[12]; const float* bnp = (const float*)d_in[13];
    const float* Wp2 = (const float*)d_in[14]; const float* bp2 = (const float*)d_in[15];
    const float* Ww1 = (const float*)d_in[16]; const float* bw1 = (const float*)d_in[17]; const float* bnw = (const float*)d_in[18];
    const float* Ww2 = (const float*)d_in[19]; const float* bw2 = (const float*)d_in[20];
    float* out = (float*)d_out;

    int k1_smem = (BM * FSH + BM * YSH) * 2;
    cudaFuncSetAttribute(k1_qkv,  cudaFuncAttributeMaxDynamicSharedMemorySize, k1_smem);
    cudaFuncSetAttribute(k2_attn, cudaFuncAttributeMaxDynamicSharedMemorySize, (int)sizeof(K2S));

    mega_prep<<<21, 512>>>(bq, bnq, bk, bnk, bp1, bnp, bw1, bnw, bp2, Ww1, Wp1, Wp2);
    prep_wfrag16<<<48, 1024>>>(Wq, Wk, Wv);
    k1_qkv<<<NPTS / BM, 256, k1_smem>>>(feat, bv);
    k2_attn<<<NPTS / P, 256, sizeof(K2S)>>>(coord, knn, bp2, Ww2, bw2, out);
}

// round 16
// speedup vs baseline: 2.8914x; 1.1272x over previous
#include <cuda_runtime.h>
#include <cuda_fp16.h>
#include <math.h>

#define NPTS 20000
#define KNN  16
#define C    256
#define G    16
#define EPS  1e-5f
#define P    8          // points per block in K2
#define BM   32         // feat rows per block in K1
#define FSH  264        // k1 feat_s stride (halves)
#define YSH  264        // k1 ybuf stride (halves)
#define HP   264        // k2 hid row stride in halves
#define PSK  (16 * HP + 8)   // per-point skewed block stride (halves)
#define LGS  20         // k2 logit/weight buffer row stride (floats)

typedef unsigned long long ull;

// ---------------- scratch (static device memory) ---------------------------
__device__ __half   g_vall16[NPTS * C];          // v_all, fp16
__device__ float    g_qW[NPTS * G];
__device__ float    g_kW[NPTS * G];
__device__ unsigned g_wfrag16[3 * 16 * 32 * 64]; // W q/k/v fp16 B-frags (k1)
__device__ unsigned g_w1frag16[2048];            // ww1 fp16 B-frags (k1 projection)
__device__ unsigned g_afrag16[2048];             // (Wp2@Ww1) fp16 B-frags (k2 ph3a)
__device__ unsigned g_p5a[16 * 16 * 32 * 4];     // Wp2^T fp16 A-frags (k2 ph5)
__device__ unsigned g_wp1h[5 * 128];             // half2-packed wp1 w0/w1/w2/sc/sh
__device__ float    g_sq[C], g_tq[C];
__device__ float    g_sk[C], g_tk[C];
__device__ float    g_sw[G], g_cw[G];

// ---------------- helpers ---------------------------------------------------
__device__ __forceinline__ unsigned smem_u32(const void* p) {
    unsigned r;
    asm("{ .reg .u64 t; cvta.to.shared.u64 t, %1; cvt.u32.u64 %0, t; }"
        : "=r"(r) : "l"(p));
    return r;
}
#define CP_ASYNC16(dst, src) \
    asm volatile("cp.async.ca.shared.global [%0], [%1], 16;" :: "r"(dst), "l"(src))
#define MMA_F16(acc, a0, a1, a2, a3, b0, b1)                                    \
    asm("mma.sync.aligned.m16n8k16.row.col.f32.f16.f16.f32 "                    \
        "{%0,%1,%2,%3},{%4,%5,%6,%7},{%8,%9},{%0,%1,%2,%3};"                    \
        : "+f"(acc.x), "+f"(acc.y), "+f"(acc.z), "+f"(acc.w)                    \
        : "r"(a0), "r"(a1), "r"(a2), "r"(a3), "r"(b0), "r"(b1))

// ---------------- prep kernels ---------------------------------------------
// pack W q/k/v into fp16 m16n8k16 B-frags. blockIdx.x = pass*16 + kb.
__global__ void prep_wfrag16(const float* __restrict__ Wq,
                             const float* __restrict__ Wk,
                             const float* __restrict__ Wv) {
    int pass = blockIdx.x >> 4, kb = blockIdx.x & 15;
    const float* W = (pass == 0) ? Wq : ((pass == 1) ? Wk : Wv);
    int i  = threadIdx.x;
    int nb = i >> 5, lane = i & 31;
    int gid = lane >> 2, tig = lane & 3;
    int n  = nb * 8 + gid;
    int k0 = kb * 16 + tig * 2;
    half2 b0 = __floats2half2_rn(W[k0 * C + n],       W[(k0 + 1) * C + n]);
    half2 b1 = __floats2half2_rn(W[(k0 + 8) * C + n], W[(k0 + 9) * C + n]);
    unsigned* dst = g_wfrag16 + pass * (16 * 32 * 64);
    dst[((kb * 32 + nb) * 32 + lane) * 2 + 0] = *(unsigned*)&b0;
    dst[((kb * 32 + nb) * 32 + lane) * 2 + 1] = *(unsigned*)&b1;
}

// merged small preps. 21 blocks x 512 threads.
__global__ void mega_prep(const float* __restrict__ bq, const float* __restrict__ bnq,
                          const float* __restrict__ bk, const float* __restrict__ bnk,
                          const float* __restrict__ bp1, const float* __restrict__ bnp,
                          const float* __restrict__ bw1, const float* __restrict__ bnw,
                          const float* __restrict__ bp2, const float* __restrict__ ww1,
                          const float* __restrict__ wp1, const float* __restrict__ wp2) {
    int b = blockIdx.x, t = threadIdx.x;
    if (b == 0) {
        if (t < C) {
            float s;
            s = bnq[t] * rsqrtf(bnq[3 * C + t] + EPS);
            g_sq[t] = s; g_tq[t] = (bq[t] - bnq[2 * C + t]) * s + bnq[C + t];
            s = bnk[t] * rsqrtf(bnk[3 * C + t] + EPS);
            g_sk[t] = s; g_tk[t] = (bk[t] - bnk[2 * C + t]) * s + bnk[C + t];
        }
        if (t < G) {
            float s = bnw[t] * rsqrtf(bnw[3 * G + t] + EPS);
            float bp2w = 0.f;
            for (int c = 0; c < C; c++) bp2w += bp2[c] * ww1[c * G + t];
            g_sw[t] = s;
            g_cw[t] = (bw1[t] + bp2w - bnw[2 * G + t]) * s + bnw[G + t];
        }
        if (t >= 256 && t < 384) {
            int cpi = t - 256;
            int c0 = 2 * cpi, c1 = c0 + 1;
            float sa = bnp[c0] * rsqrtf(bnp[3 * C + c0] + EPS);
            float ta = (bp1[c0] - bnp[2 * C + c0]) * sa + bnp[C + c0];
            float sb = bnp[c1] * rsqrtf(bnp[3 * C + c1] + EPS);
            float tb = (bp1[c1] - bnp[2 * C + c1]) * sb + bnp[C + c1];
            half2 h;
            h = __floats2half2_rn(wp1[c0],         wp1[c1]);         g_wp1h[cpi]       = *(unsigned*)&h;
            h = __floats2half2_rn(wp1[C + c0],     wp1[C + c1]);     g_wp1h[128 + cpi] = *(unsigned*)&h;
            h = __floats2half2_rn(wp1[2 * C + c0], wp1[2 * C + c1]); g_wp1h[256 + cpi] = *(unsigned*)&h;
            h = __floats2half2_rn(sa, sb);                           g_wp1h[384 + cpi] = *(unsigned*)&h;
            h = __floats2half2_rn(ta, tb);                           g_wp1h[512 + cpi] = *(unsigned*)&h;
        }
    } else if (b <= 2) {
        // ww1 fp16 B-frags: 1024 entries, each uint2
        int idx  = (b - 1) * 512 + t;
        int lane = idx & 31, knb = idx >> 5;
        int kb = knb >> 1, nb = knb & 1;
        int gid = lane >> 2, tig = lane & 3;
        int n  = nb * 8 + gid;
        int k0 = kb * 16 + tig * 2;
        half2 b0 = __floats2half2_rn(ww1[k0 * G + n],       ww1[(k0 + 1) * G + n]);
        half2 b1 = __floats2half2_rn(ww1[(k0 + 8) * G + n], ww1[(k0 + 9) * G + n]);
        g_w1frag16[idx * 2 + 0] = *(unsigned*)&b0;
        g_w1frag16[idx * 2 + 1] = *(unsigned*)&b1;
    } else if (b <= 4) {
        // (Wp2@Ww1) fp16 B-frags
        int idx  = (b - 3) * 512 + t;
        int lane = idx & 31, knb = idx >> 5;
        int kb = knb >> 1, nb = knb & 1;
        int gid = lane >> 2, tig = lane & 3;
        int g  = nb * 8 + gid;
        int k0 = kb * 16 + tig * 2;
        float d0 = 0.f, d1 = 0.f, d2 = 0.f, d3 = 0.f;
        #pragma unroll 4
        for (int c = 0; c < C; c++) {
            float w = ww1[c * G + g];
            d0 = fmaf(wp2[(k0)     * C + c], w, d0);
            d1 = fmaf(wp2[(k0 + 1) * C + c], w, d1);
            d2 = fmaf(wp2[(k0 + 8) * C + c], w, d2);
            d3 = fmaf(wp2[(k0 + 9) * C + c], w, d3);
        }
        half2 b0 = __floats2half2_rn(d0, d1);
        half2 b1 = __floats2half2_rn(d2, d3);
        g_afrag16[idx * 2 + 0] = *(unsigned*)&b0;
        g_afrag16[idx * 2 + 1] = *(unsigned*)&b1;
    } else {
        // Wp2^T fp16 A-frags for k2 phase 5; g = b-5
        int g = b - 5;
        int kb = t >> 5, lane = t & 31;
        int gid = lane >> 2, tig = lane & 3;
        int c0 = g * 16 + gid;
        int k0 = kb * 16 + tig * 2;
        half2 ax = __floats2half2_rn(wp2[(k0)     * C + c0],     wp2[(k0 + 1) * C + c0]);
        half2 ay = __floats2half2_rn(wp2[(k0)     * C + c0 + 8], wp2[(k0 + 1) * C + c0 + 8]);
        half2 az = __floats2half2_rn(wp2[(k0 + 8) * C + c0],     wp2[(k0 + 9) * C + c0]);
        half2 aw = __floats2half2_rn(wp2[(k0 + 8) * C + c0 + 8], wp2[(k0 + 9) * C + c0 + 8]);
        uint4 v;
        v.x = *(unsigned*)&ax; v.y = *(unsigned*)&ay;
        v.z = *(unsigned*)&az; v.w = *(unsigned*)&aw;
        ((uint4*)g_p5a)[(g * 16 + kb) * 32 + lane] = v;
    }
}

// ---------------- K1: q/k/v GEMM + projection, all fp16 mma ----------------
__global__ __launch_bounds__(256, 2) void k1_qkv(
    const float* __restrict__ feat, const float* __restrict__ bv) {
    extern __shared__ float sm[];
    unsigned short* feat16 = (unsigned short*)sm;                   // 32*FSH halves
    unsigned short* ybuf16 = (unsigned short*)sm + BM * FSH;        // 32*YSH halves

    int t    = threadIdx.x;
    int r0b  = blockIdx.x * BM;
    int warp = t >> 5, lane = t & 31;
    int gid  = lane >> 2, tig = lane & 3;
    int n0   = warp * 32;

    for (int i = t; i < BM * C / 4; i += 256) {
        int r = i >> 6, c4 = (i & 63) * 4;
        float4 f = *(const float4*)&feat[(r0b + r) * C + c4];
        half2 h0 = __floats2half2_rn(f.x, f.y);
        half2 h1 = __floats2half2_rn(f.z, f.w);
        uint2 pk; pk.x = *(unsigned*)&h0; pk.y = *(unsigned*)&h1;
        *(uint2*)&feat16[r * FSH + c4] = pk;
    }
    __syncthreads();

    #pragma unroll 1
    for (int pass = 0; pass < 3; pass++) {
        const ull* wf = (const ull*)(g_wfrag16 + pass * (16 * 32 * 64));
        float4 acc[2][4];
        #pragma unroll
        for (int mt = 0; mt < 2; mt++)
            #pragma unroll
            for (int nt = 0; nt < 4; nt++) acc[mt][nt] = make_float4(0.f, 0.f, 0.f, 0.f);

        #pragma unroll 4
        for (int kb = 0; kb < 16; kb++) {
            int kof = kb * 16 + tig * 2;
            unsigned a0 = *(const unsigned*)&feat16[(gid)      * FSH + kof];
            unsigned a1 = *(const unsigned*)&feat16[(gid + 8)  * FSH + kof];
            unsigned a2 = *(const unsigned*)&feat16[(gid)      * FSH + kof + 8];
            unsigned a3 = *(const unsigned*)&feat16[(gid + 8)  * FSH + kof + 8];
            unsigned a4 = *(const unsigned*)&feat16[(gid + 16) * FSH + kof];
            unsigned a5 = *(const unsigned*)&feat16[(gid + 24) * FSH + kof];
            unsigned a6 = *(const unsigned*)&feat16[(gid + 16) * FSH + kof + 8];
            unsigned a7 = *(const unsigned*)&feat16[(gid + 24) * FSH + kof + 8];
            #pragma unroll
            for (int nt = 0; nt < 4; nt++) {
                ull bb = wf[((kb * 32) + warp * 4 + nt) * 32 + lane];
                unsigned b0 = (unsigned)bb, b1 = (unsigned)(bb >> 32);
                MMA_F16(acc[0][nt], a0, a1, a2, a3, b0, b1);
                MMA_F16(acc[1][nt], a4, a5, a6, a7, b0, b1);
            }
        }

        if (pass == 2) {
            #pragma unroll
            for (int nt = 0; nt < 4; nt++) {
                int col = n0 + nt * 8 + tig * 2;
                float2 b2 = *(const float2*)&bv[col];
                #pragma unroll
                for (int mt = 0; mt < 2; mt++) {
                    int rA = r0b + mt * 16 + gid, rB = rA + 8;
                    *(half2*)&g_vall16[rA * C + col] =
                        __floats2half2_rn(acc[mt][nt].x + b2.x, acc[mt][nt].y + b2.y);
                    *(half2*)&g_vall16[rB * C + col] =
                        __floats2half2_rn(acc[mt][nt].z + b2.x, acc[mt][nt].w + b2.y);
                }
            }
        } else {
            const float* sA = (pass == 0) ? g_sq : g_sk;
            const float* tA = (pass == 0) ? g_tq : g_tk;
            #pragma unroll
            for (int nt = 0; nt < 4; nt++) {
                int col = n0 + nt * 8 + tig * 2;
                float2 s2 = *(const float2*)&sA[col];
                float2 t2 = *(const float2*)&tA[col];
                #pragma unroll
                for (int mt = 0; mt < 2; mt++) {
                    int rA = mt * 16 + gid, rB = rA + 8;
                    *(half2*)&ybuf16[rA * YSH + col] = __floats2half2_rn(
                        fmaxf(fmaf(acc[mt][nt].x, s2.x, t2.x), 0.f),
                        fmaxf(fmaf(acc[mt][nt].y, s2.y, t2.y), 0.f));
                    *(half2*)&ybuf16[rB * YSH + col] = __floats2half2_rn(
                        fmaxf(fmaf(acc[mt][nt].z, s2.x, t2.x), 0.f),
                        fmaxf(fmaf(acc[mt][nt].w, s2.y, t2.y), 0.f));
                }
            }
            __syncthreads();
            // projection y @ ww1 via fp16 mma: 4 warps (2 m-tiles x 2 n-halves)
            if (warp < 4) {
                int m0p = (warp & 1) * 16, nbp = warp >> 1;
                float4 pa = make_float4(0.f, 0.f, 0.f, 0.f);
                const ull* w1f = (const ull*)g_w1frag16;
                #pragma unroll 4
                for (int kb = 0; kb < 16; kb++) {
                    int kof = kb * 16 + tig * 2;
                    unsigned a0 = *(const unsigned*)&ybuf16[(m0p + gid)     * YSH + kof];
                    unsigned a1 = *(const unsigned*)&ybuf16[(m0p + gid + 8) * YSH + kof];
                    unsigned a2 = *(const unsigned*)&ybuf16[(m0p + gid)     * YSH + kof + 8];
                    unsigned a3 = *(const unsigned*)&ybuf16[(m0p + gid + 8) * YSH + kof + 8];
                    ull bb = w1f[(kb * 2 + nbp) * 32 + lane];
                    MMA_F16(pa, a0, a1, a2, a3, (unsigned)bb, (unsigned)(bb >> 32));
                }
                float* dst = (pass == 0) ? g_qW : g_kW;
                int col = nbp * 8 + tig * 2;
                dst[(r0b + m0p + gid)     * G + col]     = pa.x;
                dst[(r0b + m0p + gid)     * G + col + 1] = pa.y;
                dst[(r0b + m0p + gid + 8) * G + col]     = pa.z;
                dst[(r0b + m0p + gid + 8) * G + col + 1] = pa.w;
            }
            __syncthreads();
        }
    }
}

// ---------------- K2: fused per-point grouped attention, P=8 ---------------
// hid uses per-point skew: point p occupies halves [p*PSK, p*PSK + 16*HP)
struct K2S {
    unsigned short hid[P * PSK];      // skewed; fp16; becomes hw in place
    float    lgb[P * 16 * LGS];       // raw logits -> logits2 -> weights
    float    vterm[P * 256];
    float    kwq[P * 16 * 16];
    unsigned short wT16[P * 16 * 16]; // transposed fp16 softmax weights
    float    qwb[P * 16];
    unsigned posh[P * 16 * 3];        // broadcast half2 pos
    float    wsum[P * 16];
    float    mask[P * 16];
    int      idx[P * 16];
    float    ww2[G * G];
    float    bp2s[C];
    float    sw[G], cw[G], bw2s[G];
};

__global__ __launch_bounds__(256, 2) void k2_attn(
    const float* __restrict__ coord, const int* __restrict__ knn,
    const float* __restrict__ bp2,   const float* __restrict__ ww2,
    const float* __restrict__ bw2,   float* __restrict__ out) {
    extern __shared__ char smraw[];
    K2S& S = *reinterpret_cast<K2S*>(smraw);
    int t  = threadIdx.x;
    int n0 = blockIdx.x * P;

    S.ww2[t]  = ww2[t];
    S.bp2s[t] = __ldg(&bp2[t]);
    if (t < G) { S.sw[t] = g_sw[t]; S.cw[t] = g_cw[t]; S.bw2s[t] = bw2[t]; }

    // phase 1 (t<128): gather idx / mask / pos(half2) + cp.async kW/qW
    if (t < 128) {
        int p = t >> 4, n = n0 + p;
        int id  = knn[n * KNN + (t & 15)];
        int ip1 = id + 1;
        float m = (float)((ip1 > 0) - (ip1 < 0));
        int sid = (id > 0) ? id : 0;
        S.idx[t]  = sid;
        S.mask[t] = m;
        #pragma unroll
        for (int d = 0; d < 3; d++) {
            float pd = (coord[sid * 3 + d] - coord[n * 3 + d]) * m;
            half2 h = __float2half2_rn(pd);
            S.posh[t * 3 + d] = *(unsigned*)&h;
        }
        unsigned d0 = smem_u32(&S.kwq[t * 16]);
        const float* s0 = &g_kW[sid * G];
        #pragma unroll
        for (int j = 0; j < 4; j++) CP_ASYNC16(d0 + j * 16, s0 + j * 4);
        if (t < P) {
            unsigned d1 = smem_u32(&S.qwb[t * 16]);
            const float* s1 = &g_qW[(n0 + t) * G];
            #pragma unroll
            for (int j = 0; j < 4; j++) CP_ASYNC16(d1 + j * 16, s1 + j * 4);
        }
        asm volatile("cp.async.commit_group;");
    }
    __syncthreads();

    // phase 2: hidden = relu(bn(pos @ Wp1 + bp1)) in half2; 128 skewed rows
    {
        int half_ = t >> 7;
        int cpi = t & 127;
        half2 w0 = *(half2*)&g_wp1h[cpi];
        half2 w1 = *(half2*)&g_wp1h[128 + cpi];
        half2 w2 = *(half2*)&g_wp1h[256 + cpi];
        half2 sc = *(half2*)&g_wp1h[384 + cpi];
        half2 sh = *(half2*)&g_wp1h[512 + cpi];
        half2 z  = __float2half2_rn(0.f);
        #pragma unroll 4
        for (int ps = half_ * 64; ps < half_ * 64 + 64; ps++) {
            half2 px = *(half2*)&S.posh[ps * 3 + 0];
            half2 py = *(half2*)&S.posh[ps * 3 + 1];
            half2 pz = *(half2*)&S.posh[ps * 3 + 2];
            half2 h = __hfma2(px, w0, __hfma2(py, w1, __hmul2(pz, w2)));
            h = __hmax2(__hfma2(h, sc, sh), z);
            int ro = (ps >> 4) * PSK + (ps & 15) * HP;
            *(half2*)&S.hid[ro + cpi * 2] = h;
        }
    }
    __syncthreads();

    // phase 3a: lg = hidden @ A via fp16 mma (per-warp base = w*PSK)
    {
        int w = t >> 5, lane = t & 31, gid = lane >> 2, tig = lane & 3;
        const unsigned short* hb = &S.hid[w * PSK];
        float4 acc0 = make_float4(0.f, 0.f, 0.f, 0.f);
        float4 acc1 = make_float4(0.f, 0.f, 0.f, 0.f);
        const ull* bf = (const ull*)g_afrag16;
        #pragma unroll
        for (int kb = 0; kb < 16; kb++) {
            int kof = kb * 16 + tig * 2;
            unsigned a0 = *(const unsigned*)&hb[(gid)     * HP + kof];
            unsigned a1 = *(const unsigned*)&hb[(gid + 8) * HP + kof];
            unsigned a2 = *(const unsigned*)&hb[(gid)     * HP + kof + 8];
            unsigned a3 = *(const unsigned*)&hb[(gid + 8) * HP + kof + 8];
            ull bb0 = bf[(kb * 2 + 0) * 32 + lane];
            ull bb1 = bf[(kb * 2 + 1) * 32 + lane];
            MMA_F16(acc0, a0, a1, a2, a3, (unsigned)bb0, (unsigned)(bb0 >> 32));
            MMA_F16(acc1, a0, a1, a2, a3, (unsigned)bb1, (unsigned)(bb1 >> 32));
        }
        int m0 = w * 16;
        S.lgb[(m0 + gid)     * LGS + tig * 2]      = acc0.x;
        S.lgb[(m0 + gid)     * LGS + tig * 2 + 1]  = acc0.y;
        S.lgb[(m0 + gid + 8) * LGS + tig * 2]      = acc0.z;
        S.lgb[(m0 + gid + 8) * LGS + tig * 2 + 1]  = acc0.w;
        S.lgb[(m0 + gid)     * LGS + 8 + tig * 2]     = acc1.x;
        S.lgb[(m0 + gid)     * LGS + 8 + tig * 2 + 1] = acc1.y;
        S.lgb[(m0 + gid + 8) * LGS + 8 + tig * 2]     = acc1.z;
        S.lgb[(m0 + gid + 8) * LGS + 8 + tig * 2 + 1] = acc1.w;
    }
    __syncthreads();

    // phase 3b (t<128): + lb, relu/sw/cw, @Ww2 (in place); then 4a softmax
    if (t < 128) {
        asm volatile("cp.async.wait_group 0;" ::: "memory");
        int r = t, p = r >> 4;
        float m = S.mask[r];
        const float4* kw = (const float4*)&S.kwq[r * 16];
        const float4* qw = (const float4*)&S.qwb[p * 16];
        float u[16];
        #pragma unroll
        for (int q = 0; q < 4; q++) {
            float4 sv = *(const float4*)&S.lgb[r * LGS + q * 4];
            float4 kv = kw[q], qv = qw[q];
            float4 lb;
            lb.x = fmaf(m, kv.x, -qv.x); lb.y = fmaf(m, kv.y, -qv.y);
            lb.z = fmaf(m, kv.z, -qv.z); lb.w = fmaf(m, kv.w, -qv.w);
            u[q*4+0] = fmaxf(fmaf(sv.x + lb.x, S.sw[q*4+0], S.cw[q*4+0]), 0.f);
            u[q*4+1] = fmaxf(fmaf(sv.y + lb.y, S.sw[q*4+1], S.cw[q*4+1]), 0.f);
            u[q*4+2] = fmaxf(fmaf(sv.z + lb.z, S.sw[q*4+2], S.cw[q*4+2]), 0.f);
            u[q*4+3] = fmaxf(fmaf(sv.w + lb.w, S.sw[q*4+3], S.cw[q*4+3]), 0.f);
        }
        #pragma unroll
        for (int g2 = 0; g2 < 16; g2++) {
            float acc = S.bw2s[g2];
            #pragma unroll
            for (int g = 0; g < 16; g++) acc = fmaf(u[g], S.ww2[g * 16 + g2], acc);
            S.lgb[r * LGS + g2] = acc;
        }
        __syncwarp();
        // 4a softmax; warp w covers rows 32w..32w+31 = points 2w,2w+1
        int pp = t >> 4, g = t & 15;
        float mx = -1e30f;
        #pragma unroll
        for (int s = 0; s < 16; s++) mx = fmaxf(mx, S.lgb[(pp * 16 + s) * LGS + g]);
        float e[16], sum = 0.f;
        #pragma unroll
        for (int s = 0; s < 16; s++) {
            e[s] = __expf(S.lgb[(pp * 16 + s) * LGS + g] - mx);
            sum += e[s];
        }
        float inv = 1.f / sum, ws = 0.f;
        #pragma unroll
        for (int s = 0; s < 16; s++) {
            float w = e[s] * inv * S.mask[pp * 16 + s];
            e[s] = w;
            S.lgb[(pp * 16 + s) * LGS + g] = w;
            ws += w;
        }
        S.wsum[t] = ws;
        unsigned wu[8];
        #pragma unroll
        for (int sb = 0; sb < 8; sb++) {
            half2 h = __floats2half2_rn(e[sb * 2], e[sb * 2 + 1]);
            wu[sb] = *(unsigned*)&h;
        }
        uint4* wtrow = (uint4*)&S.wT16[(pp * 16 + g) * 16];
        wtrow[0] = make_uint4(wu[0], wu[1], wu[2], wu[3]);
        wtrow[1] = make_uint4(wu[4], wu[5], wu[6], wu[7]);
    }
    __syncthreads();

    // phase 4A: v-gather: 512 (point, 4ch) slots, 2 per thread
    {
        #pragma unroll
        for (int j = 0; j < 2; j++) {
            int si = t + j * 256;
            int p  = si >> 6;
            int c0 = (si & 63) * 4;
            int g  = c0 >> 4;
            float a0 = 0.f, a1 = 0.f, a2 = 0.f, a3 = 0.f;
            #pragma unroll
            for (int s = 0; s < 16; s++) {
                float w = S.lgb[(p * 16 + s) * LGS + g];
                uint2 v = *(const uint2*)&g_vall16[S.idx[p * 16 + s] * C + c0];
                float2 v0 = __half22float2(*(half2*)&v.x);
                float2 v1 = __half22float2(*(half2*)&v.y);
                a0 = fmaf(w, v0.x, a0); a1 = fmaf(w, v0.y, a1);
                a2 = fmaf(w, v1.x, a2); a3 = fmaf(w, v1.y, a3);
            }
            *(float4*)&S.vterm[p * 256 + c0] = make_float4(a0, a1, a2, a3);
        }
    }
    // phase 4B: hw = wT @ hid via fp16 mma, in place. warp = point.
    {
        int w = t >> 5, lane = t & 31, gid = lane >> 2, tig = lane & 3;
        int p = w;
        const unsigned short* wa = &S.wT16[p * 256];
        unsigned a0 = *(const unsigned*)&wa[gid * 16 + tig * 2];
        unsigned a1 = *(const unsigned*)&wa[(gid + 8) * 16 + tig * 2];
        unsigned a2 = *(const unsigned*)&wa[gid * 16 + tig * 2 + 8];
        unsigned a3 = *(const unsigned*)&wa[(gid + 8) * 16 + tig * 2 + 8];
        unsigned short* hb = &S.hid[p * PSK];
        #pragma unroll 4
        for (int nb = 0; nb < 32; nb++) {
            int c = nb * 8 + gid;
            unsigned s0 = hb[(2 * tig)     * HP + c];
            unsigned s1 = hb[(2 * tig + 1) * HP + c];
            unsigned s2 = hb[(2 * tig + 8) * HP + c];
            unsigned s3 = hb[(2 * tig + 9) * HP + c];
            unsigned b0 = s0 | (s1 << 16);
            unsigned b1 = s2 | (s3 << 16);
            float4 acc = make_float4(0.f, 0.f, 0.f, 0.f);
            MMA_F16(acc, a0, a1, a2, a3, b0, b1);
            int co = nb * 8 + tig * 2;
            *(half2*)&hb[(gid)     * HP + co] = __floats2half2_rn(acc.x, acc.y);
            *(half2*)&hb[(gid + 8) * HP + co] = __floats2half2_rn(acc.z, acc.w);
        }
    }
    __syncthreads();

    // phase 5: per-group GEMM out[16c x 8p] = Wp2^T-block @ hw, fp16 mma.
    // B row for lane: point gid, group g -> skewed offset gid*PSK + g*HP:
    // bank = (4*gid + tig) mod 32 -> conflict-free.
    {
        int w = t >> 5, lane = t & 31, gid = lane >> 2, tig = lane & 3;
        const uint4* af = (const uint4*)g_p5a;
        #pragma unroll
        for (int gi = 0; gi < 2; gi++) {
            int g = w + gi * 8;
            const unsigned short* hb = &S.hid[g * HP];
            float4 acc = make_float4(0.f, 0.f, 0.f, 0.f);
            #pragma unroll
            for (int kb = 0; kb < 16; kb++) {
                uint4 a = af[(g * 16 + kb) * 32 + lane];
                unsigned b0 = *(const unsigned*)&hb[gid * PSK + kb * 16 + tig * 2];
                unsigned b1 = *(const unsigned*)&hb[gid * PSK + kb * 16 + tig * 2 + 8];
                MMA_F16(acc, a.x, a.y, a.z, a.w, b0, b1);
            }
            int cg0 = g * 16 + gid, cg1 = cg0 + 8;
            int p0 = tig * 2, p1 = p0 + 1;
            float b0c = S.bp2s[cg0], b1c = S.bp2s[cg1];
            out[(n0 + p0) * C + cg0] = acc.x + S.vterm[p0 * 256 + cg0] + b0c * S.wsum[p0 * 16 + g];
            out[(n0 + p1) * C + cg0] = acc.y + S.vterm[p1 * 256 + cg0] + b0c * S.wsum[p1 * 16 + g];
            out[(n0 + p0) * C + cg1] = acc.z + S.vterm[p0 * 256 + cg1] + b1c * S.wsum[p0 * 16 + g];
            out[(n0 + p1) * C + cg1] = acc.w + S.vterm[p1 * 256 + cg1] + b1c * S.wsum[p1 * 16 + g];
        }
    }
}

// ---------------- launch ----------------------------------------------------
extern "C" void kernel_launch(void* const* d_in, const int* in_sizes, int n_in,
                              void* d_out, int out_size) {
    (void)in_sizes; (void)n_in; (void)out_size;
    const float* feat  = (const float*)d_in[0];
    const float* coord = (const float*)d_in[1];
    const int*   knn   = (const int*)  d_in[2];
    const float* Wq = (const float*)d_in[3];  const float* bq = (const float*)d_in[4];  const float* bnq = (const float*)d_in[5];
    const float* Wk = (const float*)d_in[6];  const float* bk = (const float*)d_in[7];  const float* bnk = (const float*)d_in[8];
    const float* Wv = (const float*)d_in[9];  const float* bv = (const float*)d_in[10];
    const float* Wp1 = (const float*)d_in[11]; const float* bp1 = (const float*)d_in[12]; const float* bnp = (const float*)d_in[13];
    const float* Wp2 = (const float*)d_in[14]; const float* bp2 = (const float*)d_in[15];
    const float* Ww1 = (const float*)d_in[16]; const float* bw1 = (const float*)d_in[17]; const float* bnw = (const float*)d_in[18];
    const float* Ww2 = (const float*)d_in[19]; const float* bw2 = (const float*)d_in[20];
    float* out = (float*)d_out;

    int k1_smem = (BM * FSH + BM * YSH) * 2;
    cudaFuncSetAttribute(k1_qkv,  cudaFuncAttributeMaxDynamicSharedMemorySize, k1_smem);
    cudaFuncSetAttribute(k2_attn, cudaFuncAttributeMaxDynamicSharedMemorySize, (int)sizeof(K2S));

    mega_prep<<<21, 512>>>(bq, bnq, bk, bnk, bp1, bnp, bw1, bnw, bp2, Ww1, Wp1, Wp2);
    prep_wfrag16<<<48, 1024>>>(Wq, Wk, Wv);
    k1_qkv<<<NPTS / BM, 256, k1_smem>>>(feat, bv);
    k2_attn<<<NPTS / P, 256, sizeof(K2S)>>>(coord, knn, bp2, Ww2, bw2, out);
}

// round 17
// speedup vs baseline: 3.1471x; 1.0884x over previous
#include <cuda_runtime.h>
#include <cuda_fp16.h>
#include <math.h>

#define NPTS 20000
#define KNN  16
#define C    256
#define G    16
#define EPS  1e-5f
#define P    8          // points per block in K2
#define BM   32         // feat rows per block in K1
#define FSH  264        // k1 feat_s stride (halves)
#define YSH  264        // k1 ybuf stride (halves)
#define HP   264        // k2 hid row stride (halves)
#define PSK  (16 * HP + 8)   // per-point skewed block stride (halves)
#define LGS  20         // k2 logit/weight buffer row stride (floats)

typedef unsigned long long ull;

// ---------------- scratch (static device memory) ---------------------------
__device__ __half   g_vall16[NPTS * C];          // v_all, fp16
__device__ float    g_qW[NPTS * G];
__device__ float    g_kW[NPTS * G];
__device__ unsigned g_wfrag16[3 * 16 * 32 * 64]; // W q/k/v fp16 B-frags (k1)
__device__ unsigned g_w1frag16[2048];            // ww1 fp16 B-frags (k1 projection)
__device__ unsigned g_afrag16[2048];             // (Wp2@Ww1) fp16 B-frags (k2 ph3a)
__device__ unsigned g_p5a[16 * 16 * 32 * 4];     // Wp2^T fp16 A-frags (k2 ph5)
__device__ unsigned g_wp1h[5 * 128];             // half2-packed wp1 w0/w1/w2/sc/sh
__device__ float    g_sq[C], g_tq[C];
__device__ float    g_sk[C], g_tk[C];
__device__ float    g_sw[G], g_cw[G];

// ---------------- helpers ---------------------------------------------------
__device__ __forceinline__ unsigned smem_u32(const void* p) {
    unsigned r;
    asm("{ .reg .u64 t; cvta.to.shared.u64 t, %1; cvt.u32.u64 %0, t; }"
        : "=r"(r) : "l"(p));
    return r;
}
#define CP_ASYNC16(dst, src) \
    asm volatile("cp.async.ca.shared.global [%0], [%1], 16;" :: "r"(dst), "l"(src))
#define MMA_F16(acc, a0, a1, a2, a3, b0, b1)                                    \
    asm("mma.sync.aligned.m16n8k16.row.col.f32.f16.f16.f32 "                    \
        "{%0,%1,%2,%3},{%4,%5,%6,%7},{%8,%9},{%0,%1,%2,%3};"                    \
        : "+f"(acc.x), "+f"(acc.y), "+f"(acc.z), "+f"(acc.w)                    \
        : "r"(a0), "r"(a1), "r"(a2), "r"(a3), "r"(b0), "r"(b1))
#define LDMX4(d0, d1, d2, d3, addr)                                             \
    asm volatile("ldmatrix.sync.aligned.m8n8.x4.shared.b16 {%0,%1,%2,%3}, [%4];"\
        : "=r"(d0), "=r"(d1), "=r"(d2), "=r"(d3) : "r"(addr))
#define LDMX2T(d0, d1, addr)                                                    \
    asm volatile("ldmatrix.sync.aligned.m8n8.x2.trans.shared.b16 {%0,%1}, [%2];"\
        : "=r"(d0), "=r"(d1) : "r"(addr))

// ---------------- prep kernels ---------------------------------------------
__global__ void prep_wfrag16(const float* __restrict__ Wq,
                             const float* __restrict__ Wk,
                             const float* __restrict__ Wv) {
    int pass = blockIdx.x >> 4, kb = blockIdx.x & 15;
    const float* W = (pass == 0) ? Wq : ((pass == 1) ? Wk : Wv);
    int i  = threadIdx.x;
    int nb = i >> 5, lane = i & 31;
    int gid = lane >> 2, tig = lane & 3;
    int n  = nb * 8 + gid;
    int k0 = kb * 16 + tig * 2;
    half2 b0 = __floats2half2_rn(W[k0 * C + n],       W[(k0 + 1) * C + n]);
    half2 b1 = __floats2half2_rn(W[(k0 + 8) * C + n], W[(k0 + 9) * C + n]);
    unsigned* dst = g_wfrag16 + pass * (16 * 32 * 64);
    dst[((kb * 32 + nb) * 32 + lane) * 2 + 0] = *(unsigned*)&b0;
    dst[((kb * 32 + nb) * 32 + lane) * 2 + 1] = *(unsigned*)&b1;
}

__global__ void mega_prep(const float* __restrict__ bq, const float* __restrict__ bnq,
                          const float* __restrict__ bk, const float* __restrict__ bnk,
                          const float* __restrict__ bp1, const float* __restrict__ bnp,
                          const float* __restrict__ bw1, const float* __restrict__ bnw,
                          const float* __restrict__ bp2, const float* __restrict__ ww1,
                          const float* __restrict__ wp1, const float* __restrict__ wp2) {
    int b = blockIdx.x, t = threadIdx.x;
    if (b == 0) {
        if (t < C) {
            float s;
            s = bnq[t] * rsqrtf(bnq[3 * C + t] + EPS);
            g_sq[t] = s; g_tq[t] = (bq[t] - bnq[2 * C + t]) * s + bnq[C + t];
            s = bnk[t] * rsqrtf(bnk[3 * C + t] + EPS);
            g_sk[t] = s; g_tk[t] = (bk[t] - bnk[2 * C + t]) * s + bnk[C + t];
        }
        if (t < G) {
            float s = bnw[t] * rsqrtf(bnw[3 * G + t] + EPS);
            float bp2w = 0.f;
            for (int c = 0; c < C; c++) bp2w += bp2[c] * ww1[c * G + t];
            g_sw[t] = s;
            g_cw[t] = (bw1[t] + bp2w - bnw[2 * G + t]) * s + bnw[G + t];
        }
        if (t >= 256 && t < 384) {
            int cpi = t - 256;
            int c0 = 2 * cpi, c1 = c0 + 1;
            float sa = bnp[c0] * rsqrtf(bnp[3 * C + c0] + EPS);
            float ta = (bp1[c0] - bnp[2 * C + c0]) * sa + bnp[C + c0];
            float sb = bnp[c1] * rsqrtf(bnp[3 * C + c1] + EPS);
            float tb = (bp1[c1] - bnp[2 * C + c1]) * sb + bnp[C + c1];
            half2 h;
            h = __floats2half2_rn(wp1[c0],         wp1[c1]);         g_wp1h[cpi]       = *(unsigned*)&h;
            h = __floats2half2_rn(wp1[C + c0],     wp1[C + c1]);     g_wp1h[128 + cpi] = *(unsigned*)&h;
            h = __floats2half2_rn(wp1[2 * C + c0], wp1[2 * C + c1]); g_wp1h[256 + cpi] = *(unsigned*)&h;
            h = __floats2half2_rn(sa, sb);                           g_wp1h[384 + cpi] = *(unsigned*)&h;
            h = __floats2half2_rn(ta, tb);                           g_wp1h[512 + cpi] = *(unsigned*)&h;
        }
    } else if (b <= 2) {
        int idx  = (b - 1) * 512 + t;
        int lane = idx & 31, knb = idx >> 5;
        int kb = knb >> 1, nb = knb & 1;
        int gid = lane >> 2, tig = lane & 3;
        int n  = nb * 8 + gid;
        int k0 = kb * 16 + tig * 2;
        half2 b0 = __floats2half2_rn(ww1[k0 * G + n],       ww1[(k0 + 1) * G + n]);
        half2 b1 = __floats2half2_rn(ww1[(k0 + 8) * G + n], ww1[(k0 + 9) * G + n]);
        g_w1frag16[idx * 2 + 0] = *(unsigned*)&b0;
        g_w1frag16[idx * 2 + 1] = *(unsigned*)&b1;
    } else if (b <= 4) {
        int idx  = (b - 3) * 512 + t;
        int lane = idx & 31, knb = idx >> 5;
        int kb = knb >> 1, nb = knb & 1;
        int gid = lane >> 2, tig = lane & 3;
        int g  = nb * 8 + gid;
        int k0 = kb * 16 + tig * 2;
        float d0 = 0.f, d1 = 0.f, d2 = 0.f, d3 = 0.f;
        #pragma unroll 4
        for (int c = 0; c < C; c++) {
            float w = ww1[c * G + g];
            d0 = fmaf(wp2[(k0)     * C + c], w, d0);
            d1 = fmaf(wp2[(k0 + 1) * C + c], w, d1);
            d2 = fmaf(wp2[(k0 + 8) * C + c], w, d2);
            d3 = fmaf(wp2[(k0 + 9) * C + c], w, d3);
        }
        half2 b0 = __floats2half2_rn(d0, d1);
        half2 b1 = __floats2half2_rn(d2, d3);
        g_afrag16[idx * 2 + 0] = *(unsigned*)&b0;
        g_afrag16[idx * 2 + 1] = *(unsigned*)&b1;
    } else {
        int g = b - 5;
        int kb = t >> 5, lane = t & 31;
        int gid = lane >> 2, tig = lane & 3;
        int c0 = g * 16 + gid;
        int k0 = kb * 16 + tig * 2;
        half2 ax = __floats2half2_rn(wp2[(k0)     * C + c0],     wp2[(k0 + 1) * C + c0]);
        half2 ay = __floats2half2_rn(wp2[(k0)     * C + c0 + 8], wp2[(k0 + 1) * C + c0 + 8]);
        half2 az = __floats2half2_rn(wp2[(k0 + 8) * C + c0],     wp2[(k0 + 9) * C + c0]);
        half2 aw = __floats2half2_rn(wp2[(k0 + 8) * C + c0 + 8], wp2[(k0 + 9) * C + c0 + 8]);
        uint4 v;
        v.x = *(unsigned*)&ax; v.y = *(unsigned*)&ay;
        v.z = *(unsigned*)&az; v.w = *(unsigned*)&aw;
        ((uint4*)g_p5a)[(g * 16 + kb) * 32 + lane] = v;
    }
}

// ---------------- K1: q/k/v GEMM + projection, all fp16 mma ----------------
__global__ __launch_bounds__(256, 2) void k1_qkv(
    const float* __restrict__ feat, const float* __restrict__ bv) {
    extern __shared__ float sm[];
    unsigned short* feat16 = (unsigned short*)sm;
    unsigned short* ybuf16 = (unsigned short*)sm + BM * FSH;

    int t    = threadIdx.x;
    int r0b  = blockIdx.x * BM;
    int warp = t >> 5, lane = t & 31;
    int gid  = lane >> 2, tig = lane & 3;
    int n0   = warp * 32;

    for (int i = t; i < BM * C / 4; i += 256) {
        int r = i >> 6, c4 = (i & 63) * 4;
        float4 f = *(const float4*)&feat[(r0b + r) * C + c4];
        half2 h0 = __floats2half2_rn(f.x, f.y);
        half2 h1 = __floats2half2_rn(f.z, f.w);
        uint2 pk; pk.x = *(unsigned*)&h0; pk.y = *(unsigned*)&h1;
        *(uint2*)&feat16[r * FSH + c4] = pk;
    }
    __syncthreads();

    #pragma unroll 1
    for (int pass = 0; pass < 3; pass++) {
        const ull* wf = (const ull*)(g_wfrag16 + pass * (16 * 32 * 64));
        float4 acc[2][4];
        #pragma unroll
        for (int mt = 0; mt < 2; mt++)
            #pragma unroll
            for (int nt = 0; nt < 4; nt++) acc[mt][nt] = make_float4(0.f, 0.f, 0.f, 0.f);

        #pragma unroll 4
        for (int kb = 0; kb < 16; kb++) {
            int kof = kb * 16 + tig * 2;
            unsigned a0 = *(const unsigned*)&feat16[(gid)      * FSH + kof];
            unsigned a1 = *(const unsigned*)&feat16[(gid + 8)  * FSH + kof];
            unsigned a2 = *(const unsigned*)&feat16[(gid)      * FSH + kof + 8];
            unsigned a3 = *(const unsigned*)&feat16[(gid + 8)  * FSH + kof + 8];
            unsigned a4 = *(const unsigned*)&feat16[(gid + 16) * FSH + kof];
            unsigned a5 = *(const unsigned*)&feat16[(gid + 24) * FSH + kof];
            unsigned a6 = *(const unsigned*)&feat16[(gid + 16) * FSH + kof + 8];
            unsigned a7 = *(const unsigned*)&feat16[(gid + 24) * FSH + kof + 8];
            #pragma unroll
            for (int nt = 0; nt < 4; nt++) {
                ull bb = wf[((kb * 32) + warp * 4 + nt) * 32 + lane];
                unsigned b0 = (unsigned)bb, b1 = (unsigned)(bb >> 32);
                MMA_F16(acc[0][nt], a0, a1, a2, a3, b0, b1);
                MMA_F16(acc[1][nt], a4, a5, a6, a7, b0, b1);
            }
        }

        if (pass == 2) {
            #pragma unroll
            for (int nt = 0; nt < 4; nt++) {
                int col = n0 + nt * 8 + tig * 2;
                float2 b2 = *(const float2*)&bv[col];
                #pragma unroll
                for (int mt = 0; mt < 2; mt++) {
                    int rA = r0b + mt * 16 + gid, rB = rA + 8;
                    *(half2*)&g_vall16[rA * C + col] =
                        __floats2half2_rn(acc[mt][nt].x + b2.x, acc[mt][nt].y + b2.y);
                    *(half2*)&g_vall16[rB * C + col] =
                        __floats2half2_rn(acc[mt][nt].z + b2.x, acc[mt][nt].w + b2.y);
                }
            }
        } else {
            const float* sA = (pass == 0) ? g_sq : g_sk;
            const float* tA = (pass == 0) ? g_tq : g_tk;
            #pragma unroll
            for (int nt = 0; nt < 4; nt++) {
                int col = n0 + nt * 8 + tig * 2;
                float2 s2 = *(const float2*)&sA[col];
                float2 t2 = *(const float2*)&tA[col];
                #pragma unroll
                for (int mt = 0; mt < 2; mt++) {
                    int rA = mt * 16 + gid, rB = rA + 8;
                    *(half2*)&ybuf16[rA * YSH + col] = __floats2half2_rn(
                        fmaxf(fmaf(acc[mt][nt].x, s2.x, t2.x), 0.f),
                        fmaxf(fmaf(acc[mt][nt].y, s2.y, t2.y), 0.f));
                    *(half2*)&ybuf16[rB * YSH + col] = __floats2half2_rn(
                        fmaxf(fmaf(acc[mt][nt].z, s2.x, t2.x), 0.f),
                        fmaxf(fmaf(acc[mt][nt].w, s2.y, t2.y), 0.f));
                }
            }
            __syncthreads();
            if (warp < 4) {
                int m0p = (warp & 1) * 16, nbp = warp >> 1;
                float4 pa = make_float4(0.f, 0.f, 0.f, 0.f);
                const ull* w1f = (const ull*)g_w1frag16;
                #pragma unroll 4
                for (int kb = 0; kb < 16; kb++) {
                    int kof = kb * 16 + tig * 2;
                    unsigned a0 = *(const unsigned*)&ybuf16[(m0p + gid)     * YSH + kof];
                    unsigned a1 = *(const unsigned*)&ybuf16[(m0p + gid + 8) * YSH + kof];
                    unsigned a2 = *(const unsigned*)&ybuf16[(m0p + gid)     * YSH + kof + 8];
                    unsigned a3 = *(const unsigned*)&ybuf16[(m0p + gid + 8) * YSH + kof + 8];
                    ull bb = w1f[(kb * 2 + nbp) * 32 + lane];
                    MMA_F16(pa, a0, a1, a2, a3, (unsigned)bb, (unsigned)(bb >> 32));
                }
                float* dst = (pass == 0) ? g_qW : g_kW;
                int col = nbp * 8 + tig * 2;
                dst[(r0b + m0p + gid)     * G + col]     = pa.x;
                dst[(r0b + m0p + gid)     * G + col + 1] = pa.y;
                dst[(r0b + m0p + gid + 8) * G + col]     = pa.z;
                dst[(r0b + m0p + gid + 8) * G + col + 1] = pa.w;
            }
            __syncthreads();
        }
    }
}

// ---------------- K2: fused per-point grouped attention, P=8 ---------------
struct K2S {
    unsigned short hid[P * PSK];      // skewed; fp16; becomes hw in place
    float    lgb[P * 16 * LGS];
    float    vterm[P * 256];
    float    kwq[P * 16 * 16];
    unsigned short wT16[P * 16 * 16];
    float    qwb[P * 16];
    unsigned posh[P * 16 * 3];
    float    wsum[P * 16];
    float    mask[P * 16];
    int      idx[P * 16];
    float    ww2[G * G];
    float    bp2s[C];
    float    sw[G], cw[G], bw2s[G];
};

__global__ __launch_bounds__(256, 2) void k2_attn(
    const float* __restrict__ coord, const int* __restrict__ knn,
    const float* __restrict__ bp2,   const float* __restrict__ ww2,
    const float* __restrict__ bw2,   float* __restrict__ out) {
    extern __shared__ char smraw[];
    K2S& S = *reinterpret_cast<K2S*>(smraw);
    int t  = threadIdx.x;
    int n0 = blockIdx.x * P;

    S.ww2[t]  = ww2[t];
    S.bp2s[t] = __ldg(&bp2[t]);
    if (t < G) { S.sw[t] = g_sw[t]; S.cw[t] = g_cw[t]; S.bw2s[t] = bw2[t]; }

    // phase 1 (t<128): gather idx / mask / pos(half2) + cp.async kW/qW
    if (t < 128) {
        int p = t >> 4, n = n0 + p;
        int id  = knn[n * KNN + (t & 15)];
        int ip1 = id + 1;
        float m = (float)((ip1 > 0) - (ip1 < 0));
        int sid = (id > 0) ? id : 0;
        S.idx[t]  = sid;
        S.mask[t] = m;
        #pragma unroll
        for (int d = 0; d < 3; d++) {
            float pd = (coord[sid * 3 + d] - coord[n * 3 + d]) * m;
            half2 h = __float2half2_rn(pd);
            S.posh[t * 3 + d] = *(unsigned*)&h;
        }
        unsigned d0 = smem_u32(&S.kwq[t * 16]);
        const float* s0 = &g_kW[sid * G];
        #pragma unroll
        for (int j = 0; j < 4; j++) CP_ASYNC16(d0 + j * 16, s0 + j * 4);
        if (t < P) {
            unsigned d1 = smem_u32(&S.qwb[t * 16]);
            const float* s1 = &g_qW[(n0 + t) * G];
            #pragma unroll
            for (int j = 0; j < 4; j++) CP_ASYNC16(d1 + j * 16, s1 + j * 4);
        }
        asm volatile("cp.async.commit_group;");
    }
    __syncthreads();

    // phase 2: hidden = relu(bn(pos @ Wp1 + bp1)) in half2.
    // thread = (warp-uniform ps, 8-channel chunk); 16 iters, STS.128.
    {
        int w = t >> 5, ci = t & 31;
        uint4 w0q = *(const uint4*)&g_wp1h[ci * 4];
        uint4 w1q = *(const uint4*)&g_wp1h[128 + ci * 4];
        uint4 w2q = *(const uint4*)&g_wp1h[256 + ci * 4];
        uint4 scq = *(const uint4*)&g_wp1h[384 + ci * 4];
        uint4 shq = *(const uint4*)&g_wp1h[512 + ci * 4];
        half2 z = __float2half2_rn(0.f);
        #pragma unroll 4
        for (int it = 0; it < 16; it++) {
            int ps = w + it * 8;
            half2 px = *(half2*)&S.posh[ps * 3 + 0];
            half2 py = *(half2*)&S.posh[ps * 3 + 1];
            half2 pz = *(half2*)&S.posh[ps * 3 + 2];
            uint4 o;
            {
                half2 h = __hfma2(px, *(half2*)&w0q.x, __hfma2(py, *(half2*)&w1q.x, __hmul2(pz, *(half2*)&w2q.x)));
                h = __hmax2(__hfma2(h, *(half2*)&scq.x, *(half2*)&shq.x), z);
                o.x = *(unsigned*)&h;
            }
            {
                half2 h = __hfma2(px, *(half2*)&w0q.y, __hfma2(py, *(half2*)&w1q.y, __hmul2(pz, *(half2*)&w2q.y)));
                h = __hmax2(__hfma2(h, *(half2*)&scq.y, *(half2*)&shq.y), z);
                o.y = *(unsigned*)&h;
            }
            {
                half2 h = __hfma2(px, *(half2*)&w0q.z, __hfma2(py, *(half2*)&w1q.z, __hmul2(pz, *(half2*)&w2q.z)));
                h = __hmax2(__hfma2(h, *(half2*)&scq.z, *(half2*)&shq.z), z);
                o.z = *(unsigned*)&h;
            }
            {
                half2 h = __hfma2(px, *(half2*)&w0q.w, __hfma2(py, *(half2*)&w1q.w, __hmul2(pz, *(half2*)&w2q.w)));
                h = __hmax2(__hfma2(h, *(half2*)&scq.w, *(half2*)&shq.w), z);
                o.w = *(unsigned*)&h;
            }
            int ro = (ps >> 4) * PSK + (ps & 15) * HP + ci * 8;
            *(uint4*)&S.hid[ro] = o;
        }
    }
    __syncthreads();

    // phase 3a: lg = hidden @ A via fp16 mma; A-frags via ldmatrix.x4
    {
        int w = t >> 5, lane = t & 31, gid = lane >> 2, tig = lane & 3;
        const unsigned short* hb = &S.hid[w * PSK];
        int lrow = (lane & 7) + ((lane >> 3) & 1) * 8;
        int kof0 = (lane >> 4) * 8;
        unsigned aaddr = smem_u32(&hb[lrow * HP + kof0]);
        float4 acc0 = make_float4(0.f, 0.f, 0.f, 0.f);
        float4 acc1 = make_float4(0.f, 0.f, 0.f, 0.f);
        const ull* bf = (const ull*)g_afrag16;
        #pragma unroll
        for (int kb = 0; kb < 16; kb++) {
            unsigned a0, a1, a2, a3;
            LDMX4(a0, a1, a2, a3, aaddr + kb * 32);
            ull bb0 = bf[(kb * 2 + 0) * 32 + lane];
            ull bb1 = bf[(kb * 2 + 1) * 32 + lane];
            MMA_F16(acc0, a0, a1, a2, a3, (unsigned)bb0, (unsigned)(bb0 >> 32));
            MMA_F16(acc1, a0, a1, a2, a3, (unsigned)bb1, (unsigned)(bb1 >> 32));
        }
        int m0 = w * 16;
        S.lgb[(m0 + gid)     * LGS + tig * 2]      = acc0.x;
        S.lgb[(m0 + gid)     * LGS + tig * 2 + 1]  = acc0.y;
        S.lgb[(m0 + gid + 8) * LGS + tig * 2]      = acc0.z;
        S.lgb[(m0 + gid + 8) * LGS + tig * 2 + 1]  = acc0.w;
        S.lgb[(m0 + gid)     * LGS + 8 + tig * 2]     = acc1.x;
        S.lgb[(m0 + gid)     * LGS + 8 + tig * 2 + 1] = acc1.y;
        S.lgb[(m0 + gid + 8) * LGS + 8 + tig * 2]     = acc1.z;
        S.lgb[(m0 + gid + 8) * LGS + 8 + tig * 2 + 1] = acc1.w;
    }
    __syncthreads();

    // phase 3b (t<128): + lb, relu/sw/cw, @Ww2 (in place); then 4a softmax
    if (t < 128) {
        asm volatile("cp.async.wait_group 0;" ::: "memory");
        int r = t, p = r >> 4;
        float m = S.mask[r];
        const float4* kw = (const float4*)&S.kwq[r * 16];
        const float4* qw = (const float4*)&S.qwb[p * 16];
        float u[16];
        #pragma unroll
        for (int q = 0; q < 4; q++) {
            float4 sv = *(const float4*)&S.lgb[r * LGS + q * 4];
            float4 kv = kw[q], qv = qw[q];
            float4 lb;
            lb.x = fmaf(m, kv.x, -qv.x); lb.y = fmaf(m, kv.y, -qv.y);
            lb.z = fmaf(m, kv.z, -qv.z); lb.w = fmaf(m, kv.w, -qv.w);
            u[q*4+0] = fmaxf(fmaf(sv.x + lb.x, S.sw[q*4+0], S.cw[q*4+0]), 0.f);
            u[q*4+1] = fmaxf(fmaf(sv.y + lb.y, S.sw[q*4+1], S.cw[q*4+1]), 0.f);
            u[q*4+2] = fmaxf(fmaf(sv.z + lb.z, S.sw[q*4+2], S.cw[q*4+2]), 0.f);
            u[q*4+3] = fmaxf(fmaf(sv.w + lb.w, S.sw[q*4+3], S.cw[q*4+3]), 0.f);
        }
        #pragma unroll
        for (int g2 = 0; g2 < 16; g2++) {
            float acc = S.bw2s[g2];
            #pragma unroll
            for (int g = 0; g < 16; g++) acc = fmaf(u[g], S.ww2[g * 16 + g2], acc);
            S.lgb[r * LGS + g2] = acc;
        }
        __syncwarp();
        int pp = t >> 4, g = t & 15;
        float mx = -1e30f;
        #pragma unroll
        for (int s = 0; s < 16; s++) mx = fmaxf(mx, S.lgb[(pp * 16 + s) * LGS + g]);
        float e[16], sum = 0.f;
        #pragma unroll
        for (int s = 0; s < 16; s++) {
            e[s] = __expf(S.lgb[(pp * 16 + s) * LGS + g] - mx);
            sum += e[s];
        }
        float inv = 1.f / sum, ws = 0.f;
        #pragma unroll
        for (int s = 0; s < 16; s++) {
            float w = e[s] * inv * S.mask[pp * 16 + s];
            e[s] = w;
            S.lgb[(pp * 16 + s) * LGS + g] = w;
            ws += w;
        }
        S.wsum[t] = ws;
        unsigned wu[8];
        #pragma unroll
        for (int sb = 0; sb < 8; sb++) {
            half2 h = __floats2half2_rn(e[sb * 2], e[sb * 2 + 1]);
            wu[sb] = *(unsigned*)&h;
        }
        uint4* wtrow = (uint4*)&S.wT16[(pp * 16 + g) * 16];
        wtrow[0] = make_uint4(wu[0], wu[1], wu[2], wu[3]);
        wtrow[1] = make_uint4(wu[4], wu[5], wu[6], wu[7]);
    }
    __syncthreads();

    // phase 4A: v-gather: 512 (point, 4ch) slots, 2 per thread
    {
        #pragma unroll
        for (int j = 0; j < 2; j++) {
            int si = t + j * 256;
            int p  = si >> 6;
            int c0 = (si & 63) * 4;
            int g  = c0 >> 4;
            float a0 = 0.f, a1 = 0.f, a2 = 0.f, a3 = 0.f;
            #pragma unroll
            for (int s = 0; s < 16; s++) {
                float w = S.lgb[(p * 16 + s) * LGS + g];
                uint2 v = *(const uint2*)&g_vall16[S.idx[p * 16 + s] * C + c0];
                float2 v0 = __half22float2(*(half2*)&v.x);
                float2 v1 = __half22float2(*(half2*)&v.y);
                a0 = fmaf(w, v0.x, a0); a1 = fmaf(w, v0.y, a1);
                a2 = fmaf(w, v1.x, a2); a3 = fmaf(w, v1.y, a3);
            }
            *(float4*)&S.vterm[p * 256 + c0] = make_float4(a0, a1, a2, a3);
        }
    }
    // phase 4B: hw = wT @ hid via fp16 mma, in place; B via ldmatrix.x2.trans
    {
        int w = t >> 5, lane = t & 31, gid = lane >> 2, tig = lane & 3;
        int p = w;
        const unsigned short* wa = &S.wT16[p * 256];
        unsigned a0 = *(const unsigned*)&wa[gid * 16 + tig * 2];
        unsigned a1 = *(const unsigned*)&wa[(gid + 8) * 16 + tig * 2];
        unsigned a2 = *(const unsigned*)&wa[gid * 16 + tig * 2 + 8];
        unsigned a3 = *(const unsigned*)&wa[(gid + 8) * 16 + tig * 2 + 8];
        unsigned short* hb = &S.hid[p * PSK];
        int lrow = lane & 15;
        unsigned baddr = smem_u32(&hb[lrow * HP]);
        #pragma unroll 4
        for (int nb = 0; nb < 32; nb++) {
            unsigned b0, b1;
            LDMX2T(b0, b1, baddr + nb * 16);
            float4 acc = make_float4(0.f, 0.f, 0.f, 0.f);
            MMA_F16(acc, a0, a1, a2, a3, b0, b1);
            int co = nb * 8 + tig * 2;
            *(half2*)&hb[(gid)     * HP + co] = __floats2half2_rn(acc.x, acc.y);
            *(half2*)&hb[(gid + 8) * HP + co] = __floats2half2_rn(acc.z, acc.w);
        }
    }
    __syncthreads();

    // phase 5: per-group GEMM out[16c x 8p] = Wp2^T-block @ hw, fp16 mma.
    {
        int w = t >> 5, lane = t & 31, gid = lane >> 2, tig = lane & 3;
        const uint4* af = (const uint4*)g_p5a;
        #pragma unroll
        for (int gi = 0; gi < 2; gi++) {
            int g = w + gi * 8;
            const unsigned short* hb = &S.hid[g * HP];
            float4 acc = make_float4(0.f, 0.f, 0.f, 0.f);
            #pragma unroll
            for (int kb = 0; kb < 16; kb++) {
                uint4 a = af[(g * 16 + kb) * 32 + lane];
                unsigned b0 = *(const unsigned*)&hb[gid * PSK + kb * 16 + tig * 2];
                unsigned b1 = *(const unsigned*)&hb[gid * PSK + kb * 16 + tig * 2 + 8];
                MMA_F16(acc, a.x, a.y, a.z, a.w, b0, b1);
            }
            int cg0 = g * 16 + gid, cg1 = cg0 + 8;
            int p0 = tig * 2, p1 = p0 + 1;
            float b0c = S.bp2s[cg0], b1c = S.bp2s[cg1];
            out[(n0 + p0) * C + cg0] = acc.x + S.vterm[p0 * 256 + cg0] + b0c * S.wsum[p0 * 16 + g];
            out[(n0 + p1) * C + cg0] = acc.y + S.vterm[p1 * 256 + cg0] + b0c * S.wsum[p1 * 16 + g];
            out[(n0 + p0) * C + cg1] = acc.z + S.vterm[p0 * 256 + cg1] + b1c * S.wsum[p0 * 16 + g];
            out[(n0 + p1) * C + cg1] = acc.w + S.vterm[p1 * 256 + cg1] + b1c * S.wsum[p1 * 16 + g];
        }
    }
}

// ---------------- launch ----------------------------------------------------
extern "C" void kernel_launch(void* const* d_in, const int* in_sizes, int n_in,
                              void* d_out, int out_size) {
    (void)in_sizes; (void)n_in; (void)out_size;
    const float* feat  = (const float*)d_in[0];
    const float* coord = (const float*)d_in[1];
    const int*   knn   = (const int*)  d_in[2];
    const float* Wq = (const float*)d_in[3];  const float* bq = (const float*)d_in[4];  const float* bnq = (const float*)d_in[5];
    const float* Wk = (const float*)d_in[6];  const float* bk = (const float*)d_in[7];  const float* bnk = (const float*)d_in[8];
    const float* Wv = (const float*)d_in[9];  const float* bv = (const float*)d_in[10];
    const float* Wp1 = (const float*)d_in[11]; const float* bp1 = (const float*)d_in[12]; const float* bnp = (const float*)d_in[13];
    const float* Wp2 = (const float*)d_in[14]; const float* bp2 = (const float*)d_in[15];
    const float* Ww1 = (const float*)d_in[16]; const float* bw1 = (const float*)d_in[17]; const float* bnw = (const float*)d_in[18];
    const float* Ww2 = (const float*)d_in[19]; const float* bw2 = (const float*)d_in[20];
    float* out = (float*)d_out;

    int k1_smem = (BM * FSH + BM * YSH) * 2;
    cudaFuncSetAttribute(k1_qkv,  cudaFuncAttributeMaxDynamicSharedMemorySize, k1_smem);
    cudaFuncSetAttribute(k2_attn, cudaFuncAttributeMaxDynamicSharedMemorySize, (int)sizeof(K2S));

    mega_prep<<<21, 512>>>(bq, bnq, bk, bnk, bp1, bnp, bw1, bnw, bp2, Ww1, Wp1, Wp2);
    prep_wfrag16<<<48, 1024>>>(Wq, Wk, Wv);
    k1_qkv<<<NPTS / BM, 256, k1_smem>>>(feat, bv);
    k2_attn<<<NPTS / P, 256, sizeof(K2S)>>>(coord, knn, bp2, Ww2, bw2, out);
}